// round 1
// baseline (speedup 1.0000x reference)
#include <cuda_runtime.h>

#define BB   8
#define LLEN 4096
#define CEMB 192
#define DIN  384
#define XD   20
#define DTR  12
#define NC   32
#define LC   128
#define MROWS (BB*LLEN)

// ---------------- scratch (static device globals; no runtime allocation) ----------------
__device__ float g_xh  [MROWS*CEMB];     // transposed input (B,L,C) -- also residual
__device__ float g_h2  [MROWS*CEMB];     // mamba0 output
__device__ float g_h3  [MROWS*CEMB];     // mamba1 output
__device__ float g_xz  [MROWS*2*DIN];    // in_proj output (xin | z)
__device__ float g_xa  [MROWS*DIN];      // conv+silu output
__device__ float g_dt  [MROWS*DIN];
__device__ float g_e1  [MROWS*DIN];      // exp(A0*dt)
__device__ float g_y   [MROWS*DIN];      // scan output (gated)
__device__ float g_xdbl[MROWS*XD];
__device__ float g_hpart[BB*DIN*NC*4];
__device__ float g_sumdt[BB*DIN*NC];
__device__ float g_Hinit[BB*DIN*NC*4];
__device__ float g_A[DIN*4];
__device__ int   g_slow;

// ---------------- transpose (B,C,L) -> (B,L,C) ----------------
__global__ void transpose_k(const float* __restrict__ x) {
    __shared__ float t[32][33];
    int b = blockIdx.z;
    int l0 = blockIdx.x * 32, c0 = blockIdx.y * 32;
    int tx = threadIdx.x, ty = threadIdx.y;
    #pragma unroll
    for (int j = ty; j < 32; j += 8)
        t[j][tx] = x[((b*CEMB) + (c0 + j)) * LLEN + l0 + tx];
    __syncthreads();
    #pragma unroll
    for (int j = ty; j < 32; j += 8)
        g_xh[((b*LLEN) + (l0 + j)) * CEMB + c0 + tx] = t[tx][j];
}

// ---------------- A structure prep ----------------
__global__ void prepA_k(const float* __restrict__ A_log) {
    int d = threadIdx.x;
    if (d == 0) g_slow = 0;
    __syncthreads();
    float a[4];
    #pragma unroll
    for (int s = 0; s < 4; s++) {
        a[s] = -expf(A_log[d*4 + s]);
        g_A[d*4 + s] = a[s];
    }
    bool ok = true;
    #pragma unroll
    for (int s = 0; s < 4; s++) {
        float want = (float)(s + 1) * a[0];
        if (fabsf(a[s] - want) > 1e-5f * fabsf(a[s]) + 1e-7f) ok = false;
    }
    if (!ok) atomicExch(&g_slow, 1);
}

// ---------------- generic C[M,N] = A[M,K] @ W[N,K]^T ----------------
template<int BM, int BN, int BK, int TM, int TN>
__global__ void __launch_bounds__((BM/TM)*(BN/TN))
gemm_tn(const float* __restrict__ A, const float* __restrict__ W,
        float* __restrict__ C, int M, int N, int K)
{
    constexpr int THREADS = (BM/TM)*(BN/TN);
    __shared__ float As[BK][BM];
    __shared__ float Ws[BK][BN];
    const int tid = threadIdx.x;
    const int bm = blockIdx.y * BM, bn = blockIdx.x * BN;
    const int tx = tid % (BN/TN), ty = tid / (BN/TN);
    float acc[TM][TN];
    #pragma unroll
    for (int i = 0; i < TM; i++)
        #pragma unroll
        for (int j = 0; j < TN; j++) acc[i][j] = 0.f;

    for (int k0 = 0; k0 < K; k0 += BK) {
        for (int i = tid; i < BM*BK/4; i += THREADS) {
            int r = i / (BK/4), c = i % (BK/4);
            float4 v = *(const float4*)(A + (size_t)(bm + r)*K + k0 + c*4);
            As[c*4+0][r] = v.x; As[c*4+1][r] = v.y; As[c*4+2][r] = v.z; As[c*4+3][r] = v.w;
        }
        for (int i = tid; i < BN*BK/4; i += THREADS) {
            int r = i / (BK/4), c = i % (BK/4);
            float4 v = *(const float4*)(W + (size_t)(bn + r)*K + k0 + c*4);
            Ws[c*4+0][r] = v.x; Ws[c*4+1][r] = v.y; Ws[c*4+2][r] = v.z; Ws[c*4+3][r] = v.w;
        }
        __syncthreads();
        #pragma unroll
        for (int kk = 0; kk < BK; kk++) {
            float ar[TM], wr[TN];
            #pragma unroll
            for (int i = 0; i < TM; i++) ar[i] = As[kk][ty*TM + i];
            #pragma unroll
            for (int j = 0; j < TN; j++) wr[j] = Ws[kk][tx*TN + j];
            #pragma unroll
            for (int i = 0; i < TM; i++)
                #pragma unroll
                for (int j = 0; j < TN; j++)
                    acc[i][j] = fmaf(ar[i], wr[j], acc[i][j]);
        }
        __syncthreads();
    }
    #pragma unroll
    for (int i = 0; i < TM; i++) {
        int row = bm + ty*TM + i;
        #pragma unroll
        for (int j = 0; j < TN; j += 4) {
            float4 v = make_float4(acc[i][j], acc[i][j+1], acc[i][j+2], acc[i][j+3]);
            *(float4*)(C + (size_t)row*N + bn + tx*TN + j) = v;
        }
    }
}

// ---------------- depthwise causal conv (k=4) + silu ----------------
__global__ void conv_k(const float* __restrict__ w, const float* __restrict__ bias) {
    int idx = blockIdx.x * blockDim.x + threadIdx.x;
    if (idx >= MROWS * DIN) return;
    int d  = idx % DIN;
    int bl = idx / DIN;
    int l  = bl % LLEN;
    float w0 = w[d*4+0], w1 = w[d*4+1], w2 = w[d*4+2], w3 = w[d*4+3];
    const float* p = g_xz + (size_t)bl * (2*DIN) + d;
    float acc = bias[d];
    if (l >= 3) acc = fmaf(w0, p[-3*2*DIN], acc);
    if (l >= 2) acc = fmaf(w1, p[-2*2*DIN], acc);
    if (l >= 1) acc = fmaf(w2, p[-1*2*DIN], acc);
    acc = fmaf(w3, p[0], acc);
    // silu
    float s = __fdividef(acc, 1.f + __expf(-acc));
    g_xa[idx] = s;
}

// ---------------- x_proj: x_dbl[M,20] = xa[M,384] @ Wx[20,384]^T ----------------
__global__ void xproj_k(const float* __restrict__ W) {
    __shared__ float Wsh[XD * DIN];
    for (int i = threadIdx.x; i < XD*DIN; i += 256) Wsh[i] = W[i];
    __syncthreads();
    int warp = threadIdx.x >> 5, lane = threadIdx.x & 31;
    int m = blockIdx.x * 8 + warp;
    const float* ar = g_xa + (size_t)m * DIN;
    float acc[XD];
    #pragma unroll
    for (int n = 0; n < XD; n++) acc[n] = 0.f;
    for (int k = lane; k < DIN; k += 32) {
        float a = ar[k];
        #pragma unroll
        for (int n = 0; n < XD; n++)
            acc[n] = fmaf(a, Wsh[n*DIN + k], acc[n]);
    }
    float myv = 0.f;
    #pragma unroll
    for (int n = 0; n < XD; n++) {
        float v = acc[n];
        #pragma unroll
        for (int off = 16; off > 0; off >>= 1)
            v += __shfl_xor_sync(0xffffffffu, v, off);
        if (lane == n) myv = v;
    }
    if (lane < XD) g_xdbl[(size_t)m*XD + lane] = myv;
}

// ---------------- dt = softplus(dt_lr @ dtw^T + b); e1 = exp(A0*dt) ----------------
__global__ void dt_k(const float* __restrict__ dtw, const float* __restrict__ dtb) {
    __shared__ float dl[DTR];
    int m = blockIdx.x, n = threadIdx.x;
    if (n < DTR) dl[n] = g_xdbl[(size_t)m*XD + n];
    __syncthreads();
    float p = dtb[n];
    const float4* w4 = (const float4*)(dtw + n*DTR);
    #pragma unroll
    for (int q = 0; q < 3; q++) {
        float4 w = w4[q];
        p = fmaf(dl[q*4+0], w.x, p);
        p = fmaf(dl[q*4+1], w.y, p);
        p = fmaf(dl[q*4+2], w.z, p);
        p = fmaf(dl[q*4+3], w.w, p);
    }
    float dv = (p > 20.f) ? p : __logf(1.f + __expf(p));
    int idx = m*DIN + n;
    g_dt[idx] = dv;
    g_e1[idx] = __expf(g_A[n*4] * dv);
}

// ---------------- scan pass 1: per-chunk partial states ----------------
__global__ void scan1_k() {
    __shared__ float Bsm[LC][4];
    int chunk = blockIdx.x, b = blockIdx.y, d = threadIdx.x;
    int l0 = chunk * LC;
    for (int i = threadIdx.x; i < LC*4; i += DIN) {
        int l = i >> 2, s = i & 3;
        Bsm[l][s] = g_xdbl[((size_t)(b*LLEN + l0 + l))*XD + DTR + s];
    }
    __syncthreads();
    int slow = g_slow;
    float Av0 = g_A[d*4], Av1 = g_A[d*4+1], Av2 = g_A[d*4+2], Av3 = g_A[d*4+3];
    float h0 = 0.f, h1 = 0.f, h2 = 0.f, h3 = 0.f, sd = 0.f;
    int base = (b*LLEN + l0)*DIN + d;
    for (int l = 0; l < LC; l++) {
        int idx = base + l*DIN;
        float dtv = g_dt[idx];
        float xav = g_xa[idx];
        float dbu = dtv * xav;
        sd += dtv;
        float b0 = Bsm[l][0], b1 = Bsm[l][1], b2 = Bsm[l][2], b3 = Bsm[l][3];
        if (!slow) {
            float e = g_e1[idx];
            float p = e;
            h0 = fmaf(p, h0, dbu*b0); p *= e;
            h1 = fmaf(p, h1, dbu*b1); p *= e;
            h2 = fmaf(p, h2, dbu*b2); p *= e;
            h3 = fmaf(p, h3, dbu*b3);
        } else {
            h0 = fmaf(__expf(dtv*Av0), h0, dbu*b0);
            h1 = fmaf(__expf(dtv*Av1), h1, dbu*b1);
            h2 = fmaf(__expf(dtv*Av2), h2, dbu*b2);
            h3 = fmaf(__expf(dtv*Av3), h3, dbu*b3);
        }
    }
    int o = ((b*DIN) + d)*NC + chunk;
    ((float4*)g_hpart)[o] = make_float4(h0, h1, h2, h3);
    g_sumdt[o] = sd;
}

// ---------------- scan pass 2: combine chunks ----------------
__global__ void scan2_k() {
    int t = blockIdx.x * blockDim.x + threadIdx.x;
    if (t >= BB*DIN) return;
    int d = t % DIN;
    float Av0 = g_A[d*4], Av1 = g_A[d*4+1], Av2 = g_A[d*4+2], Av3 = g_A[d*4+3];
    float H0 = 0.f, H1 = 0.f, H2 = 0.f, H3 = 0.f;
    for (int c = 0; c < NC; c++) {
        int o = t*NC + c;
        ((float4*)g_Hinit)[o] = make_float4(H0, H1, H2, H3);
        float4 hp = ((const float4*)g_hpart)[o];
        float sd = g_sumdt[o];
        H0 = fmaf(__expf(Av0*sd), H0, hp.x);
        H1 = fmaf(__expf(Av1*sd), H1, hp.y);
        H2 = fmaf(__expf(Av2*sd), H2, hp.z);
        H3 = fmaf(__expf(Av3*sd), H3, hp.w);
    }
}

// ---------------- scan pass 3: replay with init + gate ----------------
__global__ void scan3_k(const float* __restrict__ Dw) {
    __shared__ float Bsm[LC][4];
    __shared__ float Csm[LC][4];
    int chunk = blockIdx.x, b = blockIdx.y, d = threadIdx.x;
    int l0 = chunk * LC;
    for (int i = threadIdx.x; i < LC*4; i += DIN) {
        int l = i >> 2, s = i & 3;
        const float* row = g_xdbl + ((size_t)(b*LLEN + l0 + l))*XD + DTR;
        Bsm[l][s] = row[s];
        Csm[l][s] = row[4 + s];
    }
    __syncthreads();
    int slow = g_slow;
    float Av0 = g_A[d*4], Av1 = g_A[d*4+1], Av2 = g_A[d*4+2], Av3 = g_A[d*4+3];
    float Dd = Dw[d];
    int o = ((b*DIN) + d)*NC + chunk;
    float4 Hi = ((const float4*)g_Hinit)[o];
    float h0 = Hi.x, h1 = Hi.y, h2 = Hi.z, h3 = Hi.w;
    int base = (b*LLEN + l0)*DIN + d;
    for (int l = 0; l < LC; l++) {
        int idx = base + l*DIN;
        float dtv = g_dt[idx];
        float xav = g_xa[idx];
        float dbu = dtv * xav;
        float b0 = Bsm[l][0], b1 = Bsm[l][1], b2 = Bsm[l][2], b3 = Bsm[l][3];
        if (!slow) {
            float e = g_e1[idx];
            float p = e;
            h0 = fmaf(p, h0, dbu*b0); p *= e;
            h1 = fmaf(p, h1, dbu*b1); p *= e;
            h2 = fmaf(p, h2, dbu*b2); p *= e;
            h3 = fmaf(p, h3, dbu*b3);
        } else {
            h0 = fmaf(__expf(dtv*Av0), h0, dbu*b0);
            h1 = fmaf(__expf(dtv*Av1), h1, dbu*b1);
            h2 = fmaf(__expf(dtv*Av2), h2, dbu*b2);
            h3 = fmaf(__expf(dtv*Av3), h3, dbu*b3);
        }
        float y = h0*Csm[l][0] + h1*Csm[l][1] + h2*Csm[l][2] + h3*Csm[l][3];
        y = fmaf(xav, Dd, y);
        float zv = g_xz[((size_t)(b*LLEN + l0 + l))*(2*DIN) + DIN + d];
        float zs = __fdividef(zv, 1.f + __expf(-zv));  // silu(z)
        g_y[idx] = y * zs;
    }
}

// ---------------- final: low-rank UV + residual + LayerNorm + transpose out ----------------
__global__ void final_k(const float* __restrict__ U, const float* __restrict__ V,
                        const float* __restrict__ lng, const float* __restrict__ lnb,
                        float* __restrict__ out)
{
    __shared__ float Ush[4*CEMB];
    __shared__ float Vsh[CEMB*4];
    __shared__ float u[32][4];
    __shared__ float vs[32][193];
    __shared__ float mu[32], rsd[32];
    int b = blockIdx.y;
    int l0 = blockIdx.x * 32;
    int tid = threadIdx.x;
    for (int i = tid; i < 4*CEMB; i += 256) { Ush[i] = U[i]; Vsh[i] = V[i]; }
    __syncthreads();
    if (tid < 128) {
        int p = tid >> 2, r = tid & 3;
        const float* hr = g_h3 + ((size_t)(b*LLEN) + l0 + p)*CEMB;
        float a = 0.f;
        #pragma unroll 8
        for (int c = 0; c < CEMB; c++) a = fmaf(hr[c], Ush[r*CEMB + c], a);
        u[p][r] = a;
    }
    __syncthreads();
    for (int i = tid; i < 32*CEMB; i += 256) {
        int p = i / CEMB, c = i % CEMB;
        float v = g_xh[((size_t)(b*LLEN) + l0 + p)*CEMB + c];
        v = fmaf(Vsh[c*4+0], u[p][0], v);
        v = fmaf(Vsh[c*4+1], u[p][1], v);
        v = fmaf(Vsh[c*4+2], u[p][2], v);
        v = fmaf(Vsh[c*4+3], u[p][3], v);
        vs[p][c] = v;
    }
    __syncthreads();
    int warp = tid >> 5, lane = tid & 31;
    #pragma unroll
    for (int pp = 0; pp < 4; pp++) {
        int p = warp*4 + pp;
        float s = 0.f, ss = 0.f;
        for (int c = lane; c < CEMB; c += 32) {
            float v = vs[p][c];
            s += v; ss = fmaf(v, v, ss);
        }
        #pragma unroll
        for (int off = 16; off > 0; off >>= 1) {
            s  += __shfl_xor_sync(0xffffffffu, s, off);
            ss += __shfl_xor_sync(0xffffffffu, ss, off);
        }
        if (lane == 0) {
            float m = s * (1.f/CEMB);
            mu[p] = m;
            rsd[p] = rsqrtf(ss * (1.f/CEMB) - m*m + 1e-5f);
        }
    }
    __syncthreads();
    for (int c = warp; c < CEMB; c += 8) {
        int p = lane;
        float v = (vs[p][c] - mu[p]) * rsd[p] * lng[c] + lnb[c];
        out[((size_t)(b*CEMB) + c)*LLEN + l0 + lane] = v;
    }
}

// ---------------- launch ----------------
extern "C" void kernel_launch(void* const* d_in, const int* in_sizes, int n_in,
                              void* d_out, int out_size)
{
    const float* x         = (const float*)d_in[0];
    const float* in_proj_w = (const float*)d_in[1];
    const float* conv_w    = (const float*)d_in[2];
    const float* conv_b    = (const float*)d_in[3];
    const float* x_proj_w  = (const float*)d_in[4];
    const float* dt_proj_w = (const float*)d_in[5];
    const float* dt_proj_b = (const float*)d_in[6];
    const float* A_log     = (const float*)d_in[7];
    const float* Dw        = (const float*)d_in[8];
    const float* out_proj_w= (const float*)d_in[9];
    const float* U_w       = (const float*)d_in[10];
    const float* V_w       = (const float*)d_in[11];
    const float* ln_g      = (const float*)d_in[12];
    const float* ln_b      = (const float*)d_in[13];
    float* out = (float*)d_out;

    float* g_xh_p;  cudaGetSymbolAddress((void**)&g_xh_p,  g_xh);
    float* g_h2_p;  cudaGetSymbolAddress((void**)&g_h2_p,  g_h2);
    float* g_h3_p;  cudaGetSymbolAddress((void**)&g_h3_p,  g_h3);
    float* g_xz_p;  cudaGetSymbolAddress((void**)&g_xz_p,  g_xz);
    float* g_y_p;   cudaGetSymbolAddress((void**)&g_y_p,   g_y);

    transpose_k<<<dim3(LLEN/32, CEMB/32, BB), dim3(32, 8)>>>(x);

    const float* cur = g_xh_p;
    float* nxt_bufs[2] = { g_h2_p, g_h3_p };

    for (int mix = 0; mix < 2; mix++) {
        prepA_k<<<1, DIN>>>(A_log + mix*DIN*4);
        gemm_tn<128,64,16,8,4><<<dim3((2*DIN)/64, MROWS/128), 256>>>(
            cur, in_proj_w + (size_t)mix*2*DIN*CEMB, g_xz_p, MROWS, 2*DIN, CEMB);
        conv_k<<<(MROWS*DIN + 255)/256, 256>>>(conv_w + mix*DIN*4, conv_b + mix*DIN);
        xproj_k<<<MROWS/8, 256>>>(x_proj_w + (size_t)mix*XD*DIN);
        dt_k<<<MROWS, DIN>>>(dt_proj_w + (size_t)mix*DIN*DTR, dt_proj_b + mix*DIN);
        scan1_k<<<dim3(NC, BB), DIN>>>();
        scan2_k<<<(BB*DIN + 255)/256, 256>>>();
        scan3_k<<<dim3(NC, BB), DIN>>>(Dw + mix*DIN);
        gemm_tn<128,64,16,8,4><<<dim3(CEMB/64, MROWS/128), 256>>>(
            g_y_p, out_proj_w + (size_t)mix*CEMB*DIN, nxt_bufs[mix], MROWS, CEMB, DIN);
        cur = nxt_bufs[mix];
    }

    final_k<<<dim3(LLEN/32, BB), 256>>>(U_w, V_w, ln_g, ln_b, out);
}

// round 3
// speedup vs baseline: 1.2996x; 1.2996x over previous
#include <cuda_runtime.h>
#include <cstdint>

#define BB   8
#define LLEN 4096
#define CEMB 192
#define DIN  384
#define XD   20
#define DTR  12
#define NC   32
#define LC   128
#define MROWS (BB*LLEN)

// ---------------- scratch ----------------
__device__ float g_xh  [MROWS*CEMB];
__device__ float g_h2  [MROWS*CEMB];
__device__ float g_h3  [MROWS*CEMB];
__device__ float g_xz  [MROWS*2*DIN];
__device__ float g_xa  [MROWS*DIN];
__device__ float g_dt  [MROWS*DIN];
__device__ float g_e1  [MROWS*DIN];
__device__ float g_y   [MROWS*DIN];
__device__ float g_xdbl[MROWS*XD];
__device__ float g_hpart[BB*DIN*NC*4];
__device__ float g_sumdt[BB*DIN*NC];
__device__ float g_Hinit[BB*DIN*NC*4];
__device__ float g_A[DIN*4];
__device__ int   g_slow;

__device__ __forceinline__ uint32_t smem_u32(const void* p) {
    uint32_t a;
    asm("{ .reg .u64 t; cvta.to.shared.u64 t, %1; cvt.u32.u64 %0, t; }" : "=r"(a) : "l"(p));
    return a;
}

// ======================= split-bf16 HMMA GEMM: C[M,N] = A[M,K] @ W[N,K]^T =======================
// mma.sync m16n8k16 bf16 (sm_80+ PTX -> HMMA on sm_103). fp32 emulated as hi+lo bf16,
// D += Ah*Bh + Ah*Bl + Al*Bh. CTA tile 128x64, BK=64, 8 warps (4x2), warp tile 32x32.

__device__ __forceinline__ void cvt_hilo(float4 v, uint32_t& h0, uint32_t& h1,
                                         uint32_t& l0, uint32_t& l1) {
    asm("cvt.rn.bf16x2.f32 %0, %1, %2;" : "=r"(h0) : "f"(v.y), "f"(v.x));
    asm("cvt.rn.bf16x2.f32 %0, %1, %2;" : "=r"(h1) : "f"(v.w), "f"(v.z));
    float a0 = v.x - __uint_as_float(h0 << 16);
    float a1 = v.y - __uint_as_float(h0 & 0xffff0000u);
    float a2 = v.z - __uint_as_float(h1 << 16);
    float a3 = v.w - __uint_as_float(h1 & 0xffff0000u);
    asm("cvt.rn.bf16x2.f32 %0, %1, %2;" : "=r"(l0) : "f"(a1), "f"(a0));
    asm("cvt.rn.bf16x2.f32 %0, %1, %2;" : "=r"(l1) : "f"(a3), "f"(a2));
}

// store tile rows x 64 floats as bf16 hi/lo into swizzled smem (128B rows, c16 ^= r&7)
__device__ __forceinline__ void load_tile(const float* __restrict__ g, int ld, int rows,
                                          char* hi, char* lo, int tid, int nthr) {
    for (int idx = tid; idx < rows * 16; idx += nthr) {
        int r = idx >> 4, q = idx & 15, k = q * 4;
        float4 v = *(const float4*)(g + (size_t)r * ld + k);
        uint32_t h0, h1, l0, l1;
        cvt_hilo(v, h0, h1, l0, l1);
        uint32_t off = (uint32_t)(r * 128 + (((q >> 1) ^ (r & 7)) << 4) + ((q & 1) << 3));
        *(uint2*)(hi + off) = make_uint2(h0, h1);
        *(uint2*)(lo + off) = make_uint2(l0, l1);
    }
}

#define LDSM_X4(r0, r1, r2, r3, addr) \
    asm volatile("ldmatrix.sync.aligned.m8n8.x4.shared.b16 {%0,%1,%2,%3}, [%4];" \
        : "=r"(r0), "=r"(r1), "=r"(r2), "=r"(r3) : "r"(addr))
#define LDSM_X2(r0, r1, addr) \
    asm volatile("ldmatrix.sync.aligned.m8n8.x2.shared.b16 {%0,%1}, [%2];" \
        : "=r"(r0), "=r"(r1) : "r"(addr))
#define MMA_BF16(c, a, b) \
    asm volatile("mma.sync.aligned.m16n8k16.row.col.f32.bf16.bf16.f32 " \
        "{%0,%1,%2,%3}, {%4,%5,%6,%7}, {%8,%9}, {%0,%1,%2,%3};" \
        : "+f"((c)[0]), "+f"((c)[1]), "+f"((c)[2]), "+f"((c)[3]) \
        : "r"((a)[0]), "r"((a)[1]), "r"((a)[2]), "r"((a)[3]), "r"((b)[0]), "r"((b)[1]))

__global__ void __launch_bounds__(256)
gemm_mma(const float* __restrict__ A, const float* __restrict__ W,
         float* __restrict__ C, int M, int N, int K)
{
    __shared__ __align__(1024) char sm[49152];
    char* AH = sm;                // 128*64*2 = 16KB
    char* AL = sm + 16384;
    char* WH = sm + 32768;        // 64*64*2  = 8KB
    char* WL = sm + 40960;

    const int tid = threadIdx.x, wid = tid >> 5, lane = tid & 31;
    const int wm = wid & 3, wn = wid >> 2;
    const int bm = blockIdx.y * 128, bn = blockIdx.x * 64;
    const uint32_t sAH = smem_u32(AH), sAL = smem_u32(AL);
    const uint32_t sWH = smem_u32(WH), sWL = smem_u32(WL);

    float acc[2][4][4];
    #pragma unroll
    for (int i = 0; i < 2; i++)
        #pragma unroll
        for (int j = 0; j < 4; j++)
            #pragma unroll
            for (int q = 0; q < 4; q++) acc[i][j][q] = 0.f;

    const int nkt = K >> 6;
    for (int kt = 0; kt < nkt; kt++) {
        if (kt) __syncthreads();
        load_tile(A + (size_t)bm * K + kt * 64, K, 128, AH, AL, tid, 256);
        load_tile(W + (size_t)bn * K + kt * 64, K, 64,  WH, WL, tid, 256);
        __syncthreads();

        #pragma unroll
        for (int ks = 0; ks < 4; ks++) {
            uint32_t ah[2][4], al[2][4], bh[4][2], bl[4][2];
            #pragma unroll
            for (int mt = 0; mt < 2; mt++) {
                int r = wm * 32 + mt * 16 + (lane & 15);
                int c16 = ks * 2 + (lane >> 4);
                uint32_t off = (uint32_t)(r * 128 + ((c16 ^ (r & 7)) << 4));
                LDSM_X4(ah[mt][0], ah[mt][1], ah[mt][2], ah[mt][3], sAH + off);
                LDSM_X4(al[mt][0], al[mt][1], al[mt][2], al[mt][3], sAL + off);
            }
            #pragma unroll
            for (int nt = 0; nt < 4; nt++) {
                int rn = wn * 32 + nt * 8 + (lane & 7);
                int c16 = ks * 2 + ((lane >> 3) & 1);
                uint32_t off = (uint32_t)(rn * 128 + ((c16 ^ (rn & 7)) << 4));
                LDSM_X2(bh[nt][0], bh[nt][1], sWH + off);
                LDSM_X2(bl[nt][0], bl[nt][1], sWL + off);
            }
            #pragma unroll
            for (int mt = 0; mt < 2; mt++)
                #pragma unroll
                for (int nt = 0; nt < 4; nt++) {
                    MMA_BF16(acc[mt][nt], ah[mt], bh[nt]);
                    MMA_BF16(acc[mt][nt], ah[mt], bl[nt]);
                    MMA_BF16(acc[mt][nt], al[mt], bh[nt]);
                }
        }
    }

    // epilogue: direct accumulator stores (8B each, 32B L2 sectors)
    #pragma unroll
    for (int mt = 0; mt < 2; mt++) {
        int row = bm + wm * 32 + mt * 16 + (lane >> 2);
        #pragma unroll
        for (int nt = 0; nt < 4; nt++) {
            int col = bn + wn * 32 + nt * 8 + (lane & 3) * 2;
            *(float2*)(C + (size_t)row * N + col)       = make_float2(acc[mt][nt][0], acc[mt][nt][1]);
            *(float2*)(C + (size_t)(row + 8) * N + col) = make_float2(acc[mt][nt][2], acc[mt][nt][3]);
        }
    }
}

// ---------------- transpose (B,C,L) -> (B,L,C) ----------------
__global__ void transpose_k(const float* __restrict__ x) {
    __shared__ float t[32][33];
    int b = blockIdx.z;
    int l0 = blockIdx.x * 32, c0 = blockIdx.y * 32;
    int tx = threadIdx.x, ty = threadIdx.y;
    #pragma unroll
    for (int j = ty; j < 32; j += 8)
        t[j][tx] = x[((b*CEMB) + (c0 + j)) * LLEN + l0 + tx];
    __syncthreads();
    #pragma unroll
    for (int j = ty; j < 32; j += 8)
        g_xh[((b*LLEN) + (l0 + j)) * CEMB + c0 + tx] = t[tx][j];
}

// ---------------- A structure prep ----------------
__global__ void prepA_k(const float* __restrict__ A_log) {
    int d = threadIdx.x;
    if (d == 0) g_slow = 0;
    __syncthreads();
    float a[4];
    #pragma unroll
    for (int s = 0; s < 4; s++) {
        a[s] = -expf(A_log[d*4 + s]);
        g_A[d*4 + s] = a[s];
    }
    bool ok = true;
    #pragma unroll
    for (int s = 0; s < 4; s++) {
        float want = (float)(s + 1) * a[0];
        if (fabsf(a[s] - want) > 1e-5f * fabsf(a[s]) + 1e-7f) ok = false;
    }
    if (!ok) atomicExch(&g_slow, 1);
}

// ---------------- depthwise causal conv (k=4) + silu ----------------
__global__ void conv_k(const float* __restrict__ w, const float* __restrict__ bias) {
    int idx = blockIdx.x * blockDim.x + threadIdx.x;
    if (idx >= MROWS * DIN) return;
    int d  = idx % DIN;
    int bl = idx / DIN;
    int l  = bl % LLEN;
    float w0 = w[d*4+0], w1 = w[d*4+1], w2 = w[d*4+2], w3 = w[d*4+3];
    const float* p = g_xz + (size_t)bl * (2*DIN) + d;
    float acc = bias[d];
    if (l >= 3) acc = fmaf(w0, p[-3*2*DIN], acc);
    if (l >= 2) acc = fmaf(w1, p[-2*2*DIN], acc);
    if (l >= 1) acc = fmaf(w2, p[-1*2*DIN], acc);
    acc = fmaf(w3, p[0], acc);
    float s = __fdividef(acc, 1.f + __expf(-acc));
    g_xa[idx] = s;
}

// ---------------- x_proj ----------------
__global__ void xproj_k(const float* __restrict__ W) {
    __shared__ float Wsh[XD * DIN];
    for (int i = threadIdx.x; i < XD*DIN; i += 256) Wsh[i] = W[i];
    __syncthreads();
    int warp = threadIdx.x >> 5, lane = threadIdx.x & 31;
    int m = blockIdx.x * 8 + warp;
    const float* ar = g_xa + (size_t)m * DIN;
    float acc[XD];
    #pragma unroll
    for (int n = 0; n < XD; n++) acc[n] = 0.f;
    for (int k = lane; k < DIN; k += 32) {
        float a = ar[k];
        #pragma unroll
        for (int n = 0; n < XD; n++)
            acc[n] = fmaf(a, Wsh[n*DIN + k], acc[n]);
    }
    float myv = 0.f;
    #pragma unroll
    for (int n = 0; n < XD; n++) {
        float v = acc[n];
        #pragma unroll
        for (int off = 16; off > 0; off >>= 1)
            v += __shfl_xor_sync(0xffffffffu, v, off);
        if (lane == n) myv = v;
    }
    if (lane < XD) g_xdbl[(size_t)m*XD + lane] = myv;
}

// ---------------- dt ----------------
__global__ void dt_k(const float* __restrict__ dtw, const float* __restrict__ dtb) {
    __shared__ float dl[DTR];
    int m = blockIdx.x, n = threadIdx.x;
    if (n < DTR) dl[n] = g_xdbl[(size_t)m*XD + n];
    __syncthreads();
    float p = dtb[n];
    const float4* w4 = (const float4*)(dtw + n*DTR);
    #pragma unroll
    for (int q = 0; q < 3; q++) {
        float4 w = w4[q];
        p = fmaf(dl[q*4+0], w.x, p);
        p = fmaf(dl[q*4+1], w.y, p);
        p = fmaf(dl[q*4+2], w.z, p);
        p = fmaf(dl[q*4+3], w.w, p);
    }
    float dv = (p > 20.f) ? p : __logf(1.f + __expf(p));
    int idx = m*DIN + n;
    g_dt[idx] = dv;
    g_e1[idx] = __expf(g_A[n*4] * dv);
}

// ---------------- scan pass 1 ----------------
__global__ void scan1_k() {
    __shared__ float Bsm[LC][4];
    int chunk = blockIdx.x, b = blockIdx.y, d = threadIdx.x;
    int l0 = chunk * LC;
    for (int i = threadIdx.x; i < LC*4; i += DIN) {
        int l = i >> 2, s = i & 3;
        Bsm[l][s] = g_xdbl[((size_t)(b*LLEN + l0 + l))*XD + DTR + s];
    }
    __syncthreads();
    int slow = g_slow;
    float Av0 = g_A[d*4], Av1 = g_A[d*4+1], Av2 = g_A[d*4+2], Av3 = g_A[d*4+3];
    float h0 = 0.f, h1 = 0.f, h2 = 0.f, h3 = 0.f, sd = 0.f;
    int base = (b*LLEN + l0)*DIN + d;
    for (int l = 0; l < LC; l++) {
        int idx = base + l*DIN;
        float dtv = g_dt[idx];
        float xav = g_xa[idx];
        float dbu = dtv * xav;
        sd += dtv;
        float b0 = Bsm[l][0], b1 = Bsm[l][1], b2 = Bsm[l][2], b3 = Bsm[l][3];
        if (!slow) {
            float e = g_e1[idx];
            float p = e;
            h0 = fmaf(p, h0, dbu*b0); p *= e;
            h1 = fmaf(p, h1, dbu*b1); p *= e;
            h2 = fmaf(p, h2, dbu*b2); p *= e;
            h3 = fmaf(p, h3, dbu*b3);
        } else {
            h0 = fmaf(__expf(dtv*Av0), h0, dbu*b0);
            h1 = fmaf(__expf(dtv*Av1), h1, dbu*b1);
            h2 = fmaf(__expf(dtv*Av2), h2, dbu*b2);
            h3 = fmaf(__expf(dtv*Av3), h3, dbu*b3);
        }
    }
    int o = ((b*DIN) + d)*NC + chunk;
    ((float4*)g_hpart)[o] = make_float4(h0, h1, h2, h3);
    g_sumdt[o] = sd;
}

// ---------------- scan pass 2 ----------------
__global__ void scan2_k() {
    int t = blockIdx.x * blockDim.x + threadIdx.x;
    if (t >= BB*DIN) return;
    int d = t % DIN;
    float Av0 = g_A[d*4], Av1 = g_A[d*4+1], Av2 = g_A[d*4+2], Av3 = g_A[d*4+3];
    float H0 = 0.f, H1 = 0.f, H2 = 0.f, H3 = 0.f;
    for (int c = 0; c < NC; c++) {
        int o = t*NC + c;
        ((float4*)g_Hinit)[o] = make_float4(H0, H1, H2, H3);
        float4 hp = ((const float4*)g_hpart)[o];
        float sd = g_sumdt[o];
        H0 = fmaf(__expf(Av0*sd), H0, hp.x);
        H1 = fmaf(__expf(Av1*sd), H1, hp.y);
        H2 = fmaf(__expf(Av2*sd), H2, hp.z);
        H3 = fmaf(__expf(Av3*sd), H3, hp.w);
    }
}

// ---------------- scan pass 3 ----------------
__global__ void scan3_k(const float* __restrict__ Dw) {
    __shared__ float Bsm[LC][4];
    __shared__ float Csm[LC][4];
    int chunk = blockIdx.x, b = blockIdx.y, d = threadIdx.x;
    int l0 = chunk * LC;
    for (int i = threadIdx.x; i < LC*4; i += DIN) {
        int l = i >> 2, s = i & 3;
        const float* row = g_xdbl + ((size_t)(b*LLEN + l0 + l))*XD + DTR;
        Bsm[l][s] = row[s];
        Csm[l][s] = row[4 + s];
    }
    __syncthreads();
    int slow = g_slow;
    float Av0 = g_A[d*4], Av1 = g_A[d*4+1], Av2 = g_A[d*4+2], Av3 = g_A[d*4+3];
    float Dd = Dw[d];
    int o = ((b*DIN) + d)*NC + chunk;
    float4 Hi = ((const float4*)g_Hinit)[o];
    float h0 = Hi.x, h1 = Hi.y, h2 = Hi.z, h3 = Hi.w;
    int base = (b*LLEN + l0)*DIN + d;
    for (int l = 0; l < LC; l++) {
        int idx = base + l*DIN;
        float dtv = g_dt[idx];
        float xav = g_xa[idx];
        float dbu = dtv * xav;
        float b0 = Bsm[l][0], b1 = Bsm[l][1], b2 = Bsm[l][2], b3 = Bsm[l][3];
        if (!slow) {
            float e = g_e1[idx];
            float p = e;
            h0 = fmaf(p, h0, dbu*b0); p *= e;
            h1 = fmaf(p, h1, dbu*b1); p *= e;
            h2 = fmaf(p, h2, dbu*b2); p *= e;
            h3 = fmaf(p, h3, dbu*b3);
        } else {
            h0 = fmaf(__expf(dtv*Av0), h0, dbu*b0);
            h1 = fmaf(__expf(dtv*Av1), h1, dbu*b1);
            h2 = fmaf(__expf(dtv*Av2), h2, dbu*b2);
            h3 = fmaf(__expf(dtv*Av3), h3, dbu*b3);
        }
        float y = h0*Csm[l][0] + h1*Csm[l][1] + h2*Csm[l][2] + h3*Csm[l][3];
        y = fmaf(xav, Dd, y);
        float zv = g_xz[((size_t)(b*LLEN + l0 + l))*(2*DIN) + DIN + d];
        float zs = __fdividef(zv, 1.f + __expf(-zv));
        g_y[idx] = y * zs;
    }
}

// ---------------- final: low-rank UV + residual + LayerNorm + transpose out ----------------
__global__ void final_k(const float* __restrict__ U, const float* __restrict__ V,
                        const float* __restrict__ lng, const float* __restrict__ lnb,
                        float* __restrict__ out)
{
    __shared__ float Ush[4*CEMB];
    __shared__ float Vsh[CEMB*4];
    __shared__ float u[32][4];
    __shared__ float vs[32][193];
    __shared__ float mu[32], rsd[32];
    int b = blockIdx.y;
    int l0 = blockIdx.x * 32;
    int tid = threadIdx.x;
    for (int i = tid; i < 4*CEMB; i += 256) { Ush[i] = U[i]; Vsh[i] = V[i]; }
    __syncthreads();
    if (tid < 128) {
        int p = tid >> 2, r = tid & 3;
        const float* hr = g_h3 + ((size_t)(b*LLEN) + l0 + p)*CEMB;
        float a = 0.f;
        #pragma unroll 8
        for (int c = 0; c < CEMB; c++) a = fmaf(hr[c], Ush[r*CEMB + c], a);
        u[p][r] = a;
    }
    __syncthreads();
    for (int i = tid; i < 32*CEMB; i += 256) {
        int p = i / CEMB, c = i % CEMB;
        float v = g_xh[((size_t)(b*LLEN) + l0 + p)*CEMB + c];
        v = fmaf(Vsh[c*4+0], u[p][0], v);
        v = fmaf(Vsh[c*4+1], u[p][1], v);
        v = fmaf(Vsh[c*4+2], u[p][2], v);
        v = fmaf(Vsh[c*4+3], u[p][3], v);
        vs[p][c] = v;
    }
    __syncthreads();
    int warp = tid >> 5, lane = tid & 31;
    #pragma unroll
    for (int pp = 0; pp < 4; pp++) {
        int p = warp*4 + pp;
        float s = 0.f, ss = 0.f;
        for (int c = lane; c < CEMB; c += 32) {
            float v = vs[p][c];
            s += v; ss = fmaf(v, v, ss);
        }
        #pragma unroll
        for (int off = 16; off > 0; off >>= 1) {
            s  += __shfl_xor_sync(0xffffffffu, s, off);
            ss += __shfl_xor_sync(0xffffffffu, ss, off);
        }
        if (lane == 0) {
            float m = s * (1.f/CEMB);
            mu[p] = m;
            rsd[p] = rsqrtf(ss * (1.f/CEMB) - m*m + 1e-5f);
        }
    }
    __syncthreads();
    for (int c = warp; c < CEMB; c += 8) {
        int p = lane;
        float v = (vs[p][c] - mu[p]) * rsd[p] * lng[c] + lnb[c];
        out[((size_t)(b*CEMB) + c)*LLEN + l0 + lane] = v;
    }
}

// ---------------- launch ----------------
extern "C" void kernel_launch(void* const* d_in, const int* in_sizes, int n_in,
                              void* d_out, int out_size)
{
    const float* x         = (const float*)d_in[0];
    const float* in_proj_w = (const float*)d_in[1];
    const float* conv_w    = (const float*)d_in[2];
    const float* conv_b    = (const float*)d_in[3];
    const float* x_proj_w  = (const float*)d_in[4];
    const float* dt_proj_w = (const float*)d_in[5];
    const float* dt_proj_b = (const float*)d_in[6];
    const float* A_log     = (const float*)d_in[7];
    const float* Dw        = (const float*)d_in[8];
    const float* out_proj_w= (const float*)d_in[9];
    const float* U_w       = (const float*)d_in[10];
    const float* V_w       = (const float*)d_in[11];
    const float* ln_g      = (const float*)d_in[12];
    const float* ln_b      = (const float*)d_in[13];
    float* out = (float*)d_out;

    float* g_xh_p;  cudaGetSymbolAddress((void**)&g_xh_p,  g_xh);
    float* g_h2_p;  cudaGetSymbolAddress((void**)&g_h2_p,  g_h2);
    float* g_h3_p;  cudaGetSymbolAddress((void**)&g_h3_p,  g_h3);
    float* g_xz_p;  cudaGetSymbolAddress((void**)&g_xz_p,  g_xz);
    float* g_y_p;   cudaGetSymbolAddress((void**)&g_y_p,   g_y);

    transpose_k<<<dim3(LLEN/32, CEMB/32, BB), dim3(32, 8)>>>(x);

    const float* cur = g_xh_p;
    float* nxt_bufs[2] = { g_h2_p, g_h3_p };

    for (int mix = 0; mix < 2; mix++) {
        prepA_k<<<1, DIN>>>(A_log + mix*DIN*4);
        gemm_mma<<<dim3((2*DIN)/64, MROWS/128), 256>>>(
            cur, in_proj_w + (size_t)mix*2*DIN*CEMB, g_xz_p, MROWS, 2*DIN, CEMB);
        conv_k<<<(MROWS*DIN + 255)/256, 256>>>(conv_w + mix*DIN*4, conv_b + mix*DIN);
        xproj_k<<<MROWS/8, 256>>>(x_proj_w + (size_t)mix*XD*DIN);
        dt_k<<<MROWS, DIN>>>(dt_proj_w + (size_t)mix*DIN*DTR, dt_proj_b + mix*DIN);
        scan1_k<<<dim3(NC, BB), DIN>>>();
        scan2_k<<<(BB*DIN + 255)/256, 256>>>();
        scan3_k<<<dim3(NC, BB), DIN>>>(Dw + mix*DIN);
        gemm_mma<<<dim3(CEMB/64, MROWS/128), 256>>>(
            g_y_p, out_proj_w + (size_t)mix*CEMB*DIN, nxt_bufs[mix], MROWS, CEMB, DIN);
        cur = nxt_bufs[mix];
    }

    final_k<<<dim3(LLEN/32, BB), 256>>>(U_w, V_w, ln_g, ln_b, out);
}

// round 4
// speedup vs baseline: 1.5133x; 1.1644x over previous
#include <cuda_runtime.h>
#include <cstdint>

#define BB   8
#define LLEN 4096
#define CEMB 192
#define DIN  384
#define XD   20
#define DTR  12
#define NC   128
#define LC   32
#define MROWS (BB*LLEN)

// ---------------- scratch ----------------
__device__ float g_xh  [MROWS*CEMB];
__device__ float g_h2  [MROWS*CEMB];
__device__ float g_h3  [MROWS*CEMB];
__device__ float g_xz  [MROWS*2*DIN];
__device__ float g_xa  [MROWS*DIN];
__device__ float g_dt  [MROWS*DIN];
__device__ float g_e1  [MROWS*DIN];
__device__ float g_y   [MROWS*DIN];
__device__ float g_xdbl[MROWS*XD];
__device__ float g_hpart[BB*DIN*NC*4];
__device__ float g_sumdt[BB*DIN*NC];
__device__ float g_Hinit[BB*DIN*NC*4];
__device__ float g_A[DIN*4];
__device__ int   g_slow;

__device__ __forceinline__ uint32_t smem_u32(const void* p) {
    uint32_t a;
    asm("{ .reg .u64 t; cvta.to.shared.u64 t, %1; cvt.u32.u64 %0, t; }" : "=r"(a) : "l"(p));
    return a;
}

// ======================= split-bf16 HMMA GEMM: C[M,N] = A[M,K] @ W[N,K]^T =======================
__device__ __forceinline__ void cvt_hilo(float4 v, uint32_t& h0, uint32_t& h1,
                                         uint32_t& l0, uint32_t& l1) {
    asm("cvt.rn.bf16x2.f32 %0, %1, %2;" : "=r"(h0) : "f"(v.y), "f"(v.x));
    asm("cvt.rn.bf16x2.f32 %0, %1, %2;" : "=r"(h1) : "f"(v.w), "f"(v.z));
    float a0 = v.x - __uint_as_float(h0 << 16);
    float a1 = v.y - __uint_as_float(h0 & 0xffff0000u);
    float a2 = v.z - __uint_as_float(h1 << 16);
    float a3 = v.w - __uint_as_float(h1 & 0xffff0000u);
    asm("cvt.rn.bf16x2.f32 %0, %1, %2;" : "=r"(l0) : "f"(a1), "f"(a0));
    asm("cvt.rn.bf16x2.f32 %0, %1, %2;" : "=r"(l1) : "f"(a3), "f"(a2));
}

__device__ __forceinline__ void load_tile(const float* __restrict__ g, int ld, int rows,
                                          char* hi, char* lo, int tid, int nthr) {
    for (int idx = tid; idx < rows * 16; idx += nthr) {
        int r = idx >> 4, q = idx & 15, k = q * 4;
        float4 v = *(const float4*)(g + (size_t)r * ld + k);
        uint32_t h0, h1, l0, l1;
        cvt_hilo(v, h0, h1, l0, l1);
        uint32_t off = (uint32_t)(r * 128 + (((q >> 1) ^ (r & 7)) << 4) + ((q & 1) << 3));
        *(uint2*)(hi + off) = make_uint2(h0, h1);
        *(uint2*)(lo + off) = make_uint2(l0, l1);
    }
}

#define LDSM_X4(r0, r1, r2, r3, addr) \
    asm volatile("ldmatrix.sync.aligned.m8n8.x4.shared.b16 {%0,%1,%2,%3}, [%4];" \
        : "=r"(r0), "=r"(r1), "=r"(r2), "=r"(r3) : "r"(addr))
#define LDSM_X2(r0, r1, addr) \
    asm volatile("ldmatrix.sync.aligned.m8n8.x2.shared.b16 {%0,%1}, [%2];" \
        : "=r"(r0), "=r"(r1) : "r"(addr))
#define MMA_BF16(c, a, b) \
    asm volatile("mma.sync.aligned.m16n8k16.row.col.f32.bf16.bf16.f32 " \
        "{%0,%1,%2,%3}, {%4,%5,%6,%7}, {%8,%9}, {%0,%1,%2,%3};" \
        : "+f"((c)[0]), "+f"((c)[1]), "+f"((c)[2]), "+f"((c)[3]) \
        : "r"((a)[0]), "r"((a)[1]), "r"((a)[2]), "r"((a)[3]), "r"((b)[0]), "r"((b)[1]))

__global__ void __launch_bounds__(256)
gemm_mma(const float* __restrict__ A, const float* __restrict__ W,
         float* __restrict__ C, int M, int N, int K)
{
    __shared__ __align__(1024) char sm[49152];
    char* AH = sm;
    char* AL = sm + 16384;
    char* WH = sm + 32768;
    char* WL = sm + 40960;

    const int tid = threadIdx.x, wid = tid >> 5, lane = tid & 31;
    const int wm = wid & 3, wn = wid >> 2;
    const int bm = blockIdx.y * 128, bn = blockIdx.x * 64;
    const uint32_t sAH = smem_u32(AH), sAL = smem_u32(AL);
    const uint32_t sWH = smem_u32(WH), sWL = smem_u32(WL);

    float acc[2][4][4];
    #pragma unroll
    for (int i = 0; i < 2; i++)
        #pragma unroll
        for (int j = 0; j < 4; j++)
            #pragma unroll
            for (int q = 0; q < 4; q++) acc[i][j][q] = 0.f;

    const int nkt = K >> 6;
    for (int kt = 0; kt < nkt; kt++) {
        if (kt) __syncthreads();
        load_tile(A + (size_t)bm * K + kt * 64, K, 128, AH, AL, tid, 256);
        load_tile(W + (size_t)bn * K + kt * 64, K, 64,  WH, WL, tid, 256);
        __syncthreads();

        #pragma unroll
        for (int ks = 0; ks < 4; ks++) {
            uint32_t ah[2][4], al[2][4], bh[4][2], bl[4][2];
            #pragma unroll
            for (int mt = 0; mt < 2; mt++) {
                int r = wm * 32 + mt * 16 + (lane & 15);
                int c16 = ks * 2 + (lane >> 4);
                uint32_t off = (uint32_t)(r * 128 + ((c16 ^ (r & 7)) << 4));
                LDSM_X4(ah[mt][0], ah[mt][1], ah[mt][2], ah[mt][3], sAH + off);
                LDSM_X4(al[mt][0], al[mt][1], al[mt][2], al[mt][3], sAL + off);
            }
            #pragma unroll
            for (int nt = 0; nt < 4; nt++) {
                int rn = wn * 32 + nt * 8 + (lane & 7);
                int c16 = ks * 2 + ((lane >> 3) & 1);
                uint32_t off = (uint32_t)(rn * 128 + ((c16 ^ (rn & 7)) << 4));
                LDSM_X2(bh[nt][0], bh[nt][1], sWH + off);
                LDSM_X2(bl[nt][0], bl[nt][1], sWL + off);
            }
            #pragma unroll
            for (int mt = 0; mt < 2; mt++)
                #pragma unroll
                for (int nt = 0; nt < 4; nt++) {
                    MMA_BF16(acc[mt][nt], ah[mt], bh[nt]);
                    MMA_BF16(acc[mt][nt], ah[mt], bl[nt]);
                    MMA_BF16(acc[mt][nt], al[mt], bh[nt]);
                }
        }
    }

    #pragma unroll
    for (int mt = 0; mt < 2; mt++) {
        int row = bm + wm * 32 + mt * 16 + (lane >> 2);
        #pragma unroll
        for (int nt = 0; nt < 4; nt++) {
            int col = bn + wn * 32 + nt * 8 + (lane & 3) * 2;
            *(float2*)(C + (size_t)row * N + col)       = make_float2(acc[mt][nt][0], acc[mt][nt][1]);
            *(float2*)(C + (size_t)(row + 8) * N + col) = make_float2(acc[mt][nt][2], acc[mt][nt][3]);
        }
    }
}

// ---------------- transpose (B,C,L) -> (B,L,C) ----------------
__global__ void transpose_k(const float* __restrict__ x) {
    __shared__ float t[32][33];
    int b = blockIdx.z;
    int l0 = blockIdx.x * 32, c0 = blockIdx.y * 32;
    int tx = threadIdx.x, ty = threadIdx.y;
    #pragma unroll
    for (int j = ty; j < 32; j += 8)
        t[j][tx] = x[((b*CEMB) + (c0 + j)) * LLEN + l0 + tx];
    __syncthreads();
    #pragma unroll
    for (int j = ty; j < 32; j += 8)
        g_xh[((b*LLEN) + (l0 + j)) * CEMB + c0 + tx] = t[tx][j];
}

// ---------------- A structure prep ----------------
__global__ void prepA_k(const float* __restrict__ A_log) {
    int d = threadIdx.x;
    if (d == 0) g_slow = 0;
    __syncthreads();
    float a[4];
    #pragma unroll
    for (int s = 0; s < 4; s++) {
        a[s] = -expf(A_log[d*4 + s]);
        g_A[d*4 + s] = a[s];
    }
    bool ok = true;
    #pragma unroll
    for (int s = 0; s < 4; s++) {
        float want = (float)(s + 1) * a[0];
        if (fabsf(a[s] - want) > 1e-5f * fabsf(a[s]) + 1e-7f) ok = false;
    }
    if (!ok) atomicExch(&g_slow, 1);
}

// ---------------- depthwise causal conv (k=4) + silu, float4 vectorized ----------------
__global__ void conv_k(const float* __restrict__ w, const float* __restrict__ bias) {
    int idx = blockIdx.x * blockDim.x + threadIdx.x;     // over MROWS * DIN/4
    if (idx >= MROWS * (DIN/4)) return;
    int d4 = idx % (DIN/4);
    int bl = idx / (DIN/4);
    int l  = bl % LLEN;
    int d  = d4 * 4;
    // weights for 4 channels
    float4 wv0 = *(const float4*)(w + (d+0)*4);
    float4 wv1 = *(const float4*)(w + (d+1)*4);
    float4 wv2 = *(const float4*)(w + (d+2)*4);
    float4 wv3 = *(const float4*)(w + (d+3)*4);
    float4 bv  = *(const float4*)(bias + d);
    const float* p = g_xz + (size_t)bl * (2*DIN) + d;
    float4 acc = bv;
    if (l >= 3) {
        float4 v = *(const float4*)(p - 3*2*DIN);
        acc.x = fmaf(wv0.x, v.x, acc.x); acc.y = fmaf(wv1.x, v.y, acc.y);
        acc.z = fmaf(wv2.x, v.z, acc.z); acc.w = fmaf(wv3.x, v.w, acc.w);
    }
    if (l >= 2) {
        float4 v = *(const float4*)(p - 2*2*DIN);
        acc.x = fmaf(wv0.y, v.x, acc.x); acc.y = fmaf(wv1.y, v.y, acc.y);
        acc.z = fmaf(wv2.y, v.z, acc.z); acc.w = fmaf(wv3.y, v.w, acc.w);
    }
    if (l >= 1) {
        float4 v = *(const float4*)(p - 2*DIN);
        acc.x = fmaf(wv0.z, v.x, acc.x); acc.y = fmaf(wv1.z, v.y, acc.y);
        acc.z = fmaf(wv2.z, v.z, acc.z); acc.w = fmaf(wv3.z, v.w, acc.w);
    }
    {
        float4 v = *(const float4*)(p);
        acc.x = fmaf(wv0.w, v.x, acc.x); acc.y = fmaf(wv1.w, v.y, acc.y);
        acc.z = fmaf(wv2.w, v.z, acc.z); acc.w = fmaf(wv3.w, v.w, acc.w);
    }
    float4 s;
    s.x = __fdividef(acc.x, 1.f + __expf(-acc.x));
    s.y = __fdividef(acc.y, 1.f + __expf(-acc.y));
    s.z = __fdividef(acc.z, 1.f + __expf(-acc.z));
    s.w = __fdividef(acc.w, 1.f + __expf(-acc.w));
    *(float4*)(g_xa + (size_t)bl * DIN + d) = s;
}

// ---------------- x_proj ----------------
__global__ void xproj_k(const float* __restrict__ W) {
    __shared__ float Wsh[XD * DIN];
    for (int i = threadIdx.x; i < XD*DIN; i += 256) Wsh[i] = W[i];
    __syncthreads();
    int warp = threadIdx.x >> 5, lane = threadIdx.x & 31;
    int m = blockIdx.x * 8 + warp;
    const float* ar = g_xa + (size_t)m * DIN;
    float acc[XD];
    #pragma unroll
    for (int n = 0; n < XD; n++) acc[n] = 0.f;
    for (int k = lane; k < DIN; k += 32) {
        float a = ar[k];
        #pragma unroll
        for (int n = 0; n < XD; n++)
            acc[n] = fmaf(a, Wsh[n*DIN + k], acc[n]);
    }
    float myv = 0.f;
    #pragma unroll
    for (int n = 0; n < XD; n++) {
        float v = acc[n];
        #pragma unroll
        for (int off = 16; off > 0; off >>= 1)
            v += __shfl_xor_sync(0xffffffffu, v, off);
        if (lane == n) myv = v;
    }
    if (lane < XD) g_xdbl[(size_t)m*XD + lane] = myv;
}

// ---------------- dt ----------------
__global__ void dt_k(const float* __restrict__ dtw, const float* __restrict__ dtb) {
    __shared__ float dl[DTR];
    int m = blockIdx.x, n = threadIdx.x;
    if (n < DTR) dl[n] = g_xdbl[(size_t)m*XD + n];
    __syncthreads();
    float p = dtb[n];
    const float4* w4 = (const float4*)(dtw + n*DTR);
    #pragma unroll
    for (int q = 0; q < 3; q++) {
        float4 w = w4[q];
        p = fmaf(dl[q*4+0], w.x, p);
        p = fmaf(dl[q*4+1], w.y, p);
        p = fmaf(dl[q*4+2], w.z, p);
        p = fmaf(dl[q*4+3], w.w, p);
    }
    float dv = (p > 20.f) ? p : __logf(1.f + __expf(p));
    int idx = m*DIN + n;
    g_dt[idx] = dv;
    g_e1[idx] = __expf(g_A[n*4] * dv);
}

// ---------------- scan pass 1 ----------------
__global__ void scan1_k() {
    __shared__ float Bsm[LC][4];
    int chunk = blockIdx.x, b = blockIdx.y, d = threadIdx.x;
    int l0 = chunk * LC;
    if (threadIdx.x < LC*4) {
        int l = threadIdx.x >> 2, s = threadIdx.x & 3;
        Bsm[l][s] = g_xdbl[((size_t)(b*LLEN + l0 + l))*XD + DTR + s];
    }
    __syncthreads();
    int slow = g_slow;
    float Av0 = g_A[d*4], Av1 = g_A[d*4+1], Av2 = g_A[d*4+2], Av3 = g_A[d*4+3];
    float h0 = 0.f, h1 = 0.f, h2 = 0.f, h3 = 0.f, sd = 0.f;
    int base = (b*LLEN + l0)*DIN + d;
    #pragma unroll 4
    for (int l = 0; l < LC; l++) {
        int idx = base + l*DIN;
        float dtv = g_dt[idx];
        float xav = g_xa[idx];
        float dbu = dtv * xav;
        sd += dtv;
        float b0 = Bsm[l][0], b1 = Bsm[l][1], b2 = Bsm[l][2], b3 = Bsm[l][3];
        if (!slow) {
            float e = g_e1[idx];
            float p = e;
            h0 = fmaf(p, h0, dbu*b0); p *= e;
            h1 = fmaf(p, h1, dbu*b1); p *= e;
            h2 = fmaf(p, h2, dbu*b2); p *= e;
            h3 = fmaf(p, h3, dbu*b3);
        } else {
            h0 = fmaf(__expf(dtv*Av0), h0, dbu*b0);
            h1 = fmaf(__expf(dtv*Av1), h1, dbu*b1);
            h2 = fmaf(__expf(dtv*Av2), h2, dbu*b2);
            h3 = fmaf(__expf(dtv*Av3), h3, dbu*b3);
        }
    }
    int o = ((b*DIN) + d)*NC + chunk;
    ((float4*)g_hpart)[o] = make_float4(h0, h1, h2, h3);
    g_sumdt[o] = sd;
}

// ---------------- scan pass 2 ----------------
__global__ void scan2_k() {
    int t = blockIdx.x * blockDim.x + threadIdx.x;
    if (t >= BB*DIN) return;
    int d = t % DIN;
    float Av0 = g_A[d*4], Av1 = g_A[d*4+1], Av2 = g_A[d*4+2], Av3 = g_A[d*4+3];
    float H0 = 0.f, H1 = 0.f, H2 = 0.f, H3 = 0.f;
    for (int c = 0; c < NC; c++) {
        int o = t*NC + c;
        ((float4*)g_Hinit)[o] = make_float4(H0, H1, H2, H3);
        float4 hp = ((const float4*)g_hpart)[o];
        float sd = g_sumdt[o];
        H0 = fmaf(__expf(Av0*sd), H0, hp.x);
        H1 = fmaf(__expf(Av1*sd), H1, hp.y);
        H2 = fmaf(__expf(Av2*sd), H2, hp.z);
        H3 = fmaf(__expf(Av3*sd), H3, hp.w);
    }
}

// ---------------- scan pass 3 ----------------
__global__ void scan3_k(const float* __restrict__ Dw) {
    __shared__ float Bsm[LC][4];
    __shared__ float Csm[LC][4];
    int chunk = blockIdx.x, b = blockIdx.y, d = threadIdx.x;
    int l0 = chunk * LC;
    if (threadIdx.x < LC*8) {
        int l = threadIdx.x >> 3, s = threadIdx.x & 7;
        float v = g_xdbl[((size_t)(b*LLEN + l0 + l))*XD + DTR + s];
        if (s < 4) Bsm[l][s] = v; else Csm[l][s-4] = v;
    }
    __syncthreads();
    int slow = g_slow;
    float Av0 = g_A[d*4], Av1 = g_A[d*4+1], Av2 = g_A[d*4+2], Av3 = g_A[d*4+3];
    float Dd = Dw[d];
    int o = ((b*DIN) + d)*NC + chunk;
    float4 Hi = ((const float4*)g_Hinit)[o];
    float h0 = Hi.x, h1 = Hi.y, h2 = Hi.z, h3 = Hi.w;
    int base = (b*LLEN + l0)*DIN + d;
    #pragma unroll 4
    for (int l = 0; l < LC; l++) {
        int idx = base + l*DIN;
        float dtv = g_dt[idx];
        float xav = g_xa[idx];
        float dbu = dtv * xav;
        float b0 = Bsm[l][0], b1 = Bsm[l][1], b2 = Bsm[l][2], b3 = Bsm[l][3];
        if (!slow) {
            float e = g_e1[idx];
            float p = e;
            h0 = fmaf(p, h0, dbu*b0); p *= e;
            h1 = fmaf(p, h1, dbu*b1); p *= e;
            h2 = fmaf(p, h2, dbu*b2); p *= e;
            h3 = fmaf(p, h3, dbu*b3);
        } else {
            h0 = fmaf(__expf(dtv*Av0), h0, dbu*b0);
            h1 = fmaf(__expf(dtv*Av1), h1, dbu*b1);
            h2 = fmaf(__expf(dtv*Av2), h2, dbu*b2);
            h3 = fmaf(__expf(dtv*Av3), h3, dbu*b3);
        }
        float y = h0*Csm[l][0] + h1*Csm[l][1] + h2*Csm[l][2] + h3*Csm[l][3];
        y = fmaf(xav, Dd, y);
        float zv = g_xz[((size_t)(b*LLEN + l0 + l))*(2*DIN) + DIN + d];
        float zs = __fdividef(zv, 1.f + __expf(-zv));
        g_y[idx] = y * zs;
    }
}

// ---------------- final: low-rank UV + residual + LayerNorm + transpose out ----------------
__global__ void final_k(const float* __restrict__ U, const float* __restrict__ V,
                        const float* __restrict__ lng, const float* __restrict__ lnb,
                        float* __restrict__ out)
{
    __shared__ float Ush[4*CEMB];
    __shared__ float Vsh[CEMB*4];
    __shared__ float u[32][4];
    __shared__ float vs[32][193];
    __shared__ float mu[32], rsd[32];
    int b = blockIdx.y;
    int l0 = blockIdx.x * 32;
    int tid = threadIdx.x;
    for (int i = tid; i < 4*CEMB; i += 256) { Ush[i] = U[i]; Vsh[i] = V[i]; }
    __syncthreads();
    if (tid < 128) {
        int p = tid >> 2, r = tid & 3;
        const float* hr = g_h3 + ((size_t)(b*LLEN) + l0 + p)*CEMB;
        float a = 0.f;
        #pragma unroll 8
        for (int c = 0; c < CEMB; c++) a = fmaf(hr[c], Ush[r*CEMB + c], a);
        u[p][r] = a;
    }
    __syncthreads();
    for (int i = tid; i < 32*CEMB; i += 256) {
        int p = i / CEMB, c = i % CEMB;
        float v = g_xh[((size_t)(b*LLEN) + l0 + p)*CEMB + c];
        v = fmaf(Vsh[c*4+0], u[p][0], v);
        v = fmaf(Vsh[c*4+1], u[p][1], v);
        v = fmaf(Vsh[c*4+2], u[p][2], v);
        v = fmaf(Vsh[c*4+3], u[p][3], v);
        vs[p][c] = v;
    }
    __syncthreads();
    int warp = tid >> 5, lane = tid & 31;
    #pragma unroll
    for (int pp = 0; pp < 4; pp++) {
        int p = warp*4 + pp;
        float s = 0.f, ss = 0.f;
        for (int c = lane; c < CEMB; c += 32) {
            float v = vs[p][c];
            s += v; ss = fmaf(v, v, ss);
        }
        #pragma unroll
        for (int off = 16; off > 0; off >>= 1) {
            s  += __shfl_xor_sync(0xffffffffu, s, off);
            ss += __shfl_xor_sync(0xffffffffu, ss, off);
        }
        if (lane == 0) {
            float m = s * (1.f/CEMB);
            mu[p] = m;
            rsd[p] = rsqrtf(ss * (1.f/CEMB) - m*m + 1e-5f);
        }
    }
    __syncthreads();
    for (int c = warp; c < CEMB; c += 8) {
        int p = lane;
        float v = (vs[p][c] - mu[p]) * rsd[p] * lng[c] + lnb[c];
        out[((size_t)(b*CEMB) + c)*LLEN + l0 + lane] = v;
    }
}

// ---------------- launch ----------------
extern "C" void kernel_launch(void* const* d_in, const int* in_sizes, int n_in,
                              void* d_out, int out_size)
{
    const float* x         = (const float*)d_in[0];
    const float* in_proj_w = (const float*)d_in[1];
    const float* conv_w    = (const float*)d_in[2];
    const float* conv_b    = (const float*)d_in[3];
    const float* x_proj_w  = (const float*)d_in[4];
    const float* dt_proj_w = (const float*)d_in[5];
    const float* dt_proj_b = (const float*)d_in[6];
    const float* A_log     = (const float*)d_in[7];
    const float* Dw        = (const float*)d_in[8];
    const float* out_proj_w= (const float*)d_in[9];
    const float* U_w       = (const float*)d_in[10];
    const float* V_w       = (const float*)d_in[11];
    const float* ln_g      = (const float*)d_in[12];
    const float* ln_b      = (const float*)d_in[13];
    float* out = (float*)d_out;

    float* g_xh_p;  cudaGetSymbolAddress((void**)&g_xh_p,  g_xh);
    float* g_h2_p;  cudaGetSymbolAddress((void**)&g_h2_p,  g_h2);
    float* g_h3_p;  cudaGetSymbolAddress((void**)&g_h3_p,  g_h3);
    float* g_xz_p;  cudaGetSymbolAddress((void**)&g_xz_p,  g_xz);
    float* g_y_p;   cudaGetSymbolAddress((void**)&g_y_p,   g_y);

    transpose_k<<<dim3(LLEN/32, CEMB/32, BB), dim3(32, 8)>>>(x);

    const float* cur = g_xh_p;
    float* nxt_bufs[2] = { g_h2_p, g_h3_p };

    for (int mix = 0; mix < 2; mix++) {
        prepA_k<<<1, DIN>>>(A_log + mix*DIN*4);
        gemm_mma<<<dim3((2*DIN)/64, MROWS/128), 256>>>(
            cur, in_proj_w + (size_t)mix*2*DIN*CEMB, g_xz_p, MROWS, 2*DIN, CEMB);
        conv_k<<<(MROWS*(DIN/4) + 255)/256, 256>>>(conv_w + mix*DIN*4, conv_b + mix*DIN);
        xproj_k<<<MROWS/8, 256>>>(x_proj_w + (size_t)mix*XD*DIN);
        dt_k<<<MROWS, DIN>>>(dt_proj_w + (size_t)mix*DIN*DTR, dt_proj_b + mix*DIN);
        scan1_k<<<dim3(NC, BB), DIN>>>();
        scan2_k<<<(BB*DIN + 255)/256, 256>>>();
        scan3_k<<<dim3(NC, BB), DIN>>>(Dw + mix*DIN);
        gemm_mma<<<dim3(CEMB/64, MROWS/128), 256>>>(
            g_y_p, out_proj_w + (size_t)mix*CEMB*DIN, nxt_bufs[mix], MROWS, CEMB, DIN);
        cur = nxt_bufs[mix];
    }

    final_k<<<dim3(LLEN/32, BB), 256>>>(U_w, V_w, ln_g, ln_b, out);
}

// round 5
// speedup vs baseline: 1.5907x; 1.0511x over previous
#include <cuda_runtime.h>
#include <cstdint>

#define BB   8
#define LLEN 4096
#define CEMB 192
#define DIN  384
#define XD   20
#define DTR  12
#define NC   128
#define LC   32
#define MROWS (BB*LLEN)

// ---------------- scratch ----------------
__device__ float g_xh  [MROWS*CEMB];
__device__ float g_h2  [MROWS*CEMB];
__device__ float g_h3  [MROWS*CEMB];
__device__ float g_xz  [MROWS*2*DIN];
__device__ float4 g_pack[MROWS*DIN];      // (dt, xa, e1, silu(z))
__device__ float g_bc  [MROWS*8];         // B[4] | C[4] per row
__device__ float g_y   [MROWS*DIN];
__device__ float g_hpart[BB*DIN*NC*4];
__device__ float g_sumdt[BB*DIN*NC];
__device__ float g_Hinit[BB*DIN*NC*4];
__device__ float g_A[DIN*4];
__device__ int   g_slow;

__device__ __forceinline__ uint32_t smem_u32(const void* p) {
    uint32_t a;
    asm("{ .reg .u64 t; cvta.to.shared.u64 t, %1; cvt.u32.u64 %0, t; }" : "=r"(a) : "l"(p));
    return a;
}

// ======================= split-bf16 HMMA GEMM (pipelined) =======================
__device__ __forceinline__ void cvt_hilo(float4 v, uint32_t& h0, uint32_t& h1,
                                         uint32_t& l0, uint32_t& l1) {
    asm("cvt.rn.bf16x2.f32 %0, %1, %2;" : "=r"(h0) : "f"(v.y), "f"(v.x));
    asm("cvt.rn.bf16x2.f32 %0, %1, %2;" : "=r"(h1) : "f"(v.w), "f"(v.z));
    float a0 = v.x - __uint_as_float(h0 << 16);
    float a1 = v.y - __uint_as_float(h0 & 0xffff0000u);
    float a2 = v.z - __uint_as_float(h1 << 16);
    float a3 = v.w - __uint_as_float(h1 & 0xffff0000u);
    asm("cvt.rn.bf16x2.f32 %0, %1, %2;" : "=r"(l0) : "f"(a1), "f"(a0));
    asm("cvt.rn.bf16x2.f32 %0, %1, %2;" : "=r"(l1) : "f"(a3), "f"(a2));
}

#define LDSM_X4(r0, r1, r2, r3, addr) \
    asm volatile("ldmatrix.sync.aligned.m8n8.x4.shared.b16 {%0,%1,%2,%3}, [%4];" \
        : "=r"(r0), "=r"(r1), "=r"(r2), "=r"(r3) : "r"(addr))
#define LDSM_X2(r0, r1, addr) \
    asm volatile("ldmatrix.sync.aligned.m8n8.x2.shared.b16 {%0,%1}, [%2];" \
        : "=r"(r0), "=r"(r1) : "r"(addr))
#define MMA_BF16(c, a, b) \
    asm volatile("mma.sync.aligned.m16n8k16.row.col.f32.bf16.bf16.f32 " \
        "{%0,%1,%2,%3}, {%4,%5,%6,%7}, {%8,%9}, {%0,%1,%2,%3};" \
        : "+f"((c)[0]), "+f"((c)[1]), "+f"((c)[2]), "+f"((c)[3]) \
        : "r"((a)[0]), "r"((a)[1]), "r"((a)[2]), "r"((a)[3]), "r"((b)[0]), "r"((b)[1]))

__global__ void __launch_bounds__(256, 2)
gemm_mma(const float* __restrict__ A, const float* __restrict__ W,
         float* __restrict__ C, int M, int N, int K)
{
    __shared__ __align__(1024) char sm[49152];
    char* AH = sm;
    char* AL = sm + 16384;
    char* WH = sm + 32768;
    char* WL = sm + 40960;

    const int tid = threadIdx.x, wid = tid >> 5, lane = tid & 31;
    const int wm = wid & 3, wn = wid >> 2;
    const int bm = blockIdx.y * 128, bn = blockIdx.x * 64;
    const uint32_t sAH = smem_u32(AH), sAL = smem_u32(AL);
    const uint32_t sWH = smem_u32(WH), sWL = smem_u32(WL);

    float acc[2][4][4];
    #pragma unroll
    for (int i = 0; i < 2; i++)
        #pragma unroll
        for (int j = 0; j < 4; j++)
            #pragma unroll
            for (int q = 0; q < 4; q++) acc[i][j][q] = 0.f;

    float4 ra[8], rw[4];
    const int nkt = K >> 6;

    // prefetch kt=0
    #pragma unroll
    for (int i = 0; i < 8; i++) {
        int idx = tid + i * 256, r = idx >> 4, q = idx & 15;
        ra[i] = *(const float4*)(A + (size_t)(bm + r) * K + q * 4);
    }
    #pragma unroll
    for (int i = 0; i < 4; i++) {
        int idx = tid + i * 256, r = idx >> 4, q = idx & 15;
        rw[i] = *(const float4*)(W + (size_t)(bn + r) * K + q * 4);
    }

    for (int kt = 0; kt < nkt; kt++) {
        // store staged regs -> swizzled smem (with hi/lo split)
        #pragma unroll
        for (int i = 0; i < 8; i++) {
            int idx = tid + i * 256, r = idx >> 4, q = idx & 15;
            uint32_t h0, h1, l0, l1;
            cvt_hilo(ra[i], h0, h1, l0, l1);
            uint32_t off = (uint32_t)(r * 128 + (((q >> 1) ^ (r & 7)) << 4) + ((q & 1) << 3));
            *(uint2*)(AH + off) = make_uint2(h0, h1);
            *(uint2*)(AL + off) = make_uint2(l0, l1);
        }
        #pragma unroll
        for (int i = 0; i < 4; i++) {
            int idx = tid + i * 256, r = idx >> 4, q = idx & 15;
            uint32_t h0, h1, l0, l1;
            cvt_hilo(rw[i], h0, h1, l0, l1);
            uint32_t off = (uint32_t)(r * 128 + (((q >> 1) ^ (r & 7)) << 4) + ((q & 1) << 3));
            *(uint2*)(WH + off) = make_uint2(h0, h1);
            *(uint2*)(WL + off) = make_uint2(l0, l1);
        }
        __syncthreads();

        // prefetch next kt (overlaps MMA below)
        if (kt + 1 < nkt) {
            int k0 = (kt + 1) * 64;
            #pragma unroll
            for (int i = 0; i < 8; i++) {
                int idx = tid + i * 256, r = idx >> 4, q = idx & 15;
                ra[i] = *(const float4*)(A + (size_t)(bm + r) * K + k0 + q * 4);
            }
            #pragma unroll
            for (int i = 0; i < 4; i++) {
                int idx = tid + i * 256, r = idx >> 4, q = idx & 15;
                rw[i] = *(const float4*)(W + (size_t)(bn + r) * K + k0 + q * 4);
            }
        }

        #pragma unroll
        for (int ks = 0; ks < 4; ks++) {
            uint32_t ah[2][4], al[2][4], bh[4][2], bl[4][2];
            #pragma unroll
            for (int mt = 0; mt < 2; mt++) {
                int r = wm * 32 + mt * 16 + (lane & 15);
                int c16 = ks * 2 + (lane >> 4);
                uint32_t off = (uint32_t)(r * 128 + ((c16 ^ (r & 7)) << 4));
                LDSM_X4(ah[mt][0], ah[mt][1], ah[mt][2], ah[mt][3], sAH + off);
                LDSM_X4(al[mt][0], al[mt][1], al[mt][2], al[mt][3], sAL + off);
            }
            #pragma unroll
            for (int nt = 0; nt < 4; nt++) {
                int rn = wn * 32 + nt * 8 + (lane & 7);
                int c16 = ks * 2 + ((lane >> 3) & 1);
                uint32_t off = (uint32_t)(rn * 128 + ((c16 ^ (rn & 7)) << 4));
                LDSM_X2(bh[nt][0], bh[nt][1], sWH + off);
                LDSM_X2(bl[nt][0], bl[nt][1], sWL + off);
            }
            #pragma unroll
            for (int mt = 0; mt < 2; mt++)
                #pragma unroll
                for (int nt = 0; nt < 4; nt++) {
                    MMA_BF16(acc[mt][nt], ah[mt], bh[nt]);
                    MMA_BF16(acc[mt][nt], ah[mt], bl[nt]);
                    MMA_BF16(acc[mt][nt], al[mt], bh[nt]);
                }
        }
        __syncthreads();
    }

    #pragma unroll
    for (int mt = 0; mt < 2; mt++) {
        int row = bm + wm * 32 + mt * 16 + (lane >> 2);
        #pragma unroll
        for (int nt = 0; nt < 4; nt++) {
            int col = bn + wn * 32 + nt * 8 + (lane & 3) * 2;
            *(float2*)(C + (size_t)row * N + col)       = make_float2(acc[mt][nt][0], acc[mt][nt][1]);
            *(float2*)(C + (size_t)(row + 8) * N + col) = make_float2(acc[mt][nt][2], acc[mt][nt][3]);
        }
    }
}

// ---------------- transpose (B,C,L) -> (B,L,C) ----------------
__global__ void transpose_k(const float* __restrict__ x) {
    __shared__ float t[32][33];
    int b = blockIdx.z;
    int l0 = blockIdx.x * 32, c0 = blockIdx.y * 32;
    int tx = threadIdx.x, ty = threadIdx.y;
    #pragma unroll
    for (int j = ty; j < 32; j += 8)
        t[j][tx] = x[((b*CEMB) + (c0 + j)) * LLEN + l0 + tx];
    __syncthreads();
    #pragma unroll
    for (int j = ty; j < 32; j += 8)
        g_xh[((b*LLEN) + (l0 + j)) * CEMB + c0 + tx] = t[tx][j];
}

// ---------------- A structure prep ----------------
__global__ void prepA_k(const float* __restrict__ A_log) {
    int d = threadIdx.x;
    if (d == 0) g_slow = 0;
    __syncthreads();
    float a[4];
    #pragma unroll
    for (int s = 0; s < 4; s++) {
        a[s] = -expf(A_log[d*4 + s]);
        g_A[d*4 + s] = a[s];
    }
    bool ok = true;
    #pragma unroll
    for (int s = 0; s < 4; s++) {
        float want = (float)(s + 1) * a[0];
        if (fabsf(a[s] - want) > 1e-5f * fabsf(a[s]) + 1e-7f) ok = false;
    }
    if (!ok) atomicExch(&g_slow, 1);
}

// ---------------- fused front: conv+silu -> x_proj -> dt/e1 -> pack ----------------
__global__ void __launch_bounds__(384)
front_k(const float* __restrict__ cw, const float* __restrict__ cb,
        const float* __restrict__ xpw, const float* __restrict__ dtw,
        const float* __restrict__ dtb)
{
    __shared__ float xa_s[32][DIN];      // 48 KB
    __shared__ float xdbl_s[32][12];
    __shared__ float Wsh[XD * DIN];      // 30 KB
    const int b = blockIdx.y, l0 = blockIdx.x * 32;
    const int d = threadIdx.x, warp = d >> 5, lane = d & 31;

    for (int i = d; i < XD * DIN; i += 384) Wsh[i] = xpw[i];

    // phase 1: rolling depthwise conv + silu
    {
        float4 wv = *(const float4*)(cw + d * 4);
        float bv = cb[d];
        const float* px = g_xz + ((size_t)(b * LLEN + l0)) * (2 * DIN) + d;
        float x1 = 0.f, x2 = 0.f, x3 = 0.f;
        if (l0) { x3 = px[-3 * 2 * DIN]; x2 = px[-2 * 2 * DIN]; x1 = px[-2 * DIN]; }
        #pragma unroll 4
        for (int l = 0; l < 32; l++) {
            float x0 = px[l * 2 * DIN];
            float acc = fmaf(wv.x, x3, fmaf(wv.y, x2, fmaf(wv.z, x1, fmaf(wv.w, x0, bv))));
            xa_s[l][d] = __fdividef(acc, 1.f + __expf(-acc));
            x3 = x2; x2 = x1; x1 = x0;
        }
    }
    __syncthreads();

    // phase 2: x_proj (20 outputs per row), rows strided over 12 warps
    for (int r = warp; r < 32; r += 12) {
        float acc[XD];
        #pragma unroll
        for (int n = 0; n < XD; n++) acc[n] = 0.f;
        for (int k = lane; k < DIN; k += 32) {
            float a = xa_s[r][k];
            #pragma unroll
            for (int n = 0; n < XD; n++)
                acc[n] = fmaf(a, Wsh[n * DIN + k], acc[n]);
        }
        float myv = 0.f;
        #pragma unroll
        for (int n = 0; n < XD; n++) {
            float v = acc[n];
            #pragma unroll
            for (int off = 16; off > 0; off >>= 1)
                v += __shfl_xor_sync(0xffffffffu, v, off);
            if (lane == n) myv = v;
        }
        if (lane < DTR) xdbl_s[r][lane] = myv;
        else if (lane < XD) g_bc[((size_t)(b * LLEN + l0 + r)) * 8 + (lane - DTR)] = myv;
    }
    __syncthreads();

    // phase 3: dt = softplus(dt_lr @ dtw^T + b), e1 = exp(A0*dt), zs = silu(z); pack
    {
        const float4* dw4 = (const float4*)(dtw + d * DTR);
        float4 dw0 = dw4[0], dw1 = dw4[1], dw2 = dw4[2];
        float pb = dtb[d];
        float A0 = g_A[d * 4];
        const float* pz = g_xz + ((size_t)(b * LLEN + l0)) * (2 * DIN) + DIN + d;
        float4* po = g_pack + ((size_t)(b * LLEN + l0)) * DIN + d;
        #pragma unroll 4
        for (int l = 0; l < 32; l++) {
            const float* xr = xdbl_s[l];
            float p = pb;
            p = fmaf(xr[0], dw0.x, p); p = fmaf(xr[1], dw0.y, p);
            p = fmaf(xr[2], dw0.z, p); p = fmaf(xr[3], dw0.w, p);
            p = fmaf(xr[4], dw1.x, p); p = fmaf(xr[5], dw1.y, p);
            p = fmaf(xr[6], dw1.z, p); p = fmaf(xr[7], dw1.w, p);
            p = fmaf(xr[8], dw2.x, p); p = fmaf(xr[9], dw2.y, p);
            p = fmaf(xr[10], dw2.z, p); p = fmaf(xr[11], dw2.w, p);
            float dv = (p > 20.f) ? p : __logf(1.f + __expf(p));
            float e1 = __expf(A0 * dv);
            float xav = xa_s[l][d];
            float zv = pz[l * 2 * DIN];
            float zs = __fdividef(zv, 1.f + __expf(-zv));
            po[l * DIN] = make_float4(dv, xav, e1, zs);
        }
    }
}

// ---------------- scan pass 1 ----------------
__global__ void scan1_k() {
    __shared__ float Bsm[LC][4];
    int chunk = blockIdx.x, b = blockIdx.y, d = threadIdx.x;
    int l0 = chunk * LC;
    if (threadIdx.x < LC*4) {
        int l = threadIdx.x >> 2, s = threadIdx.x & 3;
        Bsm[l][s] = g_bc[((size_t)(b*LLEN + l0 + l))*8 + s];
    }
    __syncthreads();
    int slow = g_slow;
    float Av0 = g_A[d*4], Av1 = g_A[d*4+1], Av2 = g_A[d*4+2], Av3 = g_A[d*4+3];
    float h0 = 0.f, h1 = 0.f, h2 = 0.f, h3 = 0.f, sd = 0.f;
    const float4* pp = g_pack + (size_t)(b*LLEN + l0)*DIN + d;
    #pragma unroll 4
    for (int l = 0; l < LC; l++) {
        float4 pk = pp[l*DIN];
        float dtv = pk.x, xav = pk.y;
        float dbu = dtv * xav;
        sd += dtv;
        float b0 = Bsm[l][0], b1 = Bsm[l][1], b2 = Bsm[l][2], b3 = Bsm[l][3];
        if (!slow) {
            float e = pk.z;
            float p = e;
            h0 = fmaf(p, h0, dbu*b0); p *= e;
            h1 = fmaf(p, h1, dbu*b1); p *= e;
            h2 = fmaf(p, h2, dbu*b2); p *= e;
            h3 = fmaf(p, h3, dbu*b3);
        } else {
            h0 = fmaf(__expf(dtv*Av0), h0, dbu*b0);
            h1 = fmaf(__expf(dtv*Av1), h1, dbu*b1);
            h2 = fmaf(__expf(dtv*Av2), h2, dbu*b2);
            h3 = fmaf(__expf(dtv*Av3), h3, dbu*b3);
        }
    }
    int o = ((b*DIN) + d)*NC + chunk;
    ((float4*)g_hpart)[o] = make_float4(h0, h1, h2, h3);
    g_sumdt[o] = sd;
}

// ---------------- scan pass 2 ----------------
__global__ void scan2_k() {
    int t = blockIdx.x * blockDim.x + threadIdx.x;
    if (t >= BB*DIN) return;
    int d = t % DIN;
    float Av0 = g_A[d*4], Av1 = g_A[d*4+1], Av2 = g_A[d*4+2], Av3 = g_A[d*4+3];
    float H0 = 0.f, H1 = 0.f, H2 = 0.f, H3 = 0.f;
    for (int c = 0; c < NC; c++) {
        int o = t*NC + c;
        ((float4*)g_Hinit)[o] = make_float4(H0, H1, H2, H3);
        float4 hp = ((const float4*)g_hpart)[o];
        float sd = g_sumdt[o];
        H0 = fmaf(__expf(Av0*sd), H0, hp.x);
        H1 = fmaf(__expf(Av1*sd), H1, hp.y);
        H2 = fmaf(__expf(Av2*sd), H2, hp.z);
        H3 = fmaf(__expf(Av3*sd), H3, hp.w);
    }
}

// ---------------- scan pass 3 ----------------
__global__ void scan3_k(const float* __restrict__ Dw) {
    __shared__ float Bsm[LC][4];
    __shared__ float Csm[LC][4];
    int chunk = blockIdx.x, b = blockIdx.y, d = threadIdx.x;
    int l0 = chunk * LC;
    if (threadIdx.x < LC*8) {
        int l = threadIdx.x >> 3, s = threadIdx.x & 7;
        float v = g_bc[((size_t)(b*LLEN + l0 + l))*8 + s];
        if (s < 4) Bsm[l][s] = v; else Csm[l][s-4] = v;
    }
    __syncthreads();
    int slow = g_slow;
    float Av0 = g_A[d*4], Av1 = g_A[d*4+1], Av2 = g_A[d*4+2], Av3 = g_A[d*4+3];
    float Dd = Dw[d];
    int o = ((b*DIN) + d)*NC + chunk;
    float4 Hi = ((const float4*)g_Hinit)[o];
    float h0 = Hi.x, h1 = Hi.y, h2 = Hi.z, h3 = Hi.w;
    const float4* pp = g_pack + (size_t)(b*LLEN + l0)*DIN + d;
    float* py = g_y + (size_t)(b*LLEN + l0)*DIN + d;
    #pragma unroll 4
    for (int l = 0; l < LC; l++) {
        float4 pk = pp[l*DIN];
        float dtv = pk.x, xav = pk.y, zs = pk.w;
        float dbu = dtv * xav;
        float b0 = Bsm[l][0], b1 = Bsm[l][1], b2 = Bsm[l][2], b3 = Bsm[l][3];
        if (!slow) {
            float e = pk.z;
            float p = e;
            h0 = fmaf(p, h0, dbu*b0); p *= e;
            h1 = fmaf(p, h1, dbu*b1); p *= e;
            h2 = fmaf(p, h2, dbu*b2); p *= e;
            h3 = fmaf(p, h3, dbu*b3);
        } else {
            h0 = fmaf(__expf(dtv*Av0), h0, dbu*b0);
            h1 = fmaf(__expf(dtv*Av1), h1, dbu*b1);
            h2 = fmaf(__expf(dtv*Av2), h2, dbu*b2);
            h3 = fmaf(__expf(dtv*Av3), h3, dbu*b3);
        }
        float y = h0*Csm[l][0] + h1*Csm[l][1] + h2*Csm[l][2] + h3*Csm[l][3];
        y = fmaf(xav, Dd, y);
        py[l*DIN] = y * zs;
    }
}

// ---------------- final: low-rank UV + residual + LayerNorm + transpose out ----------------
__global__ void final_k(const float* __restrict__ U, const float* __restrict__ V,
                        const float* __restrict__ lng, const float* __restrict__ lnb,
                        float* __restrict__ out)
{
    __shared__ float Ush[4*CEMB];
    __shared__ float Vsh[CEMB*4];
    __shared__ float u[32][4];
    __shared__ float vs[32][193];
    __shared__ float mu[32], rsd[32];
    int b = blockIdx.y;
    int l0 = blockIdx.x * 32;
    int tid = threadIdx.x;
    for (int i = tid; i < 4*CEMB; i += 256) { Ush[i] = U[i]; Vsh[i] = V[i]; }
    __syncthreads();
    if (tid < 128) {
        int p = tid >> 2, r = tid & 3;
        const float* hr = g_h3 + ((size_t)(b*LLEN) + l0 + p)*CEMB;
        float a = 0.f;
        #pragma unroll 8
        for (int c = 0; c < CEMB; c++) a = fmaf(hr[c], Ush[r*CEMB + c], a);
        u[p][r] = a;
    }
    __syncthreads();
    for (int i = tid; i < 32*CEMB; i += 256) {
        int p = i / CEMB, c = i % CEMB;
        float v = g_xh[((size_t)(b*LLEN) + l0 + p)*CEMB + c];
        v = fmaf(Vsh[c*4+0], u[p][0], v);
        v = fmaf(Vsh[c*4+1], u[p][1], v);
        v = fmaf(Vsh[c*4+2], u[p][2], v);
        v = fmaf(Vsh[c*4+3], u[p][3], v);
        vs[p][c] = v;
    }
    __syncthreads();
    int warp = tid >> 5, lane = tid & 31;
    #pragma unroll
    for (int pp = 0; pp < 4; pp++) {
        int p = warp*4 + pp;
        float s = 0.f, ss = 0.f;
        for (int c = lane; c < CEMB; c += 32) {
            float v = vs[p][c];
            s += v; ss = fmaf(v, v, ss);
        }
        #pragma unroll
        for (int off = 16; off > 0; off >>= 1) {
            s  += __shfl_xor_sync(0xffffffffu, s, off);
            ss += __shfl_xor_sync(0xffffffffu, ss, off);
        }
        if (lane == 0) {
            float m = s * (1.f/CEMB);
            mu[p] = m;
            rsd[p] = rsqrtf(ss * (1.f/CEMB) - m*m + 1e-5f);
        }
    }
    __syncthreads();
    for (int c = warp; c < CEMB; c += 8) {
        int p = lane;
        float v = (vs[p][c] - mu[p]) * rsd[p] * lng[c] + lnb[c];
        out[((size_t)(b*CEMB) + c)*LLEN + l0 + lane] = v;
    }
}

// ---------------- launch ----------------
extern "C" void kernel_launch(void* const* d_in, const int* in_sizes, int n_in,
                              void* d_out, int out_size)
{
    const float* x         = (const float*)d_in[0];
    const float* in_proj_w = (const float*)d_in[1];
    const float* conv_w    = (const float*)d_in[2];
    const float* conv_b    = (const float*)d_in[3];
    const float* x_proj_w  = (const float*)d_in[4];
    const float* dt_proj_w = (const float*)d_in[5];
    const float* dt_proj_b = (const float*)d_in[6];
    const float* A_log     = (const float*)d_in[7];
    const float* Dw        = (const float*)d_in[8];
    const float* out_proj_w= (const float*)d_in[9];
    const float* U_w       = (const float*)d_in[10];
    const float* V_w       = (const float*)d_in[11];
    const float* ln_g      = (const float*)d_in[12];
    const float* ln_b      = (const float*)d_in[13];
    float* out = (float*)d_out;

    float* g_xh_p;  cudaGetSymbolAddress((void**)&g_xh_p,  g_xh);
    float* g_h2_p;  cudaGetSymbolAddress((void**)&g_h2_p,  g_h2);
    float* g_h3_p;  cudaGetSymbolAddress((void**)&g_h3_p,  g_h3);
    float* g_xz_p;  cudaGetSymbolAddress((void**)&g_xz_p,  g_xz);
    float* g_y_p;   cudaGetSymbolAddress((void**)&g_y_p,   g_y);

    transpose_k<<<dim3(LLEN/32, CEMB/32, BB), dim3(32, 8)>>>(x);

    const float* cur = g_xh_p;
    float* nxt_bufs[2] = { g_h2_p, g_h3_p };

    for (int mix = 0; mix < 2; mix++) {
        prepA_k<<<1, DIN>>>(A_log + mix*DIN*4);
        gemm_mma<<<dim3((2*DIN)/64, MROWS/128), 256>>>(
            cur, in_proj_w + (size_t)mix*2*DIN*CEMB, g_xz_p, MROWS, 2*DIN, CEMB);
        front_k<<<dim3(LLEN/32, BB), 384>>>(conv_w + mix*DIN*4, conv_b + mix*DIN,
            x_proj_w + (size_t)mix*XD*DIN, dt_proj_w + (size_t)mix*DIN*DTR, dt_proj_b + mix*DIN);
        scan1_k<<<dim3(NC, BB), DIN>>>();
        scan2_k<<<(BB*DIN + 255)/256, 256>>>();
        scan3_k<<<dim3(NC, BB), DIN>>>(Dw + mix*DIN);
        gemm_mma<<<dim3(CEMB/64, MROWS/128), 256>>>(
            g_y_p, out_proj_w + (size_t)mix*CEMB*DIN, nxt_bufs[mix], MROWS, CEMB, DIN);
        cur = nxt_bufs[mix];
    }

    final_k<<<dim3(LLEN/32, BB), 256>>>(U_w, V_w, ln_g, ln_b, out);
}

// round 6
// speedup vs baseline: 1.7136x; 1.0773x over previous
#include <cuda_runtime.h>
#include <cstdint>

#define BB   8
#define LLEN 4096
#define CEMB 192
#define DIN  384
#define XD   20
#define DTR  12
#define NC   128
#define LC   32
#define MROWS (BB*LLEN)

// ---------------- scratch ----------------
__device__ float g_xh  [MROWS*CEMB];
__device__ float g_h2  [MROWS*CEMB];
__device__ float g_h3  [MROWS*CEMB];
__device__ float g_xz  [MROWS*2*DIN];
__device__ float g_xa  [MROWS*DIN];
__device__ float2 g_pk [MROWS*DIN];       // (dt, xa)
__device__ float g_xdbl[MROWS*DTR];
__device__ float g_bc  [MROWS*8];         // B[4] | C[4]
__device__ float g_y   [MROWS*DIN];
__device__ float g_hpart[BB*DIN*NC*4];
__device__ float g_sumdt[BB*DIN*NC];
__device__ float g_Hinit[BB*DIN*NC*4];
__device__ float g_A[DIN*4];
__device__ int   g_slow;

__device__ __forceinline__ uint32_t smem_u32(const void* p) {
    uint32_t a;
    asm("{ .reg .u64 t; cvta.to.shared.u64 t, %1; cvt.u32.u64 %0, t; }" : "=r"(a) : "l"(p));
    return a;
}

// ======================= split-bf16 HMMA GEMM (pipelined) =======================
__device__ __forceinline__ void cvt_hilo(float4 v, uint32_t& h0, uint32_t& h1,
                                         uint32_t& l0, uint32_t& l1) {
    asm("cvt.rn.bf16x2.f32 %0, %1, %2;" : "=r"(h0) : "f"(v.y), "f"(v.x));
    asm("cvt.rn.bf16x2.f32 %0, %1, %2;" : "=r"(h1) : "f"(v.w), "f"(v.z));
    float a0 = v.x - __uint_as_float(h0 << 16);
    float a1 = v.y - __uint_as_float(h0 & 0xffff0000u);
    float a2 = v.z - __uint_as_float(h1 << 16);
    float a3 = v.w - __uint_as_float(h1 & 0xffff0000u);
    asm("cvt.rn.bf16x2.f32 %0, %1, %2;" : "=r"(l0) : "f"(a1), "f"(a0));
    asm("cvt.rn.bf16x2.f32 %0, %1, %2;" : "=r"(l1) : "f"(a3), "f"(a2));
}

#define LDSM_X4(r0, r1, r2, r3, addr) \
    asm volatile("ldmatrix.sync.aligned.m8n8.x4.shared.b16 {%0,%1,%2,%3}, [%4];" \
        : "=r"(r0), "=r"(r1), "=r"(r2), "=r"(r3) : "r"(addr))
#define LDSM_X2(r0, r1, addr) \
    asm volatile("ldmatrix.sync.aligned.m8n8.x2.shared.b16 {%0,%1}, [%2];" \
        : "=r"(r0), "=r"(r1) : "r"(addr))
#define MMA_BF16(c, a, b) \
    asm volatile("mma.sync.aligned.m16n8k16.row.col.f32.bf16.bf16.f32 " \
        "{%0,%1,%2,%3}, {%4,%5,%6,%7}, {%8,%9}, {%0,%1,%2,%3};" \
        : "+f"((c)[0]), "+f"((c)[1]), "+f"((c)[2]), "+f"((c)[3]) \
        : "r"((a)[0]), "r"((a)[1]), "r"((a)[2]), "r"((a)[3]), "r"((b)[0]), "r"((b)[1]))

__global__ void __launch_bounds__(256, 2)
gemm_mma(const float* __restrict__ A, const float* __restrict__ W,
         float* __restrict__ C, int M, int N, int K)
{
    __shared__ __align__(1024) char sm[49152];
    char* AH = sm;
    char* AL = sm + 16384;
    char* WH = sm + 32768;
    char* WL = sm + 40960;

    const int tid = threadIdx.x, wid = tid >> 5, lane = tid & 31;
    const int wm = wid & 3, wn = wid >> 2;
    const int bm = blockIdx.y * 128, bn = blockIdx.x * 64;
    const uint32_t sAH = smem_u32(AH), sAL = smem_u32(AL);
    const uint32_t sWH = smem_u32(WH), sWL = smem_u32(WL);

    float acc[2][4][4];
    #pragma unroll
    for (int i = 0; i < 2; i++)
        #pragma unroll
        for (int j = 0; j < 4; j++)
            #pragma unroll
            for (int q = 0; q < 4; q++) acc[i][j][q] = 0.f;

    float4 ra[8], rw[4];
    const int nkt = K >> 6;

    #pragma unroll
    for (int i = 0; i < 8; i++) {
        int idx = tid + i * 256, r = idx >> 4, q = idx & 15;
        ra[i] = *(const float4*)(A + (size_t)(bm + r) * K + q * 4);
    }
    #pragma unroll
    for (int i = 0; i < 4; i++) {
        int idx = tid + i * 256, r = idx >> 4, q = idx & 15;
        rw[i] = *(const float4*)(W + (size_t)(bn + r) * K + q * 4);
    }

    for (int kt = 0; kt < nkt; kt++) {
        #pragma unroll
        for (int i = 0; i < 8; i++) {
            int idx = tid + i * 256, r = idx >> 4, q = idx & 15;
            uint32_t h0, h1, l0, l1;
            cvt_hilo(ra[i], h0, h1, l0, l1);
            uint32_t off = (uint32_t)(r * 128 + (((q >> 1) ^ (r & 7)) << 4) + ((q & 1) << 3));
            *(uint2*)(AH + off) = make_uint2(h0, h1);
            *(uint2*)(AL + off) = make_uint2(l0, l1);
        }
        #pragma unroll
        for (int i = 0; i < 4; i++) {
            int idx = tid + i * 256, r = idx >> 4, q = idx & 15;
            uint32_t h0, h1, l0, l1;
            cvt_hilo(rw[i], h0, h1, l0, l1);
            uint32_t off = (uint32_t)(r * 128 + (((q >> 1) ^ (r & 7)) << 4) + ((q & 1) << 3));
            *(uint2*)(WH + off) = make_uint2(h0, h1);
            *(uint2*)(WL + off) = make_uint2(l0, l1);
        }
        __syncthreads();

        if (kt + 1 < nkt) {
            int k0 = (kt + 1) * 64;
            #pragma unroll
            for (int i = 0; i < 8; i++) {
                int idx = tid + i * 256, r = idx >> 4, q = idx & 15;
                ra[i] = *(const float4*)(A + (size_t)(bm + r) * K + k0 + q * 4);
            }
            #pragma unroll
            for (int i = 0; i < 4; i++) {
                int idx = tid + i * 256, r = idx >> 4, q = idx & 15;
                rw[i] = *(const float4*)(W + (size_t)(bn + r) * K + k0 + q * 4);
            }
        }

        #pragma unroll
        for (int ks = 0; ks < 4; ks++) {
            uint32_t ah[2][4], al[2][4], bh[4][2], bl[4][2];
            #pragma unroll
            for (int mt = 0; mt < 2; mt++) {
                int r = wm * 32 + mt * 16 + (lane & 15);
                int c16 = ks * 2 + (lane >> 4);
                uint32_t off = (uint32_t)(r * 128 + ((c16 ^ (r & 7)) << 4));
                LDSM_X4(ah[mt][0], ah[mt][1], ah[mt][2], ah[mt][3], sAH + off);
                LDSM_X4(al[mt][0], al[mt][1], al[mt][2], al[mt][3], sAL + off);
            }
            #pragma unroll
            for (int nt = 0; nt < 4; nt++) {
                int rn = wn * 32 + nt * 8 + (lane & 7);
                int c16 = ks * 2 + ((lane >> 3) & 1);
                uint32_t off = (uint32_t)(rn * 128 + ((c16 ^ (rn & 7)) << 4));
                LDSM_X2(bh[nt][0], bh[nt][1], sWH + off);
                LDSM_X2(bl[nt][0], bl[nt][1], sWL + off);
            }
            #pragma unroll
            for (int mt = 0; mt < 2; mt++)
                #pragma unroll
                for (int nt = 0; nt < 4; nt++) {
                    MMA_BF16(acc[mt][nt], ah[mt], bh[nt]);
                    MMA_BF16(acc[mt][nt], ah[mt], bl[nt]);
                    MMA_BF16(acc[mt][nt], al[mt], bh[nt]);
                }
        }
        __syncthreads();
    }

    #pragma unroll
    for (int mt = 0; mt < 2; mt++) {
        int row = bm + wm * 32 + mt * 16 + (lane >> 2);
        #pragma unroll
        for (int nt = 0; nt < 4; nt++) {
            int col = bn + wn * 32 + nt * 8 + (lane & 3) * 2;
            *(float2*)(C + (size_t)row * N + col)       = make_float2(acc[mt][nt][0], acc[mt][nt][1]);
            *(float2*)(C + (size_t)(row + 8) * N + col) = make_float2(acc[mt][nt][2], acc[mt][nt][3]);
        }
    }
}

// ---------------- transpose (B,C,L) -> (B,L,C) ----------------
__global__ void transpose_k(const float* __restrict__ x) {
    __shared__ float t[32][33];
    int b = blockIdx.z;
    int l0 = blockIdx.x * 32, c0 = blockIdx.y * 32;
    int tx = threadIdx.x, ty = threadIdx.y;
    #pragma unroll
    for (int j = ty; j < 32; j += 8)
        t[j][tx] = x[((b*CEMB) + (c0 + j)) * LLEN + l0 + tx];
    __syncthreads();
    #pragma unroll
    for (int j = ty; j < 32; j += 8)
        g_xh[((b*LLEN) + (l0 + j)) * CEMB + c0 + tx] = t[tx][j];
}

// ---------------- A structure prep ----------------
__global__ void prepA_k(const float* __restrict__ A_log) {
    int d = threadIdx.x;
    if (d == 0) g_slow = 0;
    __syncthreads();
    float a[4];
    #pragma unroll
    for (int s = 0; s < 4; s++) {
        a[s] = -expf(A_log[d*4 + s]);
        g_A[d*4 + s] = a[s];
    }
    bool ok = true;
    #pragma unroll
    for (int s = 0; s < 4; s++) {
        float want = (float)(s + 1) * a[0];
        if (fabsf(a[s] - want) > 1e-5f * fabsf(a[s]) + 1e-7f) ok = false;
    }
    if (!ok) atomicExch(&g_slow, 1);
}

// ---------------- depthwise causal conv (k=4) + silu, float4 ----------------
__global__ void conv_k(const float* __restrict__ w, const float* __restrict__ bias) {
    int idx = blockIdx.x * blockDim.x + threadIdx.x;
    if (idx >= MROWS * (DIN/4)) return;
    int d4 = idx % (DIN/4);
    int bl = idx / (DIN/4);
    int l  = bl % LLEN;
    int d  = d4 * 4;
    float4 wv0 = *(const float4*)(w + (d+0)*4);
    float4 wv1 = *(const float4*)(w + (d+1)*4);
    float4 wv2 = *(const float4*)(w + (d+2)*4);
    float4 wv3 = *(const float4*)(w + (d+3)*4);
    float4 bv  = *(const float4*)(bias + d);
    const float* p = g_xz + (size_t)bl * (2*DIN) + d;
    float4 acc = bv;
    if (l >= 3) {
        float4 v = *(const float4*)(p - 3*2*DIN);
        acc.x = fmaf(wv0.x, v.x, acc.x); acc.y = fmaf(wv1.x, v.y, acc.y);
        acc.z = fmaf(wv2.x, v.z, acc.z); acc.w = fmaf(wv3.x, v.w, acc.w);
    }
    if (l >= 2) {
        float4 v = *(const float4*)(p - 2*2*DIN);
        acc.x = fmaf(wv0.y, v.x, acc.x); acc.y = fmaf(wv1.y, v.y, acc.y);
        acc.z = fmaf(wv2.y, v.z, acc.z); acc.w = fmaf(wv3.y, v.w, acc.w);
    }
    if (l >= 1) {
        float4 v = *(const float4*)(p - 2*DIN);
        acc.x = fmaf(wv0.z, v.x, acc.x); acc.y = fmaf(wv1.z, v.y, acc.y);
        acc.z = fmaf(wv2.z, v.z, acc.z); acc.w = fmaf(wv3.z, v.w, acc.w);
    }
    {
        float4 v = *(const float4*)(p);
        acc.x = fmaf(wv0.w, v.x, acc.x); acc.y = fmaf(wv1.w, v.y, acc.y);
        acc.z = fmaf(wv2.w, v.z, acc.z); acc.w = fmaf(wv3.w, v.w, acc.w);
    }
    float4 s;
    s.x = __fdividef(acc.x, 1.f + __expf(-acc.x));
    s.y = __fdividef(acc.y, 1.f + __expf(-acc.y));
    s.z = __fdividef(acc.z, 1.f + __expf(-acc.z));
    s.w = __fdividef(acc.w, 1.f + __expf(-acc.w));
    *(float4*)(g_xa + (size_t)bl * DIN + d) = s;
}

// ---------------- x_proj: dt_lr -> g_xdbl, B/C -> g_bc ----------------
__global__ void xproj_k(const float* __restrict__ W) {
    __shared__ float Wsh[XD * DIN];
    for (int i = threadIdx.x; i < XD*DIN; i += 256) Wsh[i] = W[i];
    __syncthreads();
    int warp = threadIdx.x >> 5, lane = threadIdx.x & 31;
    int m = blockIdx.x * 8 + warp;
    const float* ar = g_xa + (size_t)m * DIN;
    float acc[XD];
    #pragma unroll
    for (int n = 0; n < XD; n++) acc[n] = 0.f;
    for (int k = lane; k < DIN; k += 32) {
        float a = ar[k];
        #pragma unroll
        for (int n = 0; n < XD; n++)
            acc[n] = fmaf(a, Wsh[n*DIN + k], acc[n]);
    }
    float myv = 0.f;
    #pragma unroll
    for (int n = 0; n < XD; n++) {
        float v = acc[n];
        #pragma unroll
        for (int off = 16; off > 0; off >>= 1)
            v += __shfl_xor_sync(0xffffffffu, v, off);
        if (lane == n) myv = v;
    }
    if (lane < DTR) g_xdbl[(size_t)m*DTR + lane] = myv;
    else if (lane < XD) g_bc[(size_t)m*8 + lane - DTR] = myv;
}

// ---------------- dtpack: dt = softplus(dt_lr @ dtw^T + b); pack (dt, xa) ----------------
__global__ void __launch_bounds__(256)
dtpack_k(const float* __restrict__ dtw, const float* __restrict__ dtb) {
    int idx = blockIdx.x * blockDim.x + threadIdx.x;
    if (idx >= MROWS * DIN) return;
    int d = idx % DIN;
    int m = idx / DIN;
    const float4* w4 = (const float4*)(dtw + d * DTR);
    float4 dw0 = w4[0], dw1 = w4[1], dw2 = w4[2];
    const float* xr = g_xdbl + (size_t)m * DTR;
    float p = dtb[d];
    p = fmaf(xr[0], dw0.x, p);  p = fmaf(xr[1], dw0.y, p);
    p = fmaf(xr[2], dw0.z, p);  p = fmaf(xr[3], dw0.w, p);
    p = fmaf(xr[4], dw1.x, p);  p = fmaf(xr[5], dw1.y, p);
    p = fmaf(xr[6], dw1.z, p);  p = fmaf(xr[7], dw1.w, p);
    p = fmaf(xr[8], dw2.x, p);  p = fmaf(xr[9], dw2.y, p);
    p = fmaf(xr[10], dw2.z, p); p = fmaf(xr[11], dw2.w, p);
    float dv = (p > 20.f) ? p : __logf(1.f + __expf(p));
    g_pk[idx] = make_float2(dv, g_xa[idx]);
}

// ---------------- scan pass 1 ----------------
__global__ void scan1_k() {
    __shared__ float Bsm[LC][4];
    int chunk = blockIdx.x, b = blockIdx.y, d = threadIdx.x;
    int l0 = chunk * LC;
    if (threadIdx.x < LC*4) {
        int l = threadIdx.x >> 2, s = threadIdx.x & 3;
        Bsm[l][s] = g_bc[((size_t)(b*LLEN + l0 + l))*8 + s];
    }
    __syncthreads();
    int slow = g_slow;
    float Av0 = g_A[d*4], Av1 = g_A[d*4+1], Av2 = g_A[d*4+2], Av3 = g_A[d*4+3];
    float h0 = 0.f, h1 = 0.f, h2 = 0.f, h3 = 0.f, sd = 0.f;
    const float2* pp = g_pk + (size_t)(b*LLEN + l0)*DIN + d;
    #pragma unroll 4
    for (int l = 0; l < LC; l++) {
        float2 pk = pp[l*DIN];
        float dtv = pk.x, xav = pk.y;
        float dbu = dtv * xav;
        sd += dtv;
        float b0 = Bsm[l][0], b1 = Bsm[l][1], b2 = Bsm[l][2], b3 = Bsm[l][3];
        if (!slow) {
            float e = __expf(Av0 * dtv);
            float p = e;
            h0 = fmaf(p, h0, dbu*b0); p *= e;
            h1 = fmaf(p, h1, dbu*b1); p *= e;
            h2 = fmaf(p, h2, dbu*b2); p *= e;
            h3 = fmaf(p, h3, dbu*b3);
        } else {
            h0 = fmaf(__expf(dtv*Av0), h0, dbu*b0);
            h1 = fmaf(__expf(dtv*Av1), h1, dbu*b1);
            h2 = fmaf(__expf(dtv*Av2), h2, dbu*b2);
            h3 = fmaf(__expf(dtv*Av3), h3, dbu*b3);
        }
    }
    int o = ((b*DIN) + d)*NC + chunk;
    ((float4*)g_hpart)[o] = make_float4(h0, h1, h2, h3);
    g_sumdt[o] = sd;
}

// ---------------- scan pass 2 ----------------
__global__ void scan2_k() {
    int t = blockIdx.x * blockDim.x + threadIdx.x;
    if (t >= BB*DIN) return;
    int d = t % DIN;
    float Av0 = g_A[d*4], Av1 = g_A[d*4+1], Av2 = g_A[d*4+2], Av3 = g_A[d*4+3];
    float H0 = 0.f, H1 = 0.f, H2 = 0.f, H3 = 0.f;
    for (int c = 0; c < NC; c++) {
        int o = t*NC + c;
        ((float4*)g_Hinit)[o] = make_float4(H0, H1, H2, H3);
        float4 hp = ((const float4*)g_hpart)[o];
        float sd = g_sumdt[o];
        H0 = fmaf(__expf(Av0*sd), H0, hp.x);
        H1 = fmaf(__expf(Av1*sd), H1, hp.y);
        H2 = fmaf(__expf(Av2*sd), H2, hp.z);
        H3 = fmaf(__expf(Av3*sd), H3, hp.w);
    }
}

// ---------------- scan pass 3 ----------------
__global__ void scan3_k(const float* __restrict__ Dw) {
    __shared__ float Bsm[LC][4];
    __shared__ float Csm[LC][4];
    int chunk = blockIdx.x, b = blockIdx.y, d = threadIdx.x;
    int l0 = chunk * LC;
    if (threadIdx.x < LC*8) {
        int l = threadIdx.x >> 3, s = threadIdx.x & 7;
        float v = g_bc[((size_t)(b*LLEN + l0 + l))*8 + s];
        if (s < 4) Bsm[l][s] = v; else Csm[l][s-4] = v;
    }
    __syncthreads();
    int slow = g_slow;
    float Av0 = g_A[d*4], Av1 = g_A[d*4+1], Av2 = g_A[d*4+2], Av3 = g_A[d*4+3];
    float Dd = Dw[d];
    int o = ((b*DIN) + d)*NC + chunk;
    float4 Hi = ((const float4*)g_Hinit)[o];
    float h0 = Hi.x, h1 = Hi.y, h2 = Hi.z, h3 = Hi.w;
    const float2* pp = g_pk + (size_t)(b*LLEN + l0)*DIN + d;
    const float* pz = g_xz + (size_t)(b*LLEN + l0)*(2*DIN) + DIN + d;
    float* py = g_y + (size_t)(b*LLEN + l0)*DIN + d;
    #pragma unroll 4
    for (int l = 0; l < LC; l++) {
        float2 pk = pp[l*DIN];
        float dtv = pk.x, xav = pk.y;
        float dbu = dtv * xav;
        float b0 = Bsm[l][0], b1 = Bsm[l][1], b2 = Bsm[l][2], b3 = Bsm[l][3];
        if (!slow) {
            float e = __expf(Av0 * dtv);
            float p = e;
            h0 = fmaf(p, h0, dbu*b0); p *= e;
            h1 = fmaf(p, h1, dbu*b1); p *= e;
            h2 = fmaf(p, h2, dbu*b2); p *= e;
            h3 = fmaf(p, h3, dbu*b3);
        } else {
            h0 = fmaf(__expf(dtv*Av0), h0, dbu*b0);
            h1 = fmaf(__expf(dtv*Av1), h1, dbu*b1);
            h2 = fmaf(__expf(dtv*Av2), h2, dbu*b2);
            h3 = fmaf(__expf(dtv*Av3), h3, dbu*b3);
        }
        float y = h0*Csm[l][0] + h1*Csm[l][1] + h2*Csm[l][2] + h3*Csm[l][3];
        y = fmaf(xav, Dd, y);
        float zv = pz[l*2*DIN];
        float zs = __fdividef(zv, 1.f + __expf(-zv));
        py[l*DIN] = y * zs;
    }
}

// ---------------- final: low-rank UV + residual + LayerNorm + transpose out ----------------
__global__ void final_k(const float* __restrict__ U, const float* __restrict__ V,
                        const float* __restrict__ lng, const float* __restrict__ lnb,
                        float* __restrict__ out)
{
    __shared__ float Ush[4*CEMB];
    __shared__ float Vsh[CEMB*4];
    __shared__ float u[32][4];
    __shared__ float vs[32][193];
    __shared__ float mu[32], rsd[32];
    int b = blockIdx.y;
    int l0 = blockIdx.x * 32;
    int tid = threadIdx.x;
    for (int i = tid; i < 4*CEMB; i += 256) { Ush[i] = U[i]; Vsh[i] = V[i]; }
    __syncthreads();
    if (tid < 128) {
        int p = tid >> 2, r = tid & 3;
        const float* hr = g_h3 + ((size_t)(b*LLEN) + l0 + p)*CEMB;
        float a = 0.f;
        #pragma unroll 8
        for (int c = 0; c < CEMB; c++) a = fmaf(hr[c], Ush[r*CEMB + c], a);
        u[p][r] = a;
    }
    __syncthreads();
    for (int i = tid; i < 32*CEMB; i += 256) {
        int p = i / CEMB, c = i % CEMB;
        float v = g_xh[((size_t)(b*LLEN) + l0 + p)*CEMB + c];
        v = fmaf(Vsh[c*4+0], u[p][0], v);
        v = fmaf(Vsh[c*4+1], u[p][1], v);
        v = fmaf(Vsh[c*4+2], u[p][2], v);
        v = fmaf(Vsh[c*4+3], u[p][3], v);
        vs[p][c] = v;
    }
    __syncthreads();
    int warp = tid >> 5, lane = tid & 31;
    #pragma unroll
    for (int pp = 0; pp < 4; pp++) {
        int p = warp*4 + pp;
        float s = 0.f, ss = 0.f;
        for (int c = lane; c < CEMB; c += 32) {
            float v = vs[p][c];
            s += v; ss = fmaf(v, v, ss);
        }
        #pragma unroll
        for (int off = 16; off > 0; off >>= 1) {
            s  += __shfl_xor_sync(0xffffffffu, s, off);
            ss += __shfl_xor_sync(0xffffffffu, ss, off);
        }
        if (lane == 0) {
            float m = s * (1.f/CEMB);
            mu[p] = m;
            rsd[p] = rsqrtf(ss * (1.f/CEMB) - m*m + 1e-5f);
        }
    }
    __syncthreads();
    for (int c = warp; c < CEMB; c += 8) {
        int p = lane;
        float v = (vs[p][c] - mu[p]) * rsd[p] * lng[c] + lnb[c];
        out[((size_t)(b*CEMB) + c)*LLEN + l0 + lane] = v;
    }
}

// ---------------- launch ----------------
extern "C" void kernel_launch(void* const* d_in, const int* in_sizes, int n_in,
                              void* d_out, int out_size)
{
    const float* x         = (const float*)d_in[0];
    const float* in_proj_w = (const float*)d_in[1];
    const float* conv_w    = (const float*)d_in[2];
    const float* conv_b    = (const float*)d_in[3];
    const float* x_proj_w  = (const float*)d_in[4];
    const float* dt_proj_w = (const float*)d_in[5];
    const float* dt_proj_b = (const float*)d_in[6];
    const float* A_log     = (const float*)d_in[7];
    const float* Dw        = (const float*)d_in[8];
    const float* out_proj_w= (const float*)d_in[9];
    const float* U_w       = (const float*)d_in[10];
    const float* V_w       = (const float*)d_in[11];
    const float* ln_g      = (const float*)d_in[12];
    const float* ln_b      = (const float*)d_in[13];
    float* out = (float*)d_out;

    float* g_xh_p;  cudaGetSymbolAddress((void**)&g_xh_p,  g_xh);
    float* g_h2_p;  cudaGetSymbolAddress((void**)&g_h2_p,  g_h2);
    float* g_h3_p;  cudaGetSymbolAddress((void**)&g_h3_p,  g_h3);
    float* g_xz_p;  cudaGetSymbolAddress((void**)&g_xz_p,  g_xz);
    float* g_y_p;   cudaGetSymbolAddress((void**)&g_y_p,   g_y);

    transpose_k<<<dim3(LLEN/32, CEMB/32, BB), dim3(32, 8)>>>(x);

    const float* cur = g_xh_p;
    float* nxt_bufs[2] = { g_h2_p, g_h3_p };

    for (int mix = 0; mix < 2; mix++) {
        prepA_k<<<1, DIN>>>(A_log + mix*DIN*4);
        gemm_mma<<<dim3((2*DIN)/64, MROWS/128), 256>>>(
            cur, in_proj_w + (size_t)mix*2*DIN*CEMB, g_xz_p, MROWS, 2*DIN, CEMB);
        conv_k<<<(MROWS*(DIN/4) + 255)/256, 256>>>(conv_w + mix*DIN*4, conv_b + mix*DIN);
        xproj_k<<<MROWS/8, 256>>>(x_proj_w + (size_t)mix*XD*DIN);
        dtpack_k<<<(MROWS*DIN + 255)/256, 256>>>(dt_proj_w + (size_t)mix*DIN*DTR, dt_proj_b + mix*DIN);
        scan1_k<<<dim3(NC, BB), DIN>>>();
        scan2_k<<<(BB*DIN + 255)/256, 256>>>();
        scan3_k<<<dim3(NC, BB), DIN>>>(Dw + mix*DIN);
        gemm_mma<<<dim3(CEMB/64, MROWS/128), 256>>>(
            g_y_p, out_proj_w + (size_t)mix*CEMB*DIN, nxt_bufs[mix], MROWS, CEMB, DIN);
        cur = nxt_bufs[mix];
    }

    final_k<<<dim3(LLEN/32, BB), 256>>>(U_w, V_w, ln_g, ln_b, out);
}

// round 8
// speedup vs baseline: 1.8573x; 1.0839x over previous
#include <cuda_runtime.h>
#include <cstdint>

#define BB   8
#define LLEN 4096
#define CEMB 192
#define DIN  384
#define XD   20
#define DTR  12
#define NC   128
#define LC   32
#define MROWS (BB*LLEN)

// ---------------- scratch ----------------
__device__ float g_xh  [MROWS*CEMB];
__device__ float g_h2  [MROWS*CEMB];
__device__ float g_h3  [MROWS*CEMB];
__device__ float g_xz  [MROWS*2*DIN];
__device__ float g_xa  [MROWS*DIN];
__device__ float g_xdbl[MROWS*DTR];
__device__ float g_bc  [MROWS*8];         // B[4] | C[4]
__device__ float g_y   [MROWS*DIN];
__device__ float g_hpart[BB*DIN*NC*4];
__device__ float g_sumdt[BB*DIN*NC];
__device__ float g_Hinit[BB*DIN*NC*4];
__device__ float g_A[DIN*4];
__device__ int   g_slow;

__device__ __forceinline__ uint32_t smem_u32(const void* p) {
    uint32_t a;
    asm("{ .reg .u64 t; cvta.to.shared.u64 t, %1; cvt.u32.u64 %0, t; }" : "=r"(a) : "l"(p));
    return a;
}

// ======================= split-bf16 HMMA GEMM (pipelined) =======================
__device__ __forceinline__ void cvt_hilo(float4 v, uint32_t& h0, uint32_t& h1,
                                         uint32_t& l0, uint32_t& l1) {
    asm("cvt.rn.bf16x2.f32 %0, %1, %2;" : "=r"(h0) : "f"(v.y), "f"(v.x));
    asm("cvt.rn.bf16x2.f32 %0, %1, %2;" : "=r"(h1) : "f"(v.w), "f"(v.z));
    float a0 = v.x - __uint_as_float(h0 << 16);
    float a1 = v.y - __uint_as_float(h0 & 0xffff0000u);
    float a2 = v.z - __uint_as_float(h1 << 16);
    float a3 = v.w - __uint_as_float(h1 & 0xffff0000u);
    asm("cvt.rn.bf16x2.f32 %0, %1, %2;" : "=r"(l0) : "f"(a1), "f"(a0));
    asm("cvt.rn.bf16x2.f32 %0, %1, %2;" : "=r"(l1) : "f"(a3), "f"(a2));
}

#define LDSM_X4(r0, r1, r2, r3, addr) \
    asm volatile("ldmatrix.sync.aligned.m8n8.x4.shared.b16 {%0,%1,%2,%3}, [%4];" \
        : "=r"(r0), "=r"(r1), "=r"(r2), "=r"(r3) : "r"(addr))
#define LDSM_X2(r0, r1, addr) \
    asm volatile("ldmatrix.sync.aligned.m8n8.x2.shared.b16 {%0,%1}, [%2];" \
        : "=r"(r0), "=r"(r1) : "r"(addr))
#define MMA_BF16(c, a, b) \
    asm volatile("mma.sync.aligned.m16n8k16.row.col.f32.bf16.bf16.f32 " \
        "{%0,%1,%2,%3}, {%4,%5,%6,%7}, {%8,%9}, {%0,%1,%2,%3};" \
        : "+f"((c)[0]), "+f"((c)[1]), "+f"((c)[2]), "+f"((c)[3]) \
        : "r"((a)[0]), "r"((a)[1]), "r"((a)[2]), "r"((a)[3]), "r"((b)[0]), "r"((b)[1]))

__global__ void __launch_bounds__(256, 2)
gemm_mma(const float* __restrict__ A, const float* __restrict__ W,
         float* __restrict__ C, int M, int N, int K)
{
    __shared__ __align__(1024) char sm[49152];
    char* AH = sm;
    char* AL = sm + 16384;
    char* WH = sm + 32768;
    char* WL = sm + 40960;

    const int tid = threadIdx.x, wid = tid >> 5, lane = tid & 31;
    const int wm = wid & 3, wn = wid >> 2;
    const int bm = blockIdx.y * 128, bn = blockIdx.x * 64;
    const uint32_t sAH = smem_u32(AH), sAL = smem_u32(AL);
    const uint32_t sWH = smem_u32(WH), sWL = smem_u32(WL);

    float acc[2][4][4];
    #pragma unroll
    for (int i = 0; i < 2; i++)
        #pragma unroll
        for (int j = 0; j < 4; j++)
            #pragma unroll
            for (int q = 0; q < 4; q++) acc[i][j][q] = 0.f;

    float4 ra[8], rw[4];
    const int nkt = K >> 6;

    #pragma unroll
    for (int i = 0; i < 8; i++) {
        int idx = tid + i * 256, r = idx >> 4, q = idx & 15;
        ra[i] = *(const float4*)(A + (size_t)(bm + r) * K + q * 4);
    }
    #pragma unroll
    for (int i = 0; i < 4; i++) {
        int idx = tid + i * 256, r = idx >> 4, q = idx & 15;
        rw[i] = *(const float4*)(W + (size_t)(bn + r) * K + q * 4);
    }

    for (int kt = 0; kt < nkt; kt++) {
        #pragma unroll
        for (int i = 0; i < 8; i++) {
            int idx = tid + i * 256, r = idx >> 4, q = idx & 15;
            uint32_t h0, h1, l0, l1;
            cvt_hilo(ra[i], h0, h1, l0, l1);
            uint32_t off = (uint32_t)(r * 128 + (((q >> 1) ^ (r & 7)) << 4) + ((q & 1) << 3));
            *(uint2*)(AH + off) = make_uint2(h0, h1);
            *(uint2*)(AL + off) = make_uint2(l0, l1);
        }
        #pragma unroll
        for (int i = 0; i < 4; i++) {
            int idx = tid + i * 256, r = idx >> 4, q = idx & 15;
            uint32_t h0, h1, l0, l1;
            cvt_hilo(rw[i], h0, h1, l0, l1);
            uint32_t off = (uint32_t)(r * 128 + (((q >> 1) ^ (r & 7)) << 4) + ((q & 1) << 3));
            *(uint2*)(WH + off) = make_uint2(h0, h1);
            *(uint2*)(WL + off) = make_uint2(l0, l1);
        }
        __syncthreads();

        if (kt + 1 < nkt) {
            int k0 = (kt + 1) * 64;
            #pragma unroll
            for (int i = 0; i < 8; i++) {
                int idx = tid + i * 256, r = idx >> 4, q = idx & 15;
                ra[i] = *(const float4*)(A + (size_t)(bm + r) * K + k0 + q * 4);
            }
            #pragma unroll
            for (int i = 0; i < 4; i++) {
                int idx = tid + i * 256, r = idx >> 4, q = idx & 15;
                rw[i] = *(const float4*)(W + (size_t)(bn + r) * K + k0 + q * 4);
            }
        }

        #pragma unroll
        for (int ks = 0; ks < 4; ks++) {
            uint32_t ah[2][4], al[2][4], bh[4][2], bl[4][2];
            #pragma unroll
            for (int mt = 0; mt < 2; mt++) {
                int r = wm * 32 + mt * 16 + (lane & 15);
                int c16 = ks * 2 + (lane >> 4);
                uint32_t off = (uint32_t)(r * 128 + ((c16 ^ (r & 7)) << 4));
                LDSM_X4(ah[mt][0], ah[mt][1], ah[mt][2], ah[mt][3], sAH + off);
                LDSM_X4(al[mt][0], al[mt][1], al[mt][2], al[mt][3], sAL + off);
            }
            #pragma unroll
            for (int nt = 0; nt < 4; nt++) {
                int rn = wn * 32 + nt * 8 + (lane & 7);
                int c16 = ks * 2 + ((lane >> 3) & 1);
                uint32_t off = (uint32_t)(rn * 128 + ((c16 ^ (rn & 7)) << 4));
                LDSM_X2(bh[nt][0], bh[nt][1], sWH + off);
                LDSM_X2(bl[nt][0], bl[nt][1], sWL + off);
            }
            #pragma unroll
            for (int mt = 0; mt < 2; mt++)
                #pragma unroll
                for (int nt = 0; nt < 4; nt++) {
                    MMA_BF16(acc[mt][nt], ah[mt], bh[nt]);
                    MMA_BF16(acc[mt][nt], ah[mt], bl[nt]);
                    MMA_BF16(acc[mt][nt], al[mt], bh[nt]);
                }
        }
        __syncthreads();
    }

    #pragma unroll
    for (int mt = 0; mt < 2; mt++) {
        int row = bm + wm * 32 + mt * 16 + (lane >> 2);
        #pragma unroll
        for (int nt = 0; nt < 4; nt++) {
            int col = bn + wn * 32 + nt * 8 + (lane & 3) * 2;
            *(float2*)(C + (size_t)row * N + col)       = make_float2(acc[mt][nt][0], acc[mt][nt][1]);
            *(float2*)(C + (size_t)(row + 8) * N + col) = make_float2(acc[mt][nt][2], acc[mt][nt][3]);
        }
    }
}

// ---------------- transpose (B,C,L) -> (B,L,C) ----------------
__global__ void transpose_k(const float* __restrict__ x) {
    __shared__ float t[32][33];
    int b = blockIdx.z;
    int l0 = blockIdx.x * 32, c0 = blockIdx.y * 32;
    int tx = threadIdx.x, ty = threadIdx.y;
    #pragma unroll
    for (int j = ty; j < 32; j += 8)
        t[j][tx] = x[((b*CEMB) + (c0 + j)) * LLEN + l0 + tx];
    __syncthreads();
    #pragma unroll
    for (int j = ty; j < 32; j += 8)
        g_xh[((b*LLEN) + (l0 + j)) * CEMB + c0 + tx] = t[tx][j];
}

// ---------------- A structure prep ----------------
__global__ void prepA_k(const float* __restrict__ A_log) {
    int d = threadIdx.x;
    if (d == 0) g_slow = 0;
    __syncthreads();
    float a[4];
    #pragma unroll
    for (int s = 0; s < 4; s++) {
        a[s] = -expf(A_log[d*4 + s]);
        g_A[d*4 + s] = a[s];
    }
    bool ok = true;
    #pragma unroll
    for (int s = 0; s < 4; s++) {
        float want = (float)(s + 1) * a[0];
        if (fabsf(a[s] - want) > 1e-5f * fabsf(a[s]) + 1e-7f) ok = false;
    }
    if (!ok) atomicExch(&g_slow, 1);
}

// ---------------- depthwise causal conv (k=4) + silu, rolling window ----------------
// each thread: 4 channels x 8 consecutive positions; window rolls in registers.
__global__ void __launch_bounds__(256)
conv_k(const float* __restrict__ w, const float* __restrict__ bias) {
    int idx = blockIdx.x * blockDim.x + threadIdx.x;
    if (idx >= (MROWS/8) * (DIN/4)) return;
    int d4 = idx % (DIN/4);
    int m8 = idx / (DIN/4);
    int d  = d4 * 4;
    int bl = m8 * 8;
    int l  = bl % LLEN;

    float4 wv0 = *(const float4*)(w + (d+0)*4);
    float4 wv1 = *(const float4*)(w + (d+1)*4);
    float4 wv2 = *(const float4*)(w + (d+2)*4);
    float4 wv3 = *(const float4*)(w + (d+3)*4);
    float4 bv  = *(const float4*)(bias + d);

    const float* p = g_xz + (size_t)bl * (2*DIN) + d;
    float* po = g_xa + (size_t)bl * DIN + d;
    float4 x1 = make_float4(0,0,0,0), x2 = x1, x3 = x1;
    if (l) {   // l is a multiple of 8, so l>=8 here: all 3 history rows valid
        x3 = *(const float4*)(p - 3*2*DIN);
        x2 = *(const float4*)(p - 2*2*DIN);
        x1 = *(const float4*)(p - 2*DIN);
    }
    #pragma unroll
    for (int j = 0; j < 8; j++) {
        float4 x0 = *(const float4*)(p + j*2*DIN);
        float4 acc = bv;
        acc.x = fmaf(wv0.x, x3.x, acc.x); acc.y = fmaf(wv1.x, x3.y, acc.y);
        acc.z = fmaf(wv2.x, x3.z, acc.z); acc.w = fmaf(wv3.x, x3.w, acc.w);
        acc.x = fmaf(wv0.y, x2.x, acc.x); acc.y = fmaf(wv1.y, x2.y, acc.y);
        acc.z = fmaf(wv2.y, x2.z, acc.z); acc.w = fmaf(wv3.y, x2.w, acc.w);
        acc.x = fmaf(wv0.z, x1.x, acc.x); acc.y = fmaf(wv1.z, x1.y, acc.y);
        acc.z = fmaf(wv2.z, x1.z, acc.z); acc.w = fmaf(wv3.z, x1.w, acc.w);
        acc.x = fmaf(wv0.w, x0.x, acc.x); acc.y = fmaf(wv1.w, x0.y, acc.y);
        acc.z = fmaf(wv2.w, x0.z, acc.z); acc.w = fmaf(wv3.w, x0.w, acc.w);
        float4 s;
        s.x = __fdividef(acc.x, 1.f + __expf(-acc.x));
        s.y = __fdividef(acc.y, 1.f + __expf(-acc.y));
        s.z = __fdividef(acc.z, 1.f + __expf(-acc.z));
        s.w = __fdividef(acc.w, 1.f + __expf(-acc.w));
        *(float4*)(po + j*DIN) = s;
        x3 = x2; x2 = x1; x1 = x0;
    }
}

// ---------------- x_proj: 32 rows/block; dt_lr -> g_xdbl, B/C -> g_bc ----------------
__global__ void __launch_bounds__(256)
xproj_k(const float* __restrict__ W) {
    __shared__ __align__(16) float Wsh[XD * DIN];
    for (int i = threadIdx.x; i < XD*DIN; i += 256) Wsh[i] = W[i];
    __syncthreads();
    int warp = threadIdx.x >> 5, lane = threadIdx.x & 31;
    int m0 = blockIdx.x * 32;
    for (int r = warp; r < 32; r += 8) {
        int m = m0 + r;
        const float4* ar = (const float4*)(g_xa + (size_t)m * DIN);
        float acc[XD];
        #pragma unroll
        for (int n = 0; n < XD; n++) acc[n] = 0.f;
        #pragma unroll
        for (int it = 0; it < 3; it++) {
            int k4 = lane + it * 32;
            float4 a = ar[k4];
            #pragma unroll
            for (int n = 0; n < XD; n++) {
                const float4 wv = *(const float4*)(Wsh + n*DIN + k4*4);
                acc[n] = fmaf(a.x, wv.x, fmaf(a.y, wv.y, fmaf(a.z, wv.z, fmaf(a.w, wv.w, acc[n]))));
            }
        }
        float myv = 0.f;
        #pragma unroll
        for (int n = 0; n < XD; n++) {
            float v = acc[n];
            #pragma unroll
            for (int off = 16; off > 0; off >>= 1)
                v += __shfl_xor_sync(0xffffffffu, v, off);
            if (lane == n) myv = v;
        }
        if (lane < DTR) g_xdbl[(size_t)m*DTR + lane] = myv;
        else if (lane < XD) g_bc[(size_t)m*8 + lane - DTR] = myv;
    }
}

// ---------------- scan pass 1 (dt inline) ----------------
__global__ void scan1_k(const float* __restrict__ dtw, const float* __restrict__ dtb) {
    __shared__ float Bsm[LC][4];
    __shared__ float Xd[LC][DTR];
    int chunk = blockIdx.x, b = blockIdx.y, d = threadIdx.x;
    int l0 = chunk * LC;
    if (threadIdx.x < LC*4) {
        int l = threadIdx.x >> 2, s = threadIdx.x & 3;
        Bsm[l][s] = g_bc[((size_t)(b*LLEN + l0 + l))*8 + s];
    }
    {
        int l = threadIdx.x / DTR, r = threadIdx.x - l*DTR;   // 384 = 32*12 exactly
        Xd[l][r] = g_xdbl[((size_t)(b*LLEN + l0 + l))*DTR + r];
    }
    __syncthreads();
    int slow = g_slow;
    float Av0 = g_A[d*4], Av1 = g_A[d*4+1], Av2 = g_A[d*4+2], Av3 = g_A[d*4+3];
    const float4* w4 = (const float4*)(dtw + d * DTR);
    float4 dw0 = w4[0], dw1 = w4[1], dw2 = w4[2];
    float pb = dtb[d];
    float h0 = 0.f, h1 = 0.f, h2 = 0.f, h3 = 0.f, sd = 0.f;
    const float* pa = g_xa + (size_t)(b*LLEN + l0)*DIN + d;
    #pragma unroll 4
    for (int l = 0; l < LC; l++) {
        float xav = pa[l*DIN];
        const float* xr = Xd[l];
        float p = pb;
        p = fmaf(xr[0], dw0.x, p);  p = fmaf(xr[1], dw0.y, p);
        p = fmaf(xr[2], dw0.z, p);  p = fmaf(xr[3], dw0.w, p);
        p = fmaf(xr[4], dw1.x, p);  p = fmaf(xr[5], dw1.y, p);
        p = fmaf(xr[6], dw1.z, p);  p = fmaf(xr[7], dw1.w, p);
        p = fmaf(xr[8], dw2.x, p);  p = fmaf(xr[9], dw2.y, p);
        p = fmaf(xr[10], dw2.z, p); p = fmaf(xr[11], dw2.w, p);
        float dtv = (p > 20.f) ? p : __logf(1.f + __expf(p));
        float dbu = dtv * xav;
        sd += dtv;
        float b0 = Bsm[l][0], b1 = Bsm[l][1], b2 = Bsm[l][2], b3 = Bsm[l][3];
        if (!slow) {
            float e = __expf(Av0 * dtv);
            float q = e;
            h0 = fmaf(q, h0, dbu*b0); q *= e;
            h1 = fmaf(q, h1, dbu*b1); q *= e;
            h2 = fmaf(q, h2, dbu*b2); q *= e;
            h3 = fmaf(q, h3, dbu*b3);
        } else {
            h0 = fmaf(__expf(dtv*Av0), h0, dbu*b0);
            h1 = fmaf(__expf(dtv*Av1), h1, dbu*b1);
            h2 = fmaf(__expf(dtv*Av2), h2, dbu*b2);
            h3 = fmaf(__expf(dtv*Av3), h3, dbu*b3);
        }
    }
    int o = ((b*DIN) + d)*NC + chunk;
    ((float4*)g_hpart)[o] = make_float4(h0, h1, h2, h3);
    g_sumdt[o] = sd;
}

// ---------------- scan pass 2 ----------------
__global__ void scan2_k() {
    int t = blockIdx.x * blockDim.x + threadIdx.x;
    if (t >= BB*DIN) return;
    int d = t % DIN;
    float Av0 = g_A[d*4], Av1 = g_A[d*4+1], Av2 = g_A[d*4+2], Av3 = g_A[d*4+3];
    float H0 = 0.f, H1 = 0.f, H2 = 0.f, H3 = 0.f;
    for (int c = 0; c < NC; c++) {
        int o = t*NC + c;
        ((float4*)g_Hinit)[o] = make_float4(H0, H1, H2, H3);
        float4 hp = ((const float4*)g_hpart)[o];
        float sd = g_sumdt[o];
        H0 = fmaf(__expf(Av0*sd), H0, hp.x);
        H1 = fmaf(__expf(Av1*sd), H1, hp.y);
        H2 = fmaf(__expf(Av2*sd), H2, hp.z);
        H3 = fmaf(__expf(Av3*sd), H3, hp.w);
    }
}

// ---------------- scan pass 3 (dt inline) ----------------
__global__ void scan3_k(const float* __restrict__ dtw, const float* __restrict__ dtb,
                        const float* __restrict__ Dw) {
    __shared__ float Bsm[LC][4];
    __shared__ float Csm[LC][4];
    __shared__ float Xd[LC][DTR];
    int chunk = blockIdx.x, b = blockIdx.y, d = threadIdx.x;
    int l0 = chunk * LC;
    if (threadIdx.x < LC*8) {
        int l = threadIdx.x >> 3, s = threadIdx.x & 7;
        float v = g_bc[((size_t)(b*LLEN + l0 + l))*8 + s];
        if (s < 4) Bsm[l][s] = v; else Csm[l][s-4] = v;
    }
    {
        int l = threadIdx.x / DTR, r = threadIdx.x - l*DTR;
        Xd[l][r] = g_xdbl[((size_t)(b*LLEN + l0 + l))*DTR + r];
    }
    __syncthreads();
    int slow = g_slow;
    float Av0 = g_A[d*4], Av1 = g_A[d*4+1], Av2 = g_A[d*4+2], Av3 = g_A[d*4+3];
    const float4* w4 = (const float4*)(dtw + d * DTR);
    float4 dw0 = w4[0], dw1 = w4[1], dw2 = w4[2];
    float pb = dtb[d];
    float Dd = Dw[d];
    int o = ((b*DIN) + d)*NC + chunk;
    float4 Hi = ((const float4*)g_Hinit)[o];
    float h0 = Hi.x, h1 = Hi.y, h2 = Hi.z, h3 = Hi.w;
    const float* pa = g_xa + (size_t)(b*LLEN + l0)*DIN + d;
    const float* pz = g_xz + (size_t)(b*LLEN + l0)*(2*DIN) + DIN + d;
    float* py = g_y + (size_t)(b*LLEN + l0)*DIN + d;
    #pragma unroll 4
    for (int l = 0; l < LC; l++) {
        float xav = pa[l*DIN];
        const float* xr = Xd[l];
        float p = pb;
        p = fmaf(xr[0], dw0.x, p);  p = fmaf(xr[1], dw0.y, p);
        p = fmaf(xr[2], dw0.z, p);  p = fmaf(xr[3], dw0.w, p);
        p = fmaf(xr[4], dw1.x, p);  p = fmaf(xr[5], dw1.y, p);
        p = fmaf(xr[6], dw1.z, p);  p = fmaf(xr[7], dw1.w, p);
        p = fmaf(xr[8], dw2.x, p);  p = fmaf(xr[9], dw2.y, p);
        p = fmaf(xr[10], dw2.z, p); p = fmaf(xr[11], dw2.w, p);
        float dtv = (p > 20.f) ? p : __logf(1.f + __expf(p));
        float dbu = dtv * xav;
        float b0 = Bsm[l][0], b1 = Bsm[l][1], b2 = Bsm[l][2], b3 = Bsm[l][3];
        if (!slow) {
            float e = __expf(Av0 * dtv);
            float q = e;
            h0 = fmaf(q, h0, dbu*b0); q *= e;
            h1 = fmaf(q, h1, dbu*b1); q *= e;
            h2 = fmaf(q, h2, dbu*b2); q *= e;
            h3 = fmaf(q, h3, dbu*b3);
        } else {
            h0 = fmaf(__expf(dtv*Av0), h0, dbu*b0);
            h1 = fmaf(__expf(dtv*Av1), h1, dbu*b1);
            h2 = fmaf(__expf(dtv*Av2), h2, dbu*b2);
            h3 = fmaf(__expf(dtv*Av3), h3, dbu*b3);
        }
        float y = h0*Csm[l][0] + h1*Csm[l][1] + h2*Csm[l][2] + h3*Csm[l][3];
        y = fmaf(xav, Dd, y);
        float zv = pz[l*2*DIN];
        float zs = __fdividef(zv, 1.f + __expf(-zv));
        py[l*DIN] = y * zs;
    }
}

// ---------------- final: low-rank UV + residual + LayerNorm + transpose out ----------------
__global__ void final_k(const float* __restrict__ U, const float* __restrict__ V,
                        const float* __restrict__ lng, const float* __restrict__ lnb,
                        float* __restrict__ out)
{
    __shared__ float Ush[4*CEMB];
    __shared__ float Vsh[CEMB*4];
    __shared__ float u[32][4];
    __shared__ float vs[32][193];
    __shared__ float mu[32], rsd[32];
    int b = blockIdx.y;
    int l0 = blockIdx.x * 32;
    int tid = threadIdx.x;
    for (int i = tid; i < 4*CEMB; i += 256) { Ush[i] = U[i]; Vsh[i] = V[i]; }
    __syncthreads();
    if (tid < 128) {
        int p = tid >> 2, r = tid & 3;
        const float* hr = g_h3 + ((size_t)(b*LLEN) + l0 + p)*CEMB;
        float a = 0.f;
        #pragma unroll 8
        for (int c = 0; c < CEMB; c++) a = fmaf(hr[c], Ush[r*CEMB + c], a);
        u[p][r] = a;
    }
    __syncthreads();
    for (int i = tid; i < 32*CEMB; i += 256) {
        int p = i / CEMB, c = i % CEMB;
        float v = g_xh[((size_t)(b*LLEN) + l0 + p)*CEMB + c];
        v = fmaf(Vsh[c*4+0], u[p][0], v);
        v = fmaf(Vsh[c*4+1], u[p][1], v);
        v = fmaf(Vsh[c*4+2], u[p][2], v);
        v = fmaf(Vsh[c*4+3], u[p][3], v);
        vs[p][c] = v;
    }
    __syncthreads();
    int warp = tid >> 5, lane = tid & 31;
    #pragma unroll
    for (int pp = 0; pp < 4; pp++) {
        int p = warp*4 + pp;
        float s = 0.f, ss = 0.f;
        for (int c = lane; c < CEMB; c += 32) {
            float v = vs[p][c];
            s += v; ss = fmaf(v, v, ss);
        }
        #pragma unroll
        for (int off = 16; off > 0; off >>= 1) {
            s  += __shfl_xor_sync(0xffffffffu, s, off);
            ss += __shfl_xor_sync(0xffffffffu, ss, off);
        }
        if (lane == 0) {
            float m = s * (1.f/CEMB);
            mu[p] = m;
            rsd[p] = rsqrtf(ss * (1.f/CEMB) - m*m + 1e-5f);
        }
    }
    __syncthreads();
    for (int c = warp; c < CEMB; c += 8) {
        int p = lane;
        float v = (vs[p][c] - mu[p]) * rsd[p] * lng[c] + lnb[c];
        out[((size_t)(b*CEMB) + c)*LLEN + l0 + lane] = v;
    }
}

// ---------------- launch ----------------
extern "C" void kernel_launch(void* const* d_in, const int* in_sizes, int n_in,
                              void* d_out, int out_size)
{
    const float* x         = (const float*)d_in[0];
    const float* in_proj_w = (const float*)d_in[1];
    const float* conv_w    = (const float*)d_in[2];
    const float* conv_b    = (const float*)d_in[3];
    const float* x_proj_w  = (const float*)d_in[4];
    const float* dt_proj_w = (const float*)d_in[5];
    const float* dt_proj_b = (const float*)d_in[6];
    const float* A_log     = (const float*)d_in[7];
    const float* Dw        = (const float*)d_in[8];
    const float* out_proj_w= (const float*)d_in[9];
    const float* U_w       = (const float*)d_in[10];
    const float* V_w       = (const float*)d_in[11];
    const float* ln_g      = (const float*)d_in[12];
    const float* ln_b      = (const float*)d_in[13];
    float* out = (float*)d_out;

    float* g_xh_p;  cudaGetSymbolAddress((void**)&g_xh_p,  g_xh);
    float* g_h2_p;  cudaGetSymbolAddress((void**)&g_h2_p,  g_h2);
    float* g_h3_p;  cudaGetSymbolAddress((void**)&g_h3_p,  g_h3);
    float* g_xz_p;  cudaGetSymbolAddress((void**)&g_xz_p,  g_xz);
    float* g_y_p;   cudaGetSymbolAddress((void**)&g_y_p,   g_y);

    transpose_k<<<dim3(LLEN/32, CEMB/32, BB), dim3(32, 8)>>>(x);

    const float* cur = g_xh_p;
    float* nxt_bufs[2] = { g_h2_p, g_h3_p };

    for (int mix = 0; mix < 2; mix++) {
        const float* dtw = dt_proj_w + (size_t)mix*DIN*DTR;
        const float* dtb = dt_proj_b + mix*DIN;
        prepA_k<<<1, DIN>>>(A_log + mix*DIN*4);
        gemm_mma<<<dim3((2*DIN)/64, MROWS/128), 256>>>(
            cur, in_proj_w + (size_t)mix*2*DIN*CEMB, g_xz_p, MROWS, 2*DIN, CEMB);
        conv_k<<<((MROWS/8)*(DIN/4) + 255)/256, 256>>>(conv_w + mix*DIN*4, conv_b + mix*DIN);
        xproj_k<<<MROWS/32, 256>>>(x_proj_w + (size_t)mix*XD*DIN);
        scan1_k<<<dim3(NC, BB), DIN>>>(dtw, dtb);
        scan2_k<<<(BB*DIN + 255)/256, 256>>>();
        scan3_k<<<dim3(NC, BB), DIN>>>(dtw, dtb, Dw + mix*DIN);
        gemm_mma<<<dim3(CEMB/64, MROWS/128), 256>>>(
            g_y_p, out_proj_w + (size_t)mix*CEMB*DIN, nxt_bufs[mix], MROWS, CEMB, DIN);
        cur = nxt_bufs[mix];
    }

    final_k<<<dim3(LLEN/32, BB), 256>>>(U_w, V_w, ln_g, ln_b, out);
}

// round 9
// speedup vs baseline: 1.8666x; 1.0050x over previous
#include <cuda_runtime.h>
#include <cstdint>

#define BB   8
#define LLEN 4096
#define CEMB 192
#define DIN  384
#define XD   20
#define DTR  12
#define NC   128
#define LC   32
#define MROWS (BB*LLEN)

// ---------------- scratch ----------------
__device__ float g_xh  [MROWS*CEMB];
__device__ float g_h2  [MROWS*CEMB];
__device__ float g_xz  [MROWS*2*DIN];
__device__ float g_xa  [MROWS*DIN];
__device__ float g_xdbl[MROWS*DTR];
__device__ float g_bc  [MROWS*8];         // B[4] | C[4]
__device__ float g_y   [MROWS*DIN];
__device__ float g_hpart[BB*DIN*NC*4];
__device__ float g_sumdt[BB*DIN*NC];
__device__ float g_Hinit[BB*DIN*NC*4];
__device__ float g_A[2*DIN*4];
__device__ int   g_slow[2];
__device__ float g_Uf[4*DIN];             // U_w @ Wout2  [4,384]

__device__ __forceinline__ uint32_t smem_u32(const void* p) {
    uint32_t a;
    asm("{ .reg .u64 t; cvta.to.shared.u64 t, %1; cvt.u32.u64 %0, t; }" : "=r"(a) : "l"(p));
    return a;
}

// ======================= split-bf16 HMMA GEMM (pipelined) =======================
__device__ __forceinline__ void cvt_hilo(float4 v, uint32_t& h0, uint32_t& h1,
                                         uint32_t& l0, uint32_t& l1) {
    asm("cvt.rn.bf16x2.f32 %0, %1, %2;" : "=r"(h0) : "f"(v.y), "f"(v.x));
    asm("cvt.rn.bf16x2.f32 %0, %1, %2;" : "=r"(h1) : "f"(v.w), "f"(v.z));
    float a0 = v.x - __uint_as_float(h0 << 16);
    float a1 = v.y - __uint_as_float(h0 & 0xffff0000u);
    float a2 = v.z - __uint_as_float(h1 << 16);
    float a3 = v.w - __uint_as_float(h1 & 0xffff0000u);
    asm("cvt.rn.bf16x2.f32 %0, %1, %2;" : "=r"(l0) : "f"(a1), "f"(a0));
    asm("cvt.rn.bf16x2.f32 %0, %1, %2;" : "=r"(l1) : "f"(a3), "f"(a2));
}

#define LDSM_X4(r0, r1, r2, r3, addr) \
    asm volatile("ldmatrix.sync.aligned.m8n8.x4.shared.b16 {%0,%1,%2,%3}, [%4];" \
        : "=r"(r0), "=r"(r1), "=r"(r2), "=r"(r3) : "r"(addr))
#define LDSM_X2(r0, r1, addr) \
    asm volatile("ldmatrix.sync.aligned.m8n8.x2.shared.b16 {%0,%1}, [%2];" \
        : "=r"(r0), "=r"(r1) : "r"(addr))
#define MMA_BF16(c, a, b) \
    asm volatile("mma.sync.aligned.m16n8k16.row.col.f32.bf16.bf16.f32 " \
        "{%0,%1,%2,%3}, {%4,%5,%6,%7}, {%8,%9}, {%0,%1,%2,%3};" \
        : "+f"((c)[0]), "+f"((c)[1]), "+f"((c)[2]), "+f"((c)[3]) \
        : "r"((a)[0]), "r"((a)[1]), "r"((a)[2]), "r"((a)[3]), "r"((b)[0]), "r"((b)[1]))

__global__ void __launch_bounds__(256, 2)
gemm_mma(const float* __restrict__ A, const float* __restrict__ W,
         float* __restrict__ C, int M, int N, int K)
{
    __shared__ __align__(1024) char sm[49152];
    char* AH = sm;
    char* AL = sm + 16384;
    char* WH = sm + 32768;
    char* WL = sm + 40960;

    const int tid = threadIdx.x, wid = tid >> 5, lane = tid & 31;
    const int wm = wid & 3, wn = wid >> 2;
    const int bm = blockIdx.y * 128, bn = blockIdx.x * 64;
    const uint32_t sAH = smem_u32(AH), sAL = smem_u32(AL);
    const uint32_t sWH = smem_u32(WH), sWL = smem_u32(WL);

    float acc[2][4][4];
    #pragma unroll
    for (int i = 0; i < 2; i++)
        #pragma unroll
        for (int j = 0; j < 4; j++)
            #pragma unroll
            for (int q = 0; q < 4; q++) acc[i][j][q] = 0.f;

    float4 ra[8], rw[4];
    const int nkt = K >> 6;

    #pragma unroll
    for (int i = 0; i < 8; i++) {
        int idx = tid + i * 256, r = idx >> 4, q = idx & 15;
        ra[i] = *(const float4*)(A + (size_t)(bm + r) * K + q * 4);
    }
    #pragma unroll
    for (int i = 0; i < 4; i++) {
        int idx = tid + i * 256, r = idx >> 4, q = idx & 15;
        rw[i] = *(const float4*)(W + (size_t)(bn + r) * K + q * 4);
    }

    for (int kt = 0; kt < nkt; kt++) {
        #pragma unroll
        for (int i = 0; i < 8; i++) {
            int idx = tid + i * 256, r = idx >> 4, q = idx & 15;
            uint32_t h0, h1, l0, l1;
            cvt_hilo(ra[i], h0, h1, l0, l1);
            uint32_t off = (uint32_t)(r * 128 + (((q >> 1) ^ (r & 7)) << 4) + ((q & 1) << 3));
            *(uint2*)(AH + off) = make_uint2(h0, h1);
            *(uint2*)(AL + off) = make_uint2(l0, l1);
        }
        #pragma unroll
        for (int i = 0; i < 4; i++) {
            int idx = tid + i * 256, r = idx >> 4, q = idx & 15;
            uint32_t h0, h1, l0, l1;
            cvt_hilo(rw[i], h0, h1, l0, l1);
            uint32_t off = (uint32_t)(r * 128 + (((q >> 1) ^ (r & 7)) << 4) + ((q & 1) << 3));
            *(uint2*)(WH + off) = make_uint2(h0, h1);
            *(uint2*)(WL + off) = make_uint2(l0, l1);
        }
        __syncthreads();

        if (kt + 1 < nkt) {
            int k0 = (kt + 1) * 64;
            #pragma unroll
            for (int i = 0; i < 8; i++) {
                int idx = tid + i * 256, r = idx >> 4, q = idx & 15;
                ra[i] = *(const float4*)(A + (size_t)(bm + r) * K + k0 + q * 4);
            }
            #pragma unroll
            for (int i = 0; i < 4; i++) {
                int idx = tid + i * 256, r = idx >> 4, q = idx & 15;
                rw[i] = *(const float4*)(W + (size_t)(bn + r) * K + k0 + q * 4);
            }
        }

        #pragma unroll
        for (int ks = 0; ks < 4; ks++) {
            uint32_t ah[2][4], al[2][4], bh[4][2], bl[4][2];
            #pragma unroll
            for (int mt = 0; mt < 2; mt++) {
                int r = wm * 32 + mt * 16 + (lane & 15);
                int c16 = ks * 2 + (lane >> 4);
                uint32_t off = (uint32_t)(r * 128 + ((c16 ^ (r & 7)) << 4));
                LDSM_X4(ah[mt][0], ah[mt][1], ah[mt][2], ah[mt][3], sAH + off);
                LDSM_X4(al[mt][0], al[mt][1], al[mt][2], al[mt][3], sAL + off);
            }
            #pragma unroll
            for (int nt = 0; nt < 4; nt++) {
                int rn = wn * 32 + nt * 8 + (lane & 7);
                int c16 = ks * 2 + ((lane >> 3) & 1);
                uint32_t off = (uint32_t)(rn * 128 + ((c16 ^ (rn & 7)) << 4));
                LDSM_X2(bh[nt][0], bh[nt][1], sWH + off);
                LDSM_X2(bl[nt][0], bl[nt][1], sWL + off);
            }
            #pragma unroll
            for (int mt = 0; mt < 2; mt++)
                #pragma unroll
                for (int nt = 0; nt < 4; nt++) {
                    MMA_BF16(acc[mt][nt], ah[mt], bh[nt]);
                    MMA_BF16(acc[mt][nt], ah[mt], bl[nt]);
                    MMA_BF16(acc[mt][nt], al[mt], bh[nt]);
                }
        }
        __syncthreads();
    }

    #pragma unroll
    for (int mt = 0; mt < 2; mt++) {
        int row = bm + wm * 32 + mt * 16 + (lane >> 2);
        #pragma unroll
        for (int nt = 0; nt < 4; nt++) {
            int col = bn + wn * 32 + nt * 8 + (lane & 3) * 2;
            *(float2*)(C + (size_t)row * N + col)       = make_float2(acc[mt][nt][0], acc[mt][nt][1]);
            *(float2*)(C + (size_t)(row + 8) * N + col) = make_float2(acc[mt][nt][2], acc[mt][nt][3]);
        }
    }
}

// ---------------- transpose (B,C,L) -> (B,L,C) ----------------
__global__ void transpose_k(const float* __restrict__ x) {
    __shared__ float t[32][33];
    int b = blockIdx.z;
    int l0 = blockIdx.x * 32, c0 = blockIdx.y * 32;
    int tx = threadIdx.x, ty = threadIdx.y;
    #pragma unroll
    for (int j = ty; j < 32; j += 8)
        t[j][tx] = x[((b*CEMB) + (c0 + j)) * LLEN + l0 + tx];
    __syncthreads();
    #pragma unroll
    for (int j = ty; j < 32; j += 8)
        g_xh[((b*LLEN) + (l0 + j)) * CEMB + c0 + tx] = t[tx][j];
}

// ---------------- A structure prep (both mixes) ----------------
__global__ void prepA_k(const float* __restrict__ A_log) {
    int mix = blockIdx.x;
    int d = threadIdx.x;
    if (d == 0) g_slow[mix] = 0;
    __syncthreads();
    const float* al = A_log + mix * DIN * 4;
    float a[4];
    #pragma unroll
    for (int s = 0; s < 4; s++) {
        a[s] = -expf(al[d*4 + s]);
        g_A[(mix*DIN + d)*4 + s] = a[s];
    }
    bool ok = true;
    #pragma unroll
    for (int s = 0; s < 4; s++) {
        float want = (float)(s + 1) * a[0];
        if (fabsf(a[s] - want) > 1e-5f * fabsf(a[s]) + 1e-7f) ok = false;
    }
    if (!ok) atomicExch(&g_slow[mix], 1);
}

// ---------------- Uf = U_w @ Wout2  [4,384] ----------------
__global__ void uf_k(const float* __restrict__ U, const float* __restrict__ Wout2) {
    __shared__ float Ush[4*CEMB];
    int k = threadIdx.x;               // 0..383
    for (int i = k; i < 4*CEMB; i += DIN) Ush[i] = U[i];
    __syncthreads();
    float acc0 = 0.f, acc1 = 0.f, acc2 = 0.f, acc3 = 0.f;
    for (int c = 0; c < CEMB; c++) {
        float w = Wout2[(size_t)c * DIN + k];
        acc0 = fmaf(Ush[0*CEMB + c], w, acc0);
        acc1 = fmaf(Ush[1*CEMB + c], w, acc1);
        acc2 = fmaf(Ush[2*CEMB + c], w, acc2);
        acc3 = fmaf(Ush[3*CEMB + c], w, acc3);
    }
    g_Uf[0*DIN + k] = acc0;
    g_Uf[1*DIN + k] = acc1;
    g_Uf[2*DIN + k] = acc2;
    g_Uf[3*DIN + k] = acc3;
}

// ---------------- depthwise causal conv (k=4) + silu, rolling window ----------------
__global__ void __launch_bounds__(256)
conv_k(const float* __restrict__ w, const float* __restrict__ bias) {
    int idx = blockIdx.x * blockDim.x + threadIdx.x;
    if (idx >= (MROWS/8) * (DIN/4)) return;
    int d4 = idx % (DIN/4);
    int m8 = idx / (DIN/4);
    int d  = d4 * 4;
    int bl = m8 * 8;
    int l  = bl % LLEN;

    float4 wv0 = *(const float4*)(w + (d+0)*4);
    float4 wv1 = *(const float4*)(w + (d+1)*4);
    float4 wv2 = *(const float4*)(w + (d+2)*4);
    float4 wv3 = *(const float4*)(w + (d+3)*4);
    float4 bv  = *(const float4*)(bias + d);

    const float* p = g_xz + (size_t)bl * (2*DIN) + d;
    float* po = g_xa + (size_t)bl * DIN + d;
    float4 x1 = make_float4(0,0,0,0), x2 = x1, x3 = x1;
    if (l) {
        x3 = *(const float4*)(p - 3*2*DIN);
        x2 = *(const float4*)(p - 2*2*DIN);
        x1 = *(const float4*)(p - 2*DIN);
    }
    #pragma unroll
    for (int j = 0; j < 8; j++) {
        float4 x0 = *(const float4*)(p + j*2*DIN);
        float4 acc = bv;
        acc.x = fmaf(wv0.x, x3.x, acc.x); acc.y = fmaf(wv1.x, x3.y, acc.y);
        acc.z = fmaf(wv2.x, x3.z, acc.z); acc.w = fmaf(wv3.x, x3.w, acc.w);
        acc.x = fmaf(wv0.y, x2.x, acc.x); acc.y = fmaf(wv1.y, x2.y, acc.y);
        acc.z = fmaf(wv2.y, x2.z, acc.z); acc.w = fmaf(wv3.y, x2.w, acc.w);
        acc.x = fmaf(wv0.z, x1.x, acc.x); acc.y = fmaf(wv1.z, x1.y, acc.y);
        acc.z = fmaf(wv2.z, x1.z, acc.z); acc.w = fmaf(wv3.z, x1.w, acc.w);
        acc.x = fmaf(wv0.w, x0.x, acc.x); acc.y = fmaf(wv1.w, x0.y, acc.y);
        acc.z = fmaf(wv2.w, x0.z, acc.z); acc.w = fmaf(wv3.w, x0.w, acc.w);
        float4 s;
        s.x = __fdividef(acc.x, 1.f + __expf(-acc.x));
        s.y = __fdividef(acc.y, 1.f + __expf(-acc.y));
        s.z = __fdividef(acc.z, 1.f + __expf(-acc.z));
        s.w = __fdividef(acc.w, 1.f + __expf(-acc.w));
        *(float4*)(po + j*DIN) = s;
        x3 = x2; x2 = x1; x1 = x0;
    }
}

// ---------------- x_proj: 32 rows/block ----------------
__global__ void __launch_bounds__(256)
xproj_k(const float* __restrict__ W) {
    __shared__ __align__(16) float Wsh[XD * DIN];
    for (int i = threadIdx.x; i < XD*DIN; i += 256) Wsh[i] = W[i];
    __syncthreads();
    int warp = threadIdx.x >> 5, lane = threadIdx.x & 31;
    int m0 = blockIdx.x * 32;
    for (int r = warp; r < 32; r += 8) {
        int m = m0 + r;
        const float4* ar = (const float4*)(g_xa + (size_t)m * DIN);
        float acc[XD];
        #pragma unroll
        for (int n = 0; n < XD; n++) acc[n] = 0.f;
        #pragma unroll
        for (int it = 0; it < 3; it++) {
            int k4 = lane + it * 32;
            float4 a = ar[k4];
            #pragma unroll
            for (int n = 0; n < XD; n++) {
                const float4 wv = *(const float4*)(Wsh + n*DIN + k4*4);
                acc[n] = fmaf(a.x, wv.x, fmaf(a.y, wv.y, fmaf(a.z, wv.z, fmaf(a.w, wv.w, acc[n]))));
            }
        }
        float myv = 0.f;
        #pragma unroll
        for (int n = 0; n < XD; n++) {
            float v = acc[n];
            #pragma unroll
            for (int off = 16; off > 0; off >>= 1)
                v += __shfl_xor_sync(0xffffffffu, v, off);
            if (lane == n) myv = v;
        }
        if (lane < DTR) g_xdbl[(size_t)m*DTR + lane] = myv;
        else if (lane < XD) g_bc[(size_t)m*8 + lane - DTR] = myv;
    }
}

// ---------------- scan pass 1 (dt inline) ----------------
__global__ void scan1_k(const float* __restrict__ dtw, const float* __restrict__ dtb, int mix) {
    __shared__ float Bsm[LC][4];
    __shared__ float Xd[LC][DTR];
    int chunk = blockIdx.x, b = blockIdx.y, d = threadIdx.x;
    int l0 = chunk * LC;
    if (threadIdx.x < LC*4) {
        int l = threadIdx.x >> 2, s = threadIdx.x & 3;
        Bsm[l][s] = g_bc[((size_t)(b*LLEN + l0 + l))*8 + s];
    }
    {
        int l = threadIdx.x / DTR, r = threadIdx.x - l*DTR;
        Xd[l][r] = g_xdbl[((size_t)(b*LLEN + l0 + l))*DTR + r];
    }
    __syncthreads();
    int slow = g_slow[mix];
    const float* Ab = g_A + (mix*DIN + d)*4;
    float Av0 = Ab[0], Av1 = Ab[1], Av2 = Ab[2], Av3 = Ab[3];
    const float4* w4 = (const float4*)(dtw + d * DTR);
    float4 dw0 = w4[0], dw1 = w4[1], dw2 = w4[2];
    float pb = dtb[d];
    float h0 = 0.f, h1 = 0.f, h2 = 0.f, h3 = 0.f, sd = 0.f;
    const float* pa = g_xa + (size_t)(b*LLEN + l0)*DIN + d;
    #pragma unroll 4
    for (int l = 0; l < LC; l++) {
        float xav = pa[l*DIN];
        const float* xr = Xd[l];
        float p = pb;
        p = fmaf(xr[0], dw0.x, p);  p = fmaf(xr[1], dw0.y, p);
        p = fmaf(xr[2], dw0.z, p);  p = fmaf(xr[3], dw0.w, p);
        p = fmaf(xr[4], dw1.x, p);  p = fmaf(xr[5], dw1.y, p);
        p = fmaf(xr[6], dw1.z, p);  p = fmaf(xr[7], dw1.w, p);
        p = fmaf(xr[8], dw2.x, p);  p = fmaf(xr[9], dw2.y, p);
        p = fmaf(xr[10], dw2.z, p); p = fmaf(xr[11], dw2.w, p);
        float dtv = (p > 20.f) ? p : __logf(1.f + __expf(p));
        float dbu = dtv * xav;
        sd += dtv;
        float b0 = Bsm[l][0], b1 = Bsm[l][1], b2 = Bsm[l][2], b3 = Bsm[l][3];
        if (!slow) {
            float e = __expf(Av0 * dtv);
            float q = e;
            h0 = fmaf(q, h0, dbu*b0); q *= e;
            h1 = fmaf(q, h1, dbu*b1); q *= e;
            h2 = fmaf(q, h2, dbu*b2); q *= e;
            h3 = fmaf(q, h3, dbu*b3);
        } else {
            h0 = fmaf(__expf(dtv*Av0), h0, dbu*b0);
            h1 = fmaf(__expf(dtv*Av1), h1, dbu*b1);
            h2 = fmaf(__expf(dtv*Av2), h2, dbu*b2);
            h3 = fmaf(__expf(dtv*Av3), h3, dbu*b3);
        }
    }
    int o = ((b*DIN) + d)*NC + chunk;
    ((float4*)g_hpart)[o] = make_float4(h0, h1, h2, h3);
    g_sumdt[o] = sd;
}

// ---------------- scan pass 2 ----------------
__global__ void scan2_k(int mix) {
    int t = blockIdx.x * blockDim.x + threadIdx.x;
    if (t >= BB*DIN) return;
    int d = t % DIN;
    const float* Ab = g_A + (mix*DIN + d)*4;
    float Av0 = Ab[0], Av1 = Ab[1], Av2 = Ab[2], Av3 = Ab[3];
    float H0 = 0.f, H1 = 0.f, H2 = 0.f, H3 = 0.f;
    for (int c = 0; c < NC; c++) {
        int o = t*NC + c;
        ((float4*)g_Hinit)[o] = make_float4(H0, H1, H2, H3);
        float4 hp = ((const float4*)g_hpart)[o];
        float sd = g_sumdt[o];
        H0 = fmaf(__expf(Av0*sd), H0, hp.x);
        H1 = fmaf(__expf(Av1*sd), H1, hp.y);
        H2 = fmaf(__expf(Av2*sd), H2, hp.z);
        H3 = fmaf(__expf(Av3*sd), H3, hp.w);
    }
}

// ---------------- scan pass 3 (dt inline) ----------------
__global__ void scan3_k(const float* __restrict__ dtw, const float* __restrict__ dtb,
                        const float* __restrict__ Dw, int mix) {
    __shared__ float Bsm[LC][4];
    __shared__ float Csm[LC][4];
    __shared__ float Xd[LC][DTR];
    int chunk = blockIdx.x, b = blockIdx.y, d = threadIdx.x;
    int l0 = chunk * LC;
    if (threadIdx.x < LC*8) {
        int l = threadIdx.x >> 3, s = threadIdx.x & 7;
        float v = g_bc[((size_t)(b*LLEN + l0 + l))*8 + s];
        if (s < 4) Bsm[l][s] = v; else Csm[l][s-4] = v;
    }
    {
        int l = threadIdx.x / DTR, r = threadIdx.x - l*DTR;
        Xd[l][r] = g_xdbl[((size_t)(b*LLEN + l0 + l))*DTR + r];
    }
    __syncthreads();
    int slow = g_slow[mix];
    const float* Ab = g_A + (mix*DIN + d)*4;
    float Av0 = Ab[0], Av1 = Ab[1], Av2 = Ab[2], Av3 = Ab[3];
    const float4* w4 = (const float4*)(dtw + d * DTR);
    float4 dw0 = w4[0], dw1 = w4[1], dw2 = w4[2];
    float pb = dtb[d];
    float Dd = Dw[d];
    int o = ((b*DIN) + d)*NC + chunk;
    float4 Hi = ((const float4*)g_Hinit)[o];
    float h0 = Hi.x, h1 = Hi.y, h2 = Hi.z, h3 = Hi.w;
    const float* pa = g_xa + (size_t)(b*LLEN + l0)*DIN + d;
    const float* pz = g_xz + (size_t)(b*LLEN + l0)*(2*DIN) + DIN + d;
    float* py = g_y + (size_t)(b*LLEN + l0)*DIN + d;
    #pragma unroll 4
    for (int l = 0; l < LC; l++) {
        float xav = pa[l*DIN];
        const float* xr = Xd[l];
        float p = pb;
        p = fmaf(xr[0], dw0.x, p);  p = fmaf(xr[1], dw0.y, p);
        p = fmaf(xr[2], dw0.z, p);  p = fmaf(xr[3], dw0.w, p);
        p = fmaf(xr[4], dw1.x, p);  p = fmaf(xr[5], dw1.y, p);
        p = fmaf(xr[6], dw1.z, p);  p = fmaf(xr[7], dw1.w, p);
        p = fmaf(xr[8], dw2.x, p);  p = fmaf(xr[9], dw2.y, p);
        p = fmaf(xr[10], dw2.z, p); p = fmaf(xr[11], dw2.w, p);
        float dtv = (p > 20.f) ? p : __logf(1.f + __expf(p));
        float dbu = dtv * xav;
        float b0 = Bsm[l][0], b1 = Bsm[l][1], b2 = Bsm[l][2], b3 = Bsm[l][3];
        if (!slow) {
            float e = __expf(Av0 * dtv);
            float q = e;
            h0 = fmaf(q, h0, dbu*b0); q *= e;
            h1 = fmaf(q, h1, dbu*b1); q *= e;
            h2 = fmaf(q, h2, dbu*b2); q *= e;
            h3 = fmaf(q, h3, dbu*b3);
        } else {
            h0 = fmaf(__expf(dtv*Av0), h0, dbu*b0);
            h1 = fmaf(__expf(dtv*Av1), h1, dbu*b1);
            h2 = fmaf(__expf(dtv*Av2), h2, dbu*b2);
            h3 = fmaf(__expf(dtv*Av3), h3, dbu*b3);
        }
        float y = h0*Csm[l][0] + h1*Csm[l][1] + h2*Csm[l][2] + h3*Csm[l][3];
        y = fmaf(xav, Dd, y);
        float zv = pz[l*2*DIN];
        float zs = __fdividef(zv, 1.f + __expf(-zv));
        py[l*DIN] = y * zs;
    }
}

// ---------------- final: u = y2 @ Uf^T; out = LN(xh + u @ V^T) ----------------
__global__ void final_k(const float* __restrict__ V,
                        const float* __restrict__ lng, const float* __restrict__ lnb,
                        float* __restrict__ out)
{
    __shared__ __align__(16) float Ufs[4*DIN];
    __shared__ float Vsh[CEMB*4];
    __shared__ float u[32][4];
    __shared__ float vs[32][193];
    __shared__ float mu[32], rsd[32];
    int b = blockIdx.y;
    int l0 = blockIdx.x * 32;
    int tid = threadIdx.x;
    for (int i = tid; i < 4*DIN; i += 256) Ufs[i] = g_Uf[i];
    for (int i = tid; i < 4*CEMB; i += 256) Vsh[i] = V[i];
    __syncthreads();
    if (tid < 128) {
        int p = tid >> 2, r = tid & 3;
        const float4* yr = (const float4*)(g_y + ((size_t)(b*LLEN) + l0 + p)*DIN);
        const float4* uf = (const float4*)(Ufs + r*DIN);
        float a = 0.f;
        #pragma unroll 8
        for (int c = 0; c < DIN/4; c++) {
            float4 yv = yr[c];
            float4 wv = uf[c];
            a = fmaf(yv.x, wv.x, fmaf(yv.y, wv.y, fmaf(yv.z, wv.z, fmaf(yv.w, wv.w, a))));
        }
        u[p][r] = a;
    }
    __syncthreads();
    for (int i = tid; i < 32*CEMB; i += 256) {
        int p = i / CEMB, c = i % CEMB;
        float v = g_xh[((size_t)(b*LLEN) + l0 + p)*CEMB + c];
        v = fmaf(Vsh[c*4+0], u[p][0], v);
        v = fmaf(Vsh[c*4+1], u[p][1], v);
        v = fmaf(Vsh[c*4+2], u[p][2], v);
        v = fmaf(Vsh[c*4+3], u[p][3], v);
        vs[p][c] = v;
    }
    __syncthreads();
    int warp = tid >> 5, lane = tid & 31;
    #pragma unroll
    for (int pp = 0; pp < 4; pp++) {
        int p = warp*4 + pp;
        float s = 0.f, ss = 0.f;
        for (int c = lane; c < CEMB; c += 32) {
            float v = vs[p][c];
            s += v; ss = fmaf(v, v, ss);
        }
        #pragma unroll
        for (int off = 16; off > 0; off >>= 1) {
            s  += __shfl_xor_sync(0xffffffffu, s, off);
            ss += __shfl_xor_sync(0xffffffffu, ss, off);
        }
        if (lane == 0) {
            float m = s * (1.f/CEMB);
            mu[p] = m;
            rsd[p] = rsqrtf(ss * (1.f/CEMB) - m*m + 1e-5f);
        }
    }
    __syncthreads();
    for (int c = warp; c < CEMB; c += 8) {
        int p = lane;
        float v = (vs[p][c] - mu[p]) * rsd[p] * lng[c] + lnb[c];
        out[((size_t)(b*CEMB) + c)*LLEN + l0 + lane] = v;
    }
}

// ---------------- launch ----------------
extern "C" void kernel_launch(void* const* d_in, const int* in_sizes, int n_in,
                              void* d_out, int out_size)
{
    const float* x         = (const float*)d_in[0];
    const float* in_proj_w = (const float*)d_in[1];
    const float* conv_w    = (const float*)d_in[2];
    const float* conv_b    = (const float*)d_in[3];
    const float* x_proj_w  = (const float*)d_in[4];
    const float* dt_proj_w = (const float*)d_in[5];
    const float* dt_proj_b = (const float*)d_in[6];
    const float* A_log     = (const float*)d_in[7];
    const float* Dw        = (const float*)d_in[8];
    const float* out_proj_w= (const float*)d_in[9];
    const float* U_w       = (const float*)d_in[10];
    const float* V_w       = (const float*)d_in[11];
    const float* ln_g      = (const float*)d_in[12];
    const float* ln_b      = (const float*)d_in[13];
    float* out = (float*)d_out;

    float* g_xh_p;  cudaGetSymbolAddress((void**)&g_xh_p,  g_xh);
    float* g_h2_p;  cudaGetSymbolAddress((void**)&g_h2_p,  g_h2);
    float* g_xz_p;  cudaGetSymbolAddress((void**)&g_xz_p,  g_xz);
    float* g_y_p;   cudaGetSymbolAddress((void**)&g_y_p,   g_y);

    transpose_k<<<dim3(LLEN/32, CEMB/32, BB), dim3(32, 8)>>>(x);
    prepA_k<<<2, DIN>>>(A_log);
    uf_k<<<1, DIN>>>(U_w, out_proj_w + (size_t)CEMB*DIN);   // mix2's out_proj

    const float* cur = g_xh_p;
    for (int mix = 0; mix < 2; mix++) {
        const float* dtw = dt_proj_w + (size_t)mix*DIN*DTR;
        const float* dtb = dt_proj_b + mix*DIN;
        gemm_mma<<<dim3((2*DIN)/64, MROWS/128), 256>>>(
            cur, in_proj_w + (size_t)mix*2*DIN*CEMB, g_xz_p, MROWS, 2*DIN, CEMB);
        conv_k<<<((MROWS/8)*(DIN/4) + 255)/256, 256>>>(conv_w + mix*DIN*4, conv_b + mix*DIN);
        xproj_k<<<MROWS/32, 256>>>(x_proj_w + (size_t)mix*XD*DIN);
        scan1_k<<<dim3(NC, BB), DIN>>>(dtw, dtb, mix);
        scan2_k<<<(BB*DIN + 255)/256, 256>>>(mix);
        scan3_k<<<dim3(NC, BB), DIN>>>(dtw, dtb, Dw + mix*DIN, mix);
        if (mix == 0) {
            gemm_mma<<<dim3(CEMB/64, MROWS/128), 256>>>(
                g_y_p, out_proj_w, g_h2_p, MROWS, CEMB, DIN);
            cur = g_h2_p;
        }
    }

    final_k<<<dim3(LLEN/32, BB), 256>>>(V_w, ln_g, ln_b, out);
}

// round 10
// speedup vs baseline: 1.8708x; 1.0023x over previous
#include <cuda_runtime.h>
#include <cuda_bf16.h>
#include <cstdint>

#define BB   8
#define LLEN 4096
#define CEMB 192
#define DIN  384
#define XD   20
#define DTR  12
#define NC   128
#define LC   32
#define MROWS (BB*LLEN)

// ---------------- scratch ----------------
__device__ float g_xh  [MROWS*CEMB];
__device__ float g_xz  [MROWS*2*DIN];
__device__ float g_xa  [MROWS*DIN];
__device__ float g_xdbl[MROWS*DTR];
__device__ float g_bc  [MROWS*8];
__device__ float g_y   [MROWS*DIN];
__device__ float g_hpart[BB*DIN*NC*4];
__device__ float g_sumdt[BB*DIN*NC];
__device__ float g_Hinit[BB*DIN*NC*4];
__device__ float g_A[2*DIN*4];
__device__ int   g_slow[2];
__device__ float g_Uf[4*DIN];
// bf16 hi/lo staging
__device__ __nv_bfloat16 g_ahi[MROWS*DIN], g_alo[MROWS*DIN];     // xh then y
__device__ __nv_bfloat16 g_bhi[MROWS*CEMB], g_blo[MROWS*CEMB];   // h2
__device__ __nv_bfloat16 g_whi[768*CEMB], g_wlo[768*CEMB];       // weights

__device__ __forceinline__ uint32_t smem_u32(const void* p) {
    uint32_t a;
    asm("{ .reg .u64 t; cvta.to.shared.u64 t, %1; cvt.u32.u64 %0, t; }" : "=r"(a) : "l"(p));
    return a;
}
__device__ __forceinline__ void cvt_hilo(float4 v, uint32_t& h0, uint32_t& h1,
                                         uint32_t& l0, uint32_t& l1) {
    asm("cvt.rn.bf16x2.f32 %0, %1, %2;" : "=r"(h0) : "f"(v.y), "f"(v.x));
    asm("cvt.rn.bf16x2.f32 %0, %1, %2;" : "=r"(h1) : "f"(v.w), "f"(v.z));
    float a0 = v.x - __uint_as_float(h0 << 16);
    float a1 = v.y - __uint_as_float(h0 & 0xffff0000u);
    float a2 = v.z - __uint_as_float(h1 << 16);
    float a3 = v.w - __uint_as_float(h1 & 0xffff0000u);
    asm("cvt.rn.bf16x2.f32 %0, %1, %2;" : "=r"(l0) : "f"(a1), "f"(a0));
    asm("cvt.rn.bf16x2.f32 %0, %1, %2;" : "=r"(l1) : "f"(a3), "f"(a2));
}
__device__ __forceinline__ void hilo_scalar(float v, __nv_bfloat16& h, __nv_bfloat16& l) {
    h = __float2bfloat16(v);
    l = __float2bfloat16(v - __bfloat162float(h));
}

#define LDSM_X4(r0, r1, r2, r3, addr) \
    asm volatile("ldmatrix.sync.aligned.m8n8.x4.shared.b16 {%0,%1,%2,%3}, [%4];" \
        : "=r"(r0), "=r"(r1), "=r"(r2), "=r"(r3) : "r"(addr))
#define LDSM_X2(r0, r1, addr) \
    asm volatile("ldmatrix.sync.aligned.m8n8.x2.shared.b16 {%0,%1}, [%2];" \
        : "=r"(r0), "=r"(r1) : "r"(addr))
#define MMA_BF16(c, a, b) \
    asm volatile("mma.sync.aligned.m16n8k16.row.col.f32.bf16.bf16.f32 " \
        "{%0,%1,%2,%3}, {%4,%5,%6,%7}, {%8,%9}, {%0,%1,%2,%3};" \
        : "+f"((c)[0]), "+f"((c)[1]), "+f"((c)[2]), "+f"((c)[3]) \
        : "r"((a)[0]), "r"((a)[1]), "r"((a)[2]), "r"((a)[3]), "r"((b)[0]), "r"((b)[1]))

// ======================= bf16 HMMA GEMM, pre-converted operands =======================
__global__ void __launch_bounds__(256, 2)
gemm_mma(const __nv_bfloat16* __restrict__ Ahi, const __nv_bfloat16* __restrict__ Alo,
         const __nv_bfloat16* __restrict__ Whi, const __nv_bfloat16* __restrict__ Wlo,
         float* __restrict__ C, __nv_bfloat16* __restrict__ Chi, __nv_bfloat16* __restrict__ Clo,
         int M, int N, int K, int out_bf16)
{
    __shared__ __align__(1024) char sm[49152];
    char* AH = sm;
    char* AL = sm + 16384;
    char* WH = sm + 32768;
    char* WL = sm + 40960;

    const int tid = threadIdx.x, wid = tid >> 5, lane = tid & 31;
    const int wm = wid & 3, wn = wid >> 2;
    const int bm = blockIdx.y * 128, bn = blockIdx.x * 64;
    const uint32_t sAH = smem_u32(AH), sAL = smem_u32(AL);
    const uint32_t sWH = smem_u32(WH), sWL = smem_u32(WL);

    float acc[2][4][4];
    #pragma unroll
    for (int i = 0; i < 2; i++)
        #pragma unroll
        for (int j = 0; j < 4; j++)
            #pragma unroll
            for (int q = 0; q < 4; q++) acc[i][j][q] = 0.f;

    uint4 rah[4], ral[4], rwh[2], rwl[2];
    const int nkt = K >> 6;

    #pragma unroll
    for (int i = 0; i < 4; i++) {
        int idx = tid + i * 256, r = idx >> 3, q = idx & 7;
        size_t go = (size_t)(bm + r) * K + q * 8;
        rah[i] = *(const uint4*)(Ahi + go);
        ral[i] = *(const uint4*)(Alo + go);
    }
    #pragma unroll
    for (int i = 0; i < 2; i++) {
        int idx = tid + i * 256, r = idx >> 3, q = idx & 7;
        size_t go = (size_t)(bn + r) * K + q * 8;
        rwh[i] = *(const uint4*)(Whi + go);
        rwl[i] = *(const uint4*)(Wlo + go);
    }

    for (int kt = 0; kt < nkt; kt++) {
        #pragma unroll
        for (int i = 0; i < 4; i++) {
            int idx = tid + i * 256, r = idx >> 3, q = idx & 7;
            uint32_t off = (uint32_t)(r * 128 + ((q ^ (r & 7)) << 4));
            *(uint4*)(AH + off) = rah[i];
            *(uint4*)(AL + off) = ral[i];
        }
        #pragma unroll
        for (int i = 0; i < 2; i++) {
            int idx = tid + i * 256, r = idx >> 3, q = idx & 7;
            uint32_t off = (uint32_t)(r * 128 + ((q ^ (r & 7)) << 4));
            *(uint4*)(WH + off) = rwh[i];
            *(uint4*)(WL + off) = rwl[i];
        }
        __syncthreads();

        if (kt + 1 < nkt) {
            int k0 = (kt + 1) * 64;
            #pragma unroll
            for (int i = 0; i < 4; i++) {
                int idx = tid + i * 256, r = idx >> 3, q = idx & 7;
                size_t go = (size_t)(bm + r) * K + k0 + q * 8;
                rah[i] = *(const uint4*)(Ahi + go);
                ral[i] = *(const uint4*)(Alo + go);
            }
            #pragma unroll
            for (int i = 0; i < 2; i++) {
                int idx = tid + i * 256, r = idx >> 3, q = idx & 7;
                size_t go = (size_t)(bn + r) * K + k0 + q * 8;
                rwh[i] = *(const uint4*)(Whi + go);
                rwl[i] = *(const uint4*)(Wlo + go);
            }
        }

        #pragma unroll
        for (int ks = 0; ks < 4; ks++) {
            uint32_t ah[2][4], al[2][4], bh[4][2], bl[4][2];
            #pragma unroll
            for (int mt = 0; mt < 2; mt++) {
                int r = wm * 32 + mt * 16 + (lane & 15);
                int c16 = ks * 2 + (lane >> 4);
                uint32_t off = (uint32_t)(r * 128 + ((c16 ^ (r & 7)) << 4));
                LDSM_X4(ah[mt][0], ah[mt][1], ah[mt][2], ah[mt][3], sAH + off);
                LDSM_X4(al[mt][0], al[mt][1], al[mt][2], al[mt][3], sAL + off);
            }
            #pragma unroll
            for (int nt = 0; nt < 4; nt++) {
                int rn = wn * 32 + nt * 8 + (lane & 7);
                int c16 = ks * 2 + ((lane >> 3) & 1);
                uint32_t off = (uint32_t)(rn * 128 + ((c16 ^ (rn & 7)) << 4));
                LDSM_X2(bh[nt][0], bh[nt][1], sWH + off);
                LDSM_X2(bl[nt][0], bl[nt][1], sWL + off);
            }
            #pragma unroll
            for (int mt = 0; mt < 2; mt++)
                #pragma unroll
                for (int nt = 0; nt < 4; nt++) {
                    MMA_BF16(acc[mt][nt], ah[mt], bh[nt]);
                    MMA_BF16(acc[mt][nt], ah[mt], bl[nt]);
                    MMA_BF16(acc[mt][nt], al[mt], bh[nt]);
                }
        }
        __syncthreads();
    }

    if (!out_bf16) {
        #pragma unroll
        for (int mt = 0; mt < 2; mt++) {
            int row = bm + wm * 32 + mt * 16 + (lane >> 2);
            #pragma unroll
            for (int nt = 0; nt < 4; nt++) {
                int col = bn + wn * 32 + nt * 8 + (lane & 3) * 2;
                *(float2*)(C + (size_t)row * N + col)       = make_float2(acc[mt][nt][0], acc[mt][nt][1]);
                *(float2*)(C + (size_t)(row + 8) * N + col) = make_float2(acc[mt][nt][2], acc[mt][nt][3]);
            }
        }
    } else {
        #pragma unroll
        for (int mt = 0; mt < 2; mt++) {
            int row = bm + wm * 32 + mt * 16 + (lane >> 2);
            #pragma unroll
            for (int nt = 0; nt < 4; nt++) {
                int col = bn + wn * 32 + nt * 8 + (lane & 3) * 2;
                #pragma unroll
                for (int hh = 0; hh < 2; hh++) {
                    float a0 = acc[mt][nt][hh*2+0], a1 = acc[mt][nt][hh*2+1];
                    size_t off = (size_t)(row + hh*8) * N + col;
                    uint32_t h, l;
                    asm("cvt.rn.bf16x2.f32 %0, %1, %2;" : "=r"(h) : "f"(a1), "f"(a0));
                    float h0f = __uint_as_float(h << 16);
                    float h1f = __uint_as_float(h & 0xffff0000u);
                    asm("cvt.rn.bf16x2.f32 %0, %1, %2;" : "=r"(l) : "f"(a1 - h1f), "f"(a0 - h0f));
                    *(uint32_t*)(Chi + off) = h;
                    *(uint32_t*)(Clo + off) = l;
                }
            }
        }
    }
}

// ---------------- weight convert: fp32 -> bf16 hi/lo ----------------
__global__ void wcvt_k(const float* __restrict__ src, int n4) {
    int idx = blockIdx.x * blockDim.x + threadIdx.x;
    if (idx >= n4) return;
    float4 v = ((const float4*)src)[idx];
    uint32_t h0, h1, l0, l1;
    cvt_hilo(v, h0, h1, l0, l1);
    ((uint2*)g_whi)[idx] = make_uint2(h0, h1);
    ((uint2*)g_wlo)[idx] = make_uint2(l0, l1);
}

// ---------------- transpose (B,C,L) -> (B,L,C), fp32 + bf16 hi/lo ----------------
__global__ void transpose_k(const float* __restrict__ x) {
    __shared__ float t[32][33];
    int b = blockIdx.z;
    int l0 = blockIdx.x * 32, c0 = blockIdx.y * 32;
    int tx = threadIdx.x, ty = threadIdx.y;
    #pragma unroll
    for (int j = ty; j < 32; j += 8)
        t[j][tx] = x[((b*CEMB) + (c0 + j)) * LLEN + l0 + tx];
    __syncthreads();
    #pragma unroll
    for (int j = ty; j < 32; j += 8) {
        float v = t[tx][j];
        size_t idx = ((size_t)(b*LLEN) + (l0 + j)) * CEMB + c0 + tx;
        g_xh[idx] = v;
        __nv_bfloat16 h, l;
        hilo_scalar(v, h, l);
        g_ahi[idx] = h; g_alo[idx] = l;
    }
}

// ---------------- A structure prep ----------------
__global__ void prepA_k(const float* __restrict__ A_log) {
    int mix = blockIdx.x;
    int d = threadIdx.x;
    if (d == 0) g_slow[mix] = 0;
    __syncthreads();
    const float* al = A_log + mix * DIN * 4;
    float a[4];
    #pragma unroll
    for (int s = 0; s < 4; s++) {
        a[s] = -expf(al[d*4 + s]);
        g_A[(mix*DIN + d)*4 + s] = a[s];
    }
    bool ok = true;
    #pragma unroll
    for (int s = 0; s < 4; s++) {
        float want = (float)(s + 1) * a[0];
        if (fabsf(a[s] - want) > 1e-5f * fabsf(a[s]) + 1e-7f) ok = false;
    }
    if (!ok) atomicExch(&g_slow[mix], 1);
}

// ---------------- Uf = U_w @ Wout2 ----------------
__global__ void uf_k(const float* __restrict__ U, const float* __restrict__ Wout2) {
    __shared__ float Ush[4*CEMB];
    int k = threadIdx.x;
    for (int i = k; i < 4*CEMB; i += DIN) Ush[i] = U[i];
    __syncthreads();
    float acc0 = 0.f, acc1 = 0.f, acc2 = 0.f, acc3 = 0.f;
    for (int c = 0; c < CEMB; c++) {
        float w = Wout2[(size_t)c * DIN + k];
        acc0 = fmaf(Ush[0*CEMB + c], w, acc0);
        acc1 = fmaf(Ush[1*CEMB + c], w, acc1);
        acc2 = fmaf(Ush[2*CEMB + c], w, acc2);
        acc3 = fmaf(Ush[3*CEMB + c], w, acc3);
    }
    g_Uf[0*DIN + k] = acc0;
    g_Uf[1*DIN + k] = acc1;
    g_Uf[2*DIN + k] = acc2;
    g_Uf[3*DIN + k] = acc3;
}

// ---------------- depthwise causal conv + silu, rolling window ----------------
__global__ void __launch_bounds__(256)
conv_k(const float* __restrict__ w, const float* __restrict__ bias) {
    int idx = blockIdx.x * blockDim.x + threadIdx.x;
    if (idx >= (MROWS/8) * (DIN/4)) return;
    int d4 = idx % (DIN/4);
    int m8 = idx / (DIN/4);
    int d  = d4 * 4;
    int bl = m8 * 8;
    int l  = bl % LLEN;

    float4 wv0 = *(const float4*)(w + (d+0)*4);
    float4 wv1 = *(const float4*)(w + (d+1)*4);
    float4 wv2 = *(const float4*)(w + (d+2)*4);
    float4 wv3 = *(const float4*)(w + (d+3)*4);
    float4 bv  = *(const float4*)(bias + d);

    const float* p = g_xz + (size_t)bl * (2*DIN) + d;
    float* po = g_xa + (size_t)bl * DIN + d;
    float4 x1 = make_float4(0,0,0,0), x2 = x1, x3 = x1;
    if (l) {
        x3 = *(const float4*)(p - 3*2*DIN);
        x2 = *(const float4*)(p - 2*2*DIN);
        x1 = *(const float4*)(p - 2*DIN);
    }
    #pragma unroll
    for (int j = 0; j < 8; j++) {
        float4 x0 = *(const float4*)(p + j*2*DIN);
        float4 acc = bv;
        acc.x = fmaf(wv0.x, x3.x, acc.x); acc.y = fmaf(wv1.x, x3.y, acc.y);
        acc.z = fmaf(wv2.x, x3.z, acc.z); acc.w = fmaf(wv3.x, x3.w, acc.w);
        acc.x = fmaf(wv0.y, x2.x, acc.x); acc.y = fmaf(wv1.y, x2.y, acc.y);
        acc.z = fmaf(wv2.y, x2.z, acc.z); acc.w = fmaf(wv3.y, x2.w, acc.w);
        acc.x = fmaf(wv0.z, x1.x, acc.x); acc.y = fmaf(wv1.z, x1.y, acc.y);
        acc.z = fmaf(wv2.z, x1.z, acc.z); acc.w = fmaf(wv3.z, x1.w, acc.w);
        acc.x = fmaf(wv0.w, x0.x, acc.x); acc.y = fmaf(wv1.w, x0.y, acc.y);
        acc.z = fmaf(wv2.w, x0.z, acc.z); acc.w = fmaf(wv3.w, x0.w, acc.w);
        float4 s;
        s.x = __fdividef(acc.x, 1.f + __expf(-acc.x));
        s.y = __fdividef(acc.y, 1.f + __expf(-acc.y));
        s.z = __fdividef(acc.z, 1.f + __expf(-acc.z));
        s.w = __fdividef(acc.w, 1.f + __expf(-acc.w));
        *(float4*)(po + j*DIN) = s;
        x3 = x2; x2 = x1; x1 = x0;
    }
}

// ---------------- x_proj: 32 rows/block ----------------
__global__ void __launch_bounds__(256)
xproj_k(const float* __restrict__ W) {
    __shared__ __align__(16) float Wsh[XD * DIN];
    for (int i = threadIdx.x; i < XD*DIN; i += 256) Wsh[i] = W[i];
    __syncthreads();
    int warp = threadIdx.x >> 5, lane = threadIdx.x & 31;
    int m0 = blockIdx.x * 32;
    for (int r = warp; r < 32; r += 8) {
        int m = m0 + r;
        const float4* ar = (const float4*)(g_xa + (size_t)m * DIN);
        float acc[XD];
        #pragma unroll
        for (int n = 0; n < XD; n++) acc[n] = 0.f;
        #pragma unroll
        for (int it = 0; it < 3; it++) {
            int k4 = lane + it * 32;
            float4 a = ar[k4];
            #pragma unroll
            for (int n = 0; n < XD; n++) {
                const float4 wv = *(const float4*)(Wsh + n*DIN + k4*4);
                acc[n] = fmaf(a.x, wv.x, fmaf(a.y, wv.y, fmaf(a.z, wv.z, fmaf(a.w, wv.w, acc[n]))));
            }
        }
        float myv = 0.f;
        #pragma unroll
        for (int n = 0; n < XD; n++) {
            float v = acc[n];
            #pragma unroll
            for (int off = 16; off > 0; off >>= 1)
                v += __shfl_xor_sync(0xffffffffu, v, off);
            if (lane == n) myv = v;
        }
        if (lane < DTR) g_xdbl[(size_t)m*DTR + lane] = myv;
        else if (lane < XD) g_bc[(size_t)m*8 + lane - DTR] = myv;
    }
}

// ---------------- scan pass 1 ----------------
__global__ void scan1_k(const float* __restrict__ dtw, const float* __restrict__ dtb, int mix) {
    __shared__ float Bsm[LC][4];
    __shared__ float Xd[LC][DTR];
    int chunk = blockIdx.x, b = blockIdx.y, d = threadIdx.x;
    int l0 = chunk * LC;
    if (threadIdx.x < LC*4) {
        int l = threadIdx.x >> 2, s = threadIdx.x & 3;
        Bsm[l][s] = g_bc[((size_t)(b*LLEN + l0 + l))*8 + s];
    }
    {
        int l = threadIdx.x / DTR, r = threadIdx.x - l*DTR;
        Xd[l][r] = g_xdbl[((size_t)(b*LLEN + l0 + l))*DTR + r];
    }
    __syncthreads();
    int slow = g_slow[mix];
    const float* Ab = g_A + (mix*DIN + d)*4;
    float Av0 = Ab[0], Av1 = Ab[1], Av2 = Ab[2], Av3 = Ab[3];
    const float4* w4 = (const float4*)(dtw + d * DTR);
    float4 dw0 = w4[0], dw1 = w4[1], dw2 = w4[2];
    float pb = dtb[d];
    float h0 = 0.f, h1 = 0.f, h2 = 0.f, h3 = 0.f, sd = 0.f;
    const float* pa = g_xa + (size_t)(b*LLEN + l0)*DIN + d;
    #pragma unroll 4
    for (int l = 0; l < LC; l++) {
        float xav = pa[l*DIN];
        const float* xr = Xd[l];
        float p = pb;
        p = fmaf(xr[0], dw0.x, p);  p = fmaf(xr[1], dw0.y, p);
        p = fmaf(xr[2], dw0.z, p);  p = fmaf(xr[3], dw0.w, p);
        p = fmaf(xr[4], dw1.x, p);  p = fmaf(xr[5], dw1.y, p);
        p = fmaf(xr[6], dw1.z, p);  p = fmaf(xr[7], dw1.w, p);
        p = fmaf(xr[8], dw2.x, p);  p = fmaf(xr[9], dw2.y, p);
        p = fmaf(xr[10], dw2.z, p); p = fmaf(xr[11], dw2.w, p);
        float dtv = (p > 20.f) ? p : __logf(1.f + __expf(p));
        float dbu = dtv * xav;
        sd += dtv;
        float b0 = Bsm[l][0], b1 = Bsm[l][1], b2 = Bsm[l][2], b3 = Bsm[l][3];
        if (!slow) {
            float e = __expf(Av0 * dtv);
            float q = e;
            h0 = fmaf(q, h0, dbu*b0); q *= e;
            h1 = fmaf(q, h1, dbu*b1); q *= e;
            h2 = fmaf(q, h2, dbu*b2); q *= e;
            h3 = fmaf(q, h3, dbu*b3);
        } else {
            h0 = fmaf(__expf(dtv*Av0), h0, dbu*b0);
            h1 = fmaf(__expf(dtv*Av1), h1, dbu*b1);
            h2 = fmaf(__expf(dtv*Av2), h2, dbu*b2);
            h3 = fmaf(__expf(dtv*Av3), h3, dbu*b3);
        }
    }
    int o = ((b*DIN) + d)*NC + chunk;
    ((float4*)g_hpart)[o] = make_float4(h0, h1, h2, h3);
    g_sumdt[o] = sd;
}

// ---------------- scan pass 2 ----------------
__global__ void scan2_k(int mix) {
    int t = blockIdx.x * blockDim.x + threadIdx.x;
    if (t >= BB*DIN) return;
    int d = t % DIN;
    const float* Ab = g_A + (mix*DIN + d)*4;
    float Av0 = Ab[0], Av1 = Ab[1], Av2 = Ab[2], Av3 = Ab[3];
    float H0 = 0.f, H1 = 0.f, H2 = 0.f, H3 = 0.f;
    for (int c = 0; c < NC; c++) {
        int o = t*NC + c;
        ((float4*)g_Hinit)[o] = make_float4(H0, H1, H2, H3);
        float4 hp = ((const float4*)g_hpart)[o];
        float sd = g_sumdt[o];
        H0 = fmaf(__expf(Av0*sd), H0, hp.x);
        H1 = fmaf(__expf(Av1*sd), H1, hp.y);
        H2 = fmaf(__expf(Av2*sd), H2, hp.z);
        H3 = fmaf(__expf(Av3*sd), H3, hp.w);
    }
}

// ---------------- scan pass 3 ----------------
__global__ void scan3_k(const float* __restrict__ dtw, const float* __restrict__ dtb,
                        const float* __restrict__ Dw, int mix, int write_bf16) {
    __shared__ float Bsm[LC][4];
    __shared__ float Csm[LC][4];
    __shared__ float Xd[LC][DTR];
    int chunk = blockIdx.x, b = blockIdx.y, d = threadIdx.x;
    int l0 = chunk * LC;
    if (threadIdx.x < LC*8) {
        int l = threadIdx.x >> 3, s = threadIdx.x & 7;
        float v = g_bc[((size_t)(b*LLEN + l0 + l))*8 + s];
        if (s < 4) Bsm[l][s] = v; else Csm[l][s-4] = v;
    }
    {
        int l = threadIdx.x / DTR, r = threadIdx.x - l*DTR;
        Xd[l][r] = g_xdbl[((size_t)(b*LLEN + l0 + l))*DTR + r];
    }
    __syncthreads();
    int slow = g_slow[mix];
    const float* Ab = g_A + (mix*DIN + d)*4;
    float Av0 = Ab[0], Av1 = Ab[1], Av2 = Ab[2], Av3 = Ab[3];
    const float4* w4 = (const float4*)(dtw + d * DTR);
    float4 dw0 = w4[0], dw1 = w4[1], dw2 = w4[2];
    float pb = dtb[d];
    float Dd = Dw[d];
    int o = ((b*DIN) + d)*NC + chunk;
    float4 Hi = ((const float4*)g_Hinit)[o];
    float h0 = Hi.x, h1 = Hi.y, h2 = Hi.z, h3 = Hi.w;
    size_t base = (size_t)(b*LLEN + l0)*DIN + d;
    const float* pa = g_xa + base;
    const float* pz = g_xz + (size_t)(b*LLEN + l0)*(2*DIN) + DIN + d;
    #pragma unroll 4
    for (int l = 0; l < LC; l++) {
        float xav = pa[l*DIN];
        const float* xr = Xd[l];
        float p = pb;
        p = fmaf(xr[0], dw0.x, p);  p = fmaf(xr[1], dw0.y, p);
        p = fmaf(xr[2], dw0.z, p);  p = fmaf(xr[3], dw0.w, p);
        p = fmaf(xr[4], dw1.x, p);  p = fmaf(xr[5], dw1.y, p);
        p = fmaf(xr[6], dw1.z, p);  p = fmaf(xr[7], dw1.w, p);
        p = fmaf(xr[8], dw2.x, p);  p = fmaf(xr[9], dw2.y, p);
        p = fmaf(xr[10], dw2.z, p); p = fmaf(xr[11], dw2.w, p);
        float dtv = (p > 20.f) ? p : __logf(1.f + __expf(p));
        float dbu = dtv * xav;
        float b0 = Bsm[l][0], b1 = Bsm[l][1], b2 = Bsm[l][2], b3 = Bsm[l][3];
        if (!slow) {
            float e = __expf(Av0 * dtv);
            float q = e;
            h0 = fmaf(q, h0, dbu*b0); q *= e;
            h1 = fmaf(q, h1, dbu*b1); q *= e;
            h2 = fmaf(q, h2, dbu*b2); q *= e;
            h3 = fmaf(q, h3, dbu*b3);
        } else {
            h0 = fmaf(__expf(dtv*Av0), h0, dbu*b0);
            h1 = fmaf(__expf(dtv*Av1), h1, dbu*b1);
            h2 = fmaf(__expf(dtv*Av2), h2, dbu*b2);
            h3 = fmaf(__expf(dtv*Av3), h3, dbu*b3);
        }
        float y = h0*Csm[l][0] + h1*Csm[l][1] + h2*Csm[l][2] + h3*Csm[l][3];
        y = fmaf(xav, Dd, y);
        float zv = pz[l*2*DIN];
        float zs = __fdividef(zv, 1.f + __expf(-zv));
        float yo = y * zs;
        if (write_bf16) {
            __nv_bfloat16 hb, lb;
            hilo_scalar(yo, hb, lb);
            g_ahi[base + l*DIN] = hb;
            g_alo[base + l*DIN] = lb;
        } else {
            g_y[base + l*DIN] = yo;
        }
    }
}

// ---------------- final: u = y2 @ Uf^T; out = LN(xh + u @ V^T) ----------------
__global__ void final_k(const float* __restrict__ V,
                        const float* __restrict__ lng, const float* __restrict__ lnb,
                        float* __restrict__ out)
{
    __shared__ __align__(16) float Ufs[4*DIN];
    __shared__ float Vsh[CEMB*4];
    __shared__ float u[32][4];
    __shared__ float vs[32][193];
    __shared__ float mu[32], rsd[32];
    int b = blockIdx.y;
    int l0 = blockIdx.x * 32;
    int tid = threadIdx.x;
    for (int i = tid; i < 4*DIN; i += 256) Ufs[i] = g_Uf[i];
    for (int i = tid; i < 4*CEMB; i += 256) Vsh[i] = V[i];
    __syncthreads();
    if (tid < 128) {
        int p = tid >> 2, r = tid & 3;
        const float4* yr = (const float4*)(g_y + ((size_t)(b*LLEN) + l0 + p)*DIN);
        const float4* uf = (const float4*)(Ufs + r*DIN);
        float a = 0.f;
        #pragma unroll 8
        for (int c = 0; c < DIN/4; c++) {
            float4 yv = yr[c];
            float4 wv = uf[c];
            a = fmaf(yv.x, wv.x, fmaf(yv.y, wv.y, fmaf(yv.z, wv.z, fmaf(yv.w, wv.w, a))));
        }
        u[p][r] = a;
    }
    __syncthreads();
    for (int i = tid; i < 32*CEMB; i += 256) {
        int p = i / CEMB, c = i % CEMB;
        float v = g_xh[((size_t)(b*LLEN) + l0 + p)*CEMB + c];
        v = fmaf(Vsh[c*4+0], u[p][0], v);
        v = fmaf(Vsh[c*4+1], u[p][1], v);
        v = fmaf(Vsh[c*4+2], u[p][2], v);
        v = fmaf(Vsh[c*4+3], u[p][3], v);
        vs[p][c] = v;
    }
    __syncthreads();
    int warp = tid >> 5, lane = tid & 31;
    #pragma unroll
    for (int pp = 0; pp < 4; pp++) {
        int p = warp*4 + pp;
        float s = 0.f, ss = 0.f;
        for (int c = lane; c < CEMB; c += 32) {
            float v = vs[p][c];
            s += v; ss = fmaf(v, v, ss);
        }
        #pragma unroll
        for (int off = 16; off > 0; off >>= 1) {
            s  += __shfl_xor_sync(0xffffffffu, s, off);
            ss += __shfl_xor_sync(0xffffffffu, ss, off);
        }
        if (lane == 0) {
            float m = s * (1.f/CEMB);
            mu[p] = m;
            rsd[p] = rsqrtf(ss * (1.f/CEMB) - m*m + 1e-5f);
        }
    }
    __syncthreads();
    for (int c = warp; c < CEMB; c += 8) {
        int p = lane;
        float v = (vs[p][c] - mu[p]) * rsd[p] * lng[c] + lnb[c];
        out[((size_t)(b*CEMB) + c)*LLEN + l0 + lane] = v;
    }
}

// ---------------- launch ----------------
extern "C" void kernel_launch(void* const* d_in, const int* in_sizes, int n_in,
                              void* d_out, int out_size)
{
    const float* x         = (const float*)d_in[0];
    const float* in_proj_w = (const float*)d_in[1];
    const float* conv_w    = (const float*)d_in[2];
    const float* conv_b    = (const float*)d_in[3];
    const float* x_proj_w  = (const float*)d_in[4];
    const float* dt_proj_w = (const float*)d_in[5];
    const float* dt_proj_b = (const float*)d_in[6];
    const float* A_log     = (const float*)d_in[7];
    const float* Dw        = (const float*)d_in[8];
    const float* out_proj_w= (const float*)d_in[9];
    const float* U_w       = (const float*)d_in[10];
    const float* V_w       = (const float*)d_in[11];
    const float* ln_g      = (const float*)d_in[12];
    const float* ln_b      = (const float*)d_in[13];
    float* out = (float*)d_out;

    float* g_xz_p;  cudaGetSymbolAddress((void**)&g_xz_p,  g_xz);
    __nv_bfloat16 *ahi_p, *alo_p, *bhi_p, *blo_p, *whi_p, *wlo_p;
    cudaGetSymbolAddress((void**)&ahi_p, g_ahi);
    cudaGetSymbolAddress((void**)&alo_p, g_alo);
    cudaGetSymbolAddress((void**)&bhi_p, g_bhi);
    cudaGetSymbolAddress((void**)&blo_p, g_blo);
    cudaGetSymbolAddress((void**)&whi_p, g_whi);
    cudaGetSymbolAddress((void**)&wlo_p, g_wlo);

    transpose_k<<<dim3(LLEN/32, CEMB/32, BB), dim3(32, 8)>>>(x);
    prepA_k<<<2, DIN>>>(A_log);
    uf_k<<<1, DIN>>>(U_w, out_proj_w + (size_t)CEMB*DIN);

    for (int mix = 0; mix < 2; mix++) {
        const float* dtw = dt_proj_w + (size_t)mix*DIN*DTR;
        const float* dtb = dt_proj_b + mix*DIN;
        const __nv_bfloat16* Ain_hi = (mix == 0) ? ahi_p : bhi_p;
        const __nv_bfloat16* Ain_lo = (mix == 0) ? alo_p : blo_p;

        wcvt_k<<<(2*DIN*CEMB/4 + 255)/256, 256>>>(in_proj_w + (size_t)mix*2*DIN*CEMB, 2*DIN*CEMB/4);
        gemm_mma<<<dim3((2*DIN)/64, MROWS/128), 256>>>(
            Ain_hi, Ain_lo, whi_p, wlo_p, g_xz_p, nullptr, nullptr, MROWS, 2*DIN, CEMB, 0);
        conv_k<<<((MROWS/8)*(DIN/4) + 255)/256, 256>>>(conv_w + mix*DIN*4, conv_b + mix*DIN);
        xproj_k<<<MROWS/32, 256>>>(x_proj_w + (size_t)mix*XD*DIN);
        scan1_k<<<dim3(NC, BB), DIN>>>(dtw, dtb, mix);
        scan2_k<<<(BB*DIN + 255)/256, 256>>>(mix);
        scan3_k<<<dim3(NC, BB), DIN>>>(dtw, dtb, Dw + mix*DIN, mix, mix == 0 ? 1 : 0);
        if (mix == 0) {
            wcvt_k<<<(CEMB*DIN/4 + 255)/256, 256>>>(out_proj_w, CEMB*DIN/4);
            gemm_mma<<<dim3(CEMB/64, MROWS/128), 256>>>(
                ahi_p, alo_p, whi_p, wlo_p, nullptr, bhi_p, blo_p, MROWS, CEMB, DIN, 1);
        }
    }

    final_k<<<dim3(LLEN/32, BB), 256>>>(V_w, ln_g, ln_b, out);
}